// round 3
// baseline (speedup 1.0000x reference)
#include <cuda_runtime.h>
#include <math.h>

#define N_MAX 100000
#define M_MAX 1600000
#define CH 128
#define KVOL 27
#define BN_EPS 1e-5f

// ---------------- scratch (device globals; no runtime allocation) ----------
__device__ float g_h2 [(size_t)N_MAX * CH];
__device__ float g_x  [(size_t)N_MAX * CH];
__device__ float g_q  [(size_t)N_MAX * CH];
__device__ float g_v  [(size_t)N_MAX * CH];
__device__ float g_acc[(size_t)N_MAX * CH];
__device__ float g_npe[KVOL * CH];
__device__ float g_s1[8];        // sums/sumsq for BN1 (3 channels)
__device__ float g_s2[2 * CH];   // sums/sumsq for BN2 (128 channels)
__device__ int   g_cnt[N_MAX];   // per-query entry count (histogram)
__device__ int   g_off[N_MAX];   // per-query exclusive offset
__device__ int   g_cur[N_MAX];   // placement cursors
__device__ int   g_sorted[M_MAX];// kk = key*27+kern, segment-sorted by q

// ---------------- packed f32x2 helpers --------------------------------------
__device__ __forceinline__ unsigned long long pack2(float x) {
    unsigned long long r;
    asm("mov.b64 %0, {%1, %1};" : "=l"(r) : "f"(x));
    return r;
}
__device__ __forceinline__ void fma2(unsigned long long& d,
                                     unsigned long long a,
                                     unsigned long long b) {
    asm("fma.rn.f32x2 %0, %1, %2, %0;" : "+l"(d) : "l"(a), "l"(b));
}
__device__ __forceinline__ float2 unpack2(unsigned long long v) {
    float2 r;
    asm("mov.b64 {%0, %1}, %2;" : "=f"(r.x), "=f"(r.y) : "l"(v));
    return r;
}

// ---------------- init: zero stats + normalize pos_enc ---------------------
__global__ void init_kernel(const float* __restrict__ pos_enc) {
    int tid = threadIdx.x;                 // 256 threads, 1 block
    if (tid < 8)  g_s1[tid] = 0.f;
    if (tid < 256) g_s2[tid] = 0.f;
    if (tid < KVOL * 8) {                  // 216 (k,h) groups, 16 each
        const float* src = pos_enc + tid * 16;
        float v[16]; float s = 0.f;
#pragma unroll
        for (int i = 0; i < 16; i++) { v[i] = src[i]; s += v[i] * v[i]; }
        float inv = 1.f / fmaxf(sqrtf(s), 1e-12f);
#pragma unroll
        for (int i = 0; i < 16; i++) g_npe[tid * 16 + i] = v[i] * inv;
    }
}

// ---------------- stats for BN1 over h1 = points @ W1 ----------------------
__global__ void __launch_bounds__(256) stats1_kernel(
        const float* __restrict__ points, const float* __restrict__ W1, int n) {
    __shared__ float sh[6];
    if (threadIdx.x < 6) sh[threadIdx.x] = 0.f;
    __syncthreads();
    float w[9];
#pragma unroll
    for (int i = 0; i < 9; i++) w[i] = __ldg(&W1[i]);
    float s[3] = {0.f, 0.f, 0.f}, q[3] = {0.f, 0.f, 0.f};
    for (int i = blockIdx.x * blockDim.x + threadIdx.x; i < n;
         i += gridDim.x * blockDim.x) {
        float px = points[i * 3 + 0], py = points[i * 3 + 1], pz = points[i * 3 + 2];
#pragma unroll
        for (int j = 0; j < 3; j++) {
            float h = px * w[j] + py * w[3 + j] + pz * w[6 + j];
            s[j] += h; q[j] += h * h;
        }
    }
#pragma unroll
    for (int o = 16; o; o >>= 1) {
#pragma unroll
        for (int j = 0; j < 3; j++) {
            s[j] += __shfl_down_sync(0xFFFFFFFFu, s[j], o);
            q[j] += __shfl_down_sync(0xFFFFFFFFu, q[j], o);
        }
    }
    if ((threadIdx.x & 31) == 0) {
#pragma unroll
        for (int j = 0; j < 3; j++) {
            atomicAdd(&sh[j], s[j]);
            atomicAdd(&sh[3 + j], q[j]);
        }
    }
    __syncthreads();
    if (threadIdx.x < 6) atomicAdd(&g_s1[threadIdx.x], sh[threadIdx.x]);
}

// ---------------- h2 = relu(bn1(points@W1)) @ W2, + BN2 stats --------------
#define H2_PB 128
__global__ void __launch_bounds__(256) h2_kernel(
        const float* __restrict__ points, const float* __restrict__ W1,
        const float* __restrict__ g1, const float* __restrict__ b1,
        const float* __restrict__ W2, int n) {
    __shared__ float ssum[CH], ssq[CH];
    int tid = threadIdx.x;
    if (tid < CH) { ssum[tid] = 0.f; ssq[tid] = 0.f; }
    __syncthreads();

    float w1[9];
#pragma unroll
    for (int i = 0; i < 9; i++) w1[i] = __ldg(&W1[i]);
    float invn = 1.f / (float)n;
    float sc[3], shf[3];
#pragma unroll
    for (int j = 0; j < 3; j++) {
        float mu  = g_s1[j] * invn;
        float var = g_s1[3 + j] * invn - mu * mu;
        float rs  = rsqrtf(var + BN_EPS);
        float s   = rs * __ldg(&g1[j]);
        sc[j] = s; shf[j] = __ldg(&b1[j]) - mu * s;
    }
    int lane = tid & 31, wid = tid >> 5;
    int c0 = lane * 4;
    float w2a[4], w2b[4], w2c[4];
#pragma unroll
    for (int i = 0; i < 4; i++) {
        w2a[i] = __ldg(&W2[0 * CH + c0 + i]);
        w2b[i] = __ldg(&W2[1 * CH + c0 + i]);
        w2c[i] = __ldg(&W2[2 * CH + c0 + i]);
    }
    float ls[4] = {0, 0, 0, 0}, lq[4] = {0, 0, 0, 0};
    int base = blockIdx.x * H2_PB;
    int nend = min(base + H2_PB, n);
    for (int p = base + wid; p < nend; p += 8) {
        float px = __ldg(&points[p * 3 + 0]);
        float py = __ldg(&points[p * 3 + 1]);
        float pz = __ldg(&points[p * 3 + 2]);
        float a[3];
#pragma unroll
        for (int j = 0; j < 3; j++) {
            float h = px * w1[j] + py * w1[3 + j] + pz * w1[6 + j];
            a[j] = fmaxf(h * sc[j] + shf[j], 0.f);
        }
        float o[4];
#pragma unroll
        for (int i = 0; i < 4; i++) {
            o[i] = a[0] * w2a[i] + a[1] * w2b[i] + a[2] * w2c[i];
            ls[i] += o[i]; lq[i] += o[i] * o[i];
        }
        float4 o4 = make_float4(o[0], o[1], o[2], o[3]);
        *(float4*)&g_h2[(size_t)p * CH + c0] = o4;
    }
#pragma unroll
    for (int i = 0; i < 4; i++) {
        atomicAdd(&ssum[c0 + i], ls[i]);
        atomicAdd(&ssq[c0 + i], lq[i]);
    }
    __syncthreads();
    if (tid < CH) {
        atomicAdd(&g_s2[tid], ssum[tid]);
        atomicAdd(&g_s2[CH + tid], ssq[tid]);
    }
}

// ---------------- generic 128-wide GEMM: C = f(A) @ B + bias, epilogue -----
// MODE 0: C = A@B + bias
// MODE 1: A' = relu(bn2(A)); C = A'@B + bias + extra   (extra = feats)
// MODE 2: C = l2norm_per16(A@B + bias)
#define GEMM_SMEM_BYTES ((16384 + 64 * 132 + 256) * 4)
template <int MODE>
__global__ void __launch_bounds__(256) gemm_kernel(
        const float* __restrict__ A, const float* __restrict__ B,
        const float* __restrict__ bias, float* __restrict__ C,
        const float* __restrict__ extra, const float* __restrict__ gamma,
        const float* __restrict__ beta, int nrows) {
    extern __shared__ float sm[];
    float* Bs   = sm;                    // 128*128
    float* As   = sm + 16384;            // 64*132 (padded)
    float* s_sc = As + 64 * 132;         // 128
    float* s_sh = s_sc + CH;             // 128

    int tid  = threadIdx.x;
    int row0 = blockIdx.x * 64;

    // load full B panel
#pragma unroll
    for (int i = 0; i < 16; i++) {
        int li = i * 256 + tid;
        ((float4*)Bs)[li] = __ldg(((const float4*)B) + li);
    }
    if (MODE == 1 && tid < CH) {
        float invn = 1.f / (float)nrows;
        float mu  = g_s2[tid] * invn;
        float var = g_s2[CH + tid] * invn - mu * mu;
        float rs  = rsqrtf(var + BN_EPS);
        float s   = rs * __ldg(&gamma[tid]);
        s_sc[tid] = s; s_sh[tid] = __ldg(&beta[tid]) - mu * s;
    }
    __syncthreads();

    // load A tile (64 rows)
#pragma unroll
    for (int i = 0; i < 8; i++) {
        int li = i * 256 + tid;          // float4 index, 2048 total
        int r  = li >> 5;
        int c  = (li & 31) << 2;
        float4 a = make_float4(0.f, 0.f, 0.f, 0.f);
        if (row0 + r < nrows)
            a = __ldg((const float4*)(A + (size_t)(row0 + r) * CH + c));
        if (MODE == 1) {
            a.x = fmaxf(a.x * s_sc[c + 0] + s_sh[c + 0], 0.f);
            a.y = fmaxf(a.y * s_sc[c + 1] + s_sh[c + 1], 0.f);
            a.z = fmaxf(a.z * s_sc[c + 2] + s_sh[c + 2], 0.f);
            a.w = fmaxf(a.w * s_sc[c + 3] + s_sh[c + 3], 0.f);
        }
        *(float4*)&As[r * 132 + c] = a;
    }
    __syncthreads();

    int tx = tid & 15, ty = tid >> 4;
    // packed f32x2 accumulators: acc2[r][c] holds cols (pair) for row r
    unsigned long long acc2[4][4];
#pragma unroll
    for (int r = 0; r < 4; r++)
#pragma unroll
        for (int c = 0; c < 4; c++) acc2[r][c] = 0ull;

    const float* Ap = As + ty * 4 * 132;
#pragma unroll 4
    for (int k = 0; k < 128; k++) {
        ulonglong2 b0 = *(const ulonglong2*)&Bs[k * CH + (tx << 2)];
        ulonglong2 b1 = *(const ulonglong2*)&Bs[k * CH + 64 + (tx << 2)];
        unsigned long long bb[4] = {b0.x, b0.y, b1.x, b1.y};
#pragma unroll
        for (int r = 0; r < 4; r++) {
            unsigned long long aa = pack2(Ap[r * 132 + k]);
#pragma unroll
            for (int c = 0; c < 4; c++) fma2(acc2[r][c], aa, bb[c]);
        }
    }

    float4 bias0 = __ldg((const float4*)(bias + (tx << 2)));
    float4 bias1 = __ldg((const float4*)(bias + 64 + (tx << 2)));
#pragma unroll
    for (int rr = 0; rr < 4; rr++) {
        int row = row0 + ty * 4 + rr;
        bool ok = row < nrows;
        float2 u0 = unpack2(acc2[rr][0]);
        float2 u1 = unpack2(acc2[rr][1]);
        float2 u2 = unpack2(acc2[rr][2]);
        float2 u3 = unpack2(acc2[rr][3]);
        float4 o0 = make_float4(u0.x + bias0.x, u0.y + bias0.y,
                                u1.x + bias0.z, u1.y + bias0.w);
        float4 o1 = make_float4(u2.x + bias1.x, u2.y + bias1.y,
                                u3.x + bias1.z, u3.y + bias1.w);
        if (MODE == 1 && ok) {
            float4 f0 = __ldg((const float4*)(extra + (size_t)row * CH + (tx << 2)));
            float4 f1 = __ldg((const float4*)(extra + (size_t)row * CH + 64 + (tx << 2)));
            o0.x += f0.x; o0.y += f0.y; o0.z += f0.z; o0.w += f0.w;
            o1.x += f1.x; o1.y += f1.y; o1.z += f1.z; o1.w += f1.w;
        }
        if (MODE == 2) {
            // l2-norm over 16-channel heads: lanes tx^1, tx^2 share a head
            float s0 = o0.x * o0.x + o0.y * o0.y + o0.z * o0.z + o0.w * o0.w;
            float s1 = o1.x * o1.x + o1.y * o1.y + o1.z * o1.z + o1.w * o1.w;
            s0 += __shfl_xor_sync(0xFFFFFFFFu, s0, 1);
            s0 += __shfl_xor_sync(0xFFFFFFFFu, s0, 2);
            s1 += __shfl_xor_sync(0xFFFFFFFFu, s1, 1);
            s1 += __shfl_xor_sync(0xFFFFFFFFu, s1, 2);
            float i0 = 1.f / fmaxf(sqrtf(s0), 1e-12f);
            float i1 = 1.f / fmaxf(sqrtf(s1), 1e-12f);
            o0.x *= i0; o0.y *= i0; o0.z *= i0; o0.w *= i0;
            o1.x *= i1; o1.y *= i1; o1.z *= i1; o1.w *= i1;
        }
        if (ok) {
            *(float4*)&C[(size_t)row * CH + (tx << 2)] = o0;
            *(float4*)&C[(size_t)row * CH + 64 + (tx << 2)] = o1;
        }
    }
}

// ---------------- counting sort of map entries by q_idx --------------------
__global__ void __launch_bounds__(256) hist_kernel(const int* __restrict__ kq, int M) {
    int i = blockIdx.x * blockDim.x + threadIdx.x;
    if (i < M) atomicAdd(&g_cnt[__ldg(&kq[M + i])], 1);
}

#define SCAN_T 1024
__global__ void __launch_bounds__(SCAN_T) scan_kernel(int n) {
    __shared__ int ssum[SCAN_T];
    int t = threadIdx.x;
    int chunk = (n + SCAN_T - 1) / SCAN_T;
    int beg = t * chunk, end = min(beg + chunk, n);
    int s = 0;
    for (int i = beg; i < end; i++) s += g_cnt[i];
    ssum[t] = s;
    __syncthreads();
    for (int o = 1; o < SCAN_T; o <<= 1) {
        int v = (t >= o) ? ssum[t - o] : 0;
        __syncthreads();
        ssum[t] += v;
        __syncthreads();
    }
    int run = (t == 0) ? 0 : ssum[t - 1];
    for (int i = beg; i < end; i++) {
        g_off[i] = run; g_cur[i] = run;
        run += g_cnt[i];
    }
}

__global__ void __launch_bounds__(256) place_kernel(const int* __restrict__ kq, int M) {
    int i = blockIdx.x * blockDim.x + threadIdx.x;
    if (i < M) {
        int q = __ldg(&kq[M + i]);
        int pos = atomicAdd(&g_cur[q], 1);
        g_sorted[pos] = __ldg(&kq[i]);
    }
}

// ---------------- segment gather: warp per query, no atomics ---------------
// 4-wide batched: decode 4 entries, issue all 4 v-loads before scoring.
__global__ void __launch_bounds__(256) gather_kernel(int n) {
    __shared__ float s_npe[KVOL * CH];
    for (int i = threadIdx.x; i < KVOL * CH / 4; i += 256)
        ((float4*)s_npe)[i] = ((const float4*)g_npe)[i];
    __syncthreads();

    int gw = (blockIdx.x * blockDim.x + threadIdx.x) >> 5;
    if (gw >= n) return;
    int lane = threadIdx.x & 31;
    int c4 = lane * 4;
    int beg = __ldg(&g_off[gw]);
    int cnt = __ldg(&g_cnt[gw]);
    float4 qv = *(const float4*)&g_q[(size_t)gw * CH + c4];
    float4 acc = make_float4(0.f, 0.f, 0.f, 0.f);

    int i = 0;
#pragma unroll 2
    for (; i + 4 <= cnt; i += 4) {
        int key[4], kern[4];
#pragma unroll
        for (int j = 0; j < 4; j++) {
            int e = __ldg(&g_sorted[beg + i + j]);
            key[j]  = e / KVOL;
            kern[j] = e - key[j] * KVOL;
        }
        // issue all 4 independent v-row loads first (MLP)
        float4 v[4];
#pragma unroll
        for (int j = 0; j < 4; j++)
            v[j] = __ldg((const float4*)&g_v[(size_t)key[j] * CH + c4]);
        // scores from smem npe (overlaps with loads in flight)
        float s[4];
#pragma unroll
        for (int j = 0; j < 4; j++) {
            float4 p = *(const float4*)&s_npe[kern[j] * CH + c4];
            float t = qv.x * p.x + qv.y * p.y + qv.z * p.z + qv.w * p.w;
            t += __shfl_xor_sync(0xFFFFFFFFu, t, 1);
            t += __shfl_xor_sync(0xFFFFFFFFu, t, 2);   // 16-ch head dot
            s[j] = t;
        }
#pragma unroll
        for (int j = 0; j < 4; j++) {
            acc.x = fmaf(s[j], v[j].x, acc.x);
            acc.y = fmaf(s[j], v[j].y, acc.y);
            acc.z = fmaf(s[j], v[j].z, acc.z);
            acc.w = fmaf(s[j], v[j].w, acc.w);
        }
    }
    for (; i < cnt; i++) {
        int e = __ldg(&g_sorted[beg + i]);
        int key = e / KVOL;
        int kern = e - key * KVOL;
        float4 v = __ldg((const float4*)&g_v[(size_t)key * CH + c4]);
        float4 p = *(const float4*)&s_npe[kern * CH + c4];
        float t = qv.x * p.x + qv.y * p.y + qv.z * p.z + qv.w * p.w;
        t += __shfl_xor_sync(0xFFFFFFFFu, t, 1);
        t += __shfl_xor_sync(0xFFFFFFFFu, t, 2);
        acc.x = fmaf(t, v.x, acc.x);
        acc.y = fmaf(t, v.y, acc.y);
        acc.z = fmaf(t, v.z, acc.z);
        acc.w = fmaf(t, v.w, acc.w);
    }
    *(float4*)&g_acc[(size_t)gw * CH + c4] = acc;
}

// ---------------- host launch ----------------------------------------------
extern "C" void kernel_launch(void* const* d_in, const int* in_sizes, int n_in,
                              void* d_out, int out_size) {
    const float* feats   = (const float*)d_in[0];
    const float* points  = (const float*)d_in[1];
    const int*   kq      = (const int*)d_in[2];
    const float* W1 = (const float*)d_in[3];
    const float* g1 = (const float*)d_in[4];
    const float* b1 = (const float*)d_in[5];
    const float* W2 = (const float*)d_in[6];
    const float* g2 = (const float*)d_in[7];
    const float* b2 = (const float*)d_in[8];
    const float* W3 = (const float*)d_in[9];
    const float* b3 = (const float*)d_in[10];
    const float* Wq = (const float*)d_in[11];
    const float* bq = (const float*)d_in[12];
    const float* Wv = (const float*)d_in[13];
    const float* bv = (const float*)d_in[14];
    const float* pos_enc = (const float*)d_in[15];
    const float* Wo = (const float*)d_in[16];
    const float* bo = (const float*)d_in[17];

    int N = in_sizes[0] / CH;
    int M = in_sizes[2] / 2;

    cudaFuncSetAttribute((const void*)gemm_kernel<0>,
                         cudaFuncAttributeMaxDynamicSharedMemorySize, GEMM_SMEM_BYTES);
    cudaFuncSetAttribute((const void*)gemm_kernel<1>,
                         cudaFuncAttributeMaxDynamicSharedMemorySize, GEMM_SMEM_BYTES);
    cudaFuncSetAttribute((const void*)gemm_kernel<2>,
                         cudaFuncAttributeMaxDynamicSharedMemorySize, GEMM_SMEM_BYTES);

    float* h2p; float* xp; float* qp; float* vp; float* ap;
    { void* t; cudaGetSymbolAddress(&t, g_h2);  h2p = (float*)t; }
    { void* t; cudaGetSymbolAddress(&t, g_x);   xp  = (float*)t; }
    { void* t; cudaGetSymbolAddress(&t, g_q);   qp  = (float*)t; }
    { void* t; cudaGetSymbolAddress(&t, g_v);   vp  = (float*)t; }
    { void* t; cudaGetSymbolAddress(&t, g_acc); ap  = (float*)t; }
    void* cntp = nullptr;
    cudaGetSymbolAddress(&cntp, g_cnt);
    cudaMemsetAsync(cntp, 0, (size_t)N * sizeof(int), 0);

    init_kernel<<<1, 256>>>(pos_enc);
    stats1_kernel<<<256, 256>>>(points, W1, N);
    h2_kernel<<<(N + H2_PB - 1) / H2_PB, 256>>>(points, W1, g1, b1, W2, N);

    // counting sort
    hist_kernel<<<(M + 255) / 256, 256>>>(kq, M);
    scan_kernel<<<1, SCAN_T>>>(N);
    place_kernel<<<(M + 255) / 256, 256>>>(kq, M);

    int gblocks = (N + 63) / 64;
    // x = relu(bn2(h2)) @ W3 + b3 + feats
    gemm_kernel<1><<<gblocks, 256, GEMM_SMEM_BYTES>>>(h2p, W3, b3, xp, feats, g2, b2, N);
    // q = l2norm16(x @ Wq + bq)
    gemm_kernel<2><<<gblocks, 256, GEMM_SMEM_BYTES>>>(xp, Wq, bq, qp, nullptr, nullptr, nullptr, N);
    // v = x @ Wv + bv
    gemm_kernel<0><<<gblocks, 256, GEMM_SMEM_BYTES>>>(xp, Wv, bv, vp, nullptr, nullptr, nullptr, N);

    // attention: segment gather, no atomics, batched 4-wide
    gather_kernel<<<(N + 7) / 8, 256>>>(N);

    // out = acc @ Wo + bo
    gemm_kernel<0><<<gblocks, 256, GEMM_SMEM_BYTES>>>(ap, Wo, bo, (float*)d_out,
                                                      nullptr, nullptr, nullptr, N);
}

// round 4
// speedup vs baseline: 1.2870x; 1.2870x over previous
#include <cuda_runtime.h>
#include <cuda_bf16.h>
#include <math.h>

#define N_MAX 100000
#define M_MAX 1600000
#define CH 128
#define KVOL 27
#define BN_EPS 1e-5f

// ---------------- scratch (device globals; no runtime allocation) ----------
__device__ float g_h2 [(size_t)N_MAX * CH];
__device__ float g_x  [(size_t)N_MAX * CH];
__device__ float g_q  [(size_t)N_MAX * CH];
__device__ float g_v  [(size_t)N_MAX * CH];
__device__ float g_acc[(size_t)N_MAX * CH];
__device__ float g_npe[KVOL * CH];
__device__ float g_s1[8];
__device__ float g_s2[2 * CH];
__device__ int   g_cnt[N_MAX];
__device__ int   g_off[N_MAX];
__device__ int   g_cur[N_MAX];
__device__ int   g_sorted[M_MAX];
// weight panels, transposed to [n][k] K-major, bf16 split hi/lo
// index: 0=W3, 1=Wq, 2=Wv, 3=Wo
__device__ __nv_bfloat16 g_Whi[4][CH * CH];
__device__ __nv_bfloat16 g_Wlo[4][CH * CH];

// ---------------- init: zero stats + normalize pos_enc ---------------------
__global__ void init_kernel(const float* __restrict__ pos_enc) {
    int tid = threadIdx.x;
    if (tid < 8)  g_s1[tid] = 0.f;
    if (tid < 256) g_s2[tid] = 0.f;
    if (tid < KVOL * 8) {
        const float* src = pos_enc + tid * 16;
        float v[16]; float s = 0.f;
#pragma unroll
        for (int i = 0; i < 16; i++) { v[i] = src[i]; s += v[i] * v[i]; }
        float inv = 1.f / fmaxf(sqrtf(s), 1e-12f);
#pragma unroll
        for (int i = 0; i < 16; i++) g_npe[tid * 16 + i] = v[i] * inv;
    }
}

// ---------------- stats for BN1 + weight split/transpose -------------------
// grid MUST be 256 blocks x 256 threads (65536 = 4 * 128 * 128)
__global__ void __launch_bounds__(256) stats1_kernel(
        const float* __restrict__ points, const float* __restrict__ W1, int n,
        const float* __restrict__ W3, const float* __restrict__ Wq,
        const float* __restrict__ Wv, const float* __restrict__ Wo) {
    // --- weight prep: one element per thread ---
    {
        int gt = blockIdx.x * 256 + threadIdx.x;   // 0..65535
        int w = gt >> 14;                          // 0..3
        int e = gt & 16383;
        int k = e >> 7, nn = e & 127;
        const float* Wsrc = (w == 0) ? W3 : (w == 1) ? Wq : (w == 2) ? Wv : Wo;
        float x = __ldg(&Wsrc[k * CH + nn]);
        __nv_bfloat16 hi = __float2bfloat16(x);
        __nv_bfloat16 lo = __float2bfloat16(x - __bfloat162float(hi));
        g_Whi[w][nn * CH + k] = hi;
        g_Wlo[w][nn * CH + k] = lo;
    }
    // --- BN1 stats ---
    __shared__ float sh[6];
    if (threadIdx.x < 6) sh[threadIdx.x] = 0.f;
    __syncthreads();
    float w[9];
#pragma unroll
    for (int i = 0; i < 9; i++) w[i] = __ldg(&W1[i]);
    float s[3] = {0.f, 0.f, 0.f}, q[3] = {0.f, 0.f, 0.f};
    for (int i = blockIdx.x * blockDim.x + threadIdx.x; i < n;
         i += gridDim.x * blockDim.x) {
        float px = points[i * 3 + 0], py = points[i * 3 + 1], pz = points[i * 3 + 2];
#pragma unroll
        for (int j = 0; j < 3; j++) {
            float h = px * w[j] + py * w[3 + j] + pz * w[6 + j];
            s[j] += h; q[j] += h * h;
        }
    }
#pragma unroll
    for (int o = 16; o; o >>= 1) {
#pragma unroll
        for (int j = 0; j < 3; j++) {
            s[j] += __shfl_down_sync(0xFFFFFFFFu, s[j], o);
            q[j] += __shfl_down_sync(0xFFFFFFFFu, q[j], o);
        }
    }
    if ((threadIdx.x & 31) == 0) {
#pragma unroll
        for (int j = 0; j < 3; j++) {
            atomicAdd(&sh[j], s[j]);
            atomicAdd(&sh[3 + j], q[j]);
        }
    }
    __syncthreads();
    if (threadIdx.x < 6) atomicAdd(&g_s1[threadIdx.x], sh[threadIdx.x]);
}

// ---------------- h2 = relu(bn1(points@W1)) @ W2, + BN2 stats --------------
#define H2_PB 128
__global__ void __launch_bounds__(256) h2_kernel(
        const float* __restrict__ points, const float* __restrict__ W1,
        const float* __restrict__ g1, const float* __restrict__ b1,
        const float* __restrict__ W2, int n) {
    __shared__ float ssum[CH], ssq[CH];
    int tid = threadIdx.x;
    if (tid < CH) { ssum[tid] = 0.f; ssq[tid] = 0.f; }
    __syncthreads();

    float w1[9];
#pragma unroll
    for (int i = 0; i < 9; i++) w1[i] = __ldg(&W1[i]);
    float invn = 1.f / (float)n;
    float sc[3], shf[3];
#pragma unroll
    for (int j = 0; j < 3; j++) {
        float mu  = g_s1[j] * invn;
        float var = g_s1[3 + j] * invn - mu * mu;
        float rs  = rsqrtf(var + BN_EPS);
        float s   = rs * __ldg(&g1[j]);
        sc[j] = s; shf[j] = __ldg(&b1[j]) - mu * s;
    }
    int lane = tid & 31, wid = tid >> 5;
    int c0 = lane * 4;
    float w2a[4], w2b[4], w2c[4];
#pragma unroll
    for (int i = 0; i < 4; i++) {
        w2a[i] = __ldg(&W2[0 * CH + c0 + i]);
        w2b[i] = __ldg(&W2[1 * CH + c0 + i]);
        w2c[i] = __ldg(&W2[2 * CH + c0 + i]);
    }
    float ls[4] = {0, 0, 0, 0}, lq[4] = {0, 0, 0, 0};
    int base = blockIdx.x * H2_PB;
    int nend = min(base + H2_PB, n);
    for (int p = base + wid; p < nend; p += 8) {
        float px = __ldg(&points[p * 3 + 0]);
        float py = __ldg(&points[p * 3 + 1]);
        float pz = __ldg(&points[p * 3 + 2]);
        float a[3];
#pragma unroll
        for (int j = 0; j < 3; j++) {
            float h = px * w1[j] + py * w1[3 + j] + pz * w1[6 + j];
            a[j] = fmaxf(h * sc[j] + shf[j], 0.f);
        }
        float o[4];
#pragma unroll
        for (int i = 0; i < 4; i++) {
            o[i] = a[0] * w2a[i] + a[1] * w2b[i] + a[2] * w2c[i];
            ls[i] += o[i]; lq[i] += o[i] * o[i];
        }
        float4 o4 = make_float4(o[0], o[1], o[2], o[3]);
        *(float4*)&g_h2[(size_t)p * CH + c0] = o4;
    }
#pragma unroll
    for (int i = 0; i < 4; i++) {
        atomicAdd(&ssum[c0 + i], ls[i]);
        atomicAdd(&ssq[c0 + i], lq[i]);
    }
    __syncthreads();
    if (tid < CH) {
        atomicAdd(&g_s2[tid], ssum[tid]);
        atomicAdd(&g_s2[CH + tid], ssq[tid]);
    }
}

// ---------------- tensor-core GEMM (bf16 split, fp32 accum) ----------------
// C[nrows,128] = f(A)[nrows,128] @ W[128,128] + bias, epilogue per MODE.
// MODE 0: plain    MODE 1: A'=relu(bn2(A)), +extra   MODE 2: l2norm per 16ch
#define SASTRIDE 136
#define TC_SMEM ((4 * 128 * SASTRIDE) * 2 + 256 * 4)

__device__ __forceinline__ void mma16816(float* c, const unsigned* a, const unsigned* b) {
    asm volatile(
        "mma.sync.aligned.m16n8k16.row.col.f32.bf16.bf16.f32 "
        "{%0,%1,%2,%3}, {%4,%5,%6,%7}, {%8,%9}, {%0,%1,%2,%3};"
        : "+f"(c[0]), "+f"(c[1]), "+f"(c[2]), "+f"(c[3])
        : "r"(a[0]), "r"(a[1]), "r"(a[2]), "r"(a[3]), "r"(b[0]), "r"(b[1]));
}

template <int MODE>
__global__ void __launch_bounds__(256, 1) gemm_tc(
        const float* __restrict__ A, const __nv_bfloat16* __restrict__ Bhi,
        const __nv_bfloat16* __restrict__ Blo, const float* __restrict__ bias,
        float* __restrict__ C, const float* __restrict__ extra,
        const float* __restrict__ gamma, const float* __restrict__ beta,
        int nrows) {
    extern __shared__ char smraw[];
    __nv_bfloat16* sAhi = (__nv_bfloat16*)smraw;
    __nv_bfloat16* sAlo = sAhi + 128 * SASTRIDE;
    __nv_bfloat16* sBhi = sAlo + 128 * SASTRIDE;
    __nv_bfloat16* sBlo = sBhi + 128 * SASTRIDE;
    float* s_sc = (float*)(sBlo + 128 * SASTRIDE);
    float* s_sh = s_sc + CH;

    int tid = threadIdx.x;
    int row0 = blockIdx.x * 128;

    // ---- load B panels ([n][k] bf16, 16 uint4 per row) ----
#pragma unroll
    for (int i = 0; i < 8; i++) {
        int g = i * 256 + tid;           // uint4 index, 2048 total
        int nn = g >> 4;
        int kk = (g & 15) * 8;
        *(uint4*)&sBhi[nn * SASTRIDE + kk] = __ldg((const uint4*)&Bhi[nn * CH + kk]);
        *(uint4*)&sBlo[nn * SASTRIDE + kk] = __ldg((const uint4*)&Blo[nn * CH + kk]);
    }
    if (MODE == 1 && tid < CH) {
        float invn = 1.f / (float)nrows;
        float mu  = g_s2[tid] * invn;
        float var = g_s2[CH + tid] * invn - mu * mu;
        float rs  = rsqrtf(var + BN_EPS);
        float s   = rs * __ldg(&gamma[tid]);
        s_sc[tid] = s; s_sh[tid] = __ldg(&beta[tid]) - mu * s;
    }
    __syncthreads();

    // ---- load A tile, transform, split to bf16 hi/lo ----
#pragma unroll
    for (int i = 0; i < 16; i++) {
        int g = i * 256 + tid;           // float4 index, 4096 total
        int r = g >> 5;
        int c = (g & 31) * 4;
        float4 a = make_float4(0.f, 0.f, 0.f, 0.f);
        if (row0 + r < nrows)
            a = __ldg((const float4*)&A[(size_t)(row0 + r) * CH + c]);
        if (MODE == 1) {
            a.x = fmaxf(a.x * s_sc[c + 0] + s_sh[c + 0], 0.f);
            a.y = fmaxf(a.y * s_sc[c + 1] + s_sh[c + 1], 0.f);
            a.z = fmaxf(a.z * s_sc[c + 2] + s_sh[c + 2], 0.f);
            a.w = fmaxf(a.w * s_sc[c + 3] + s_sh[c + 3], 0.f);
        }
        __nv_bfloat162 h0 = __floats2bfloat162_rn(a.x, a.y);
        __nv_bfloat162 h1 = __floats2bfloat162_rn(a.z, a.w);
        float2 h0f = __bfloat1622float2(h0);
        float2 h1f = __bfloat1622float2(h1);
        __nv_bfloat162 l0 = __floats2bfloat162_rn(a.x - h0f.x, a.y - h0f.y);
        __nv_bfloat162 l1 = __floats2bfloat162_rn(a.z - h1f.x, a.w - h1f.y);
        *(__nv_bfloat162*)&sAhi[r * SASTRIDE + c]     = h0;
        *(__nv_bfloat162*)&sAhi[r * SASTRIDE + c + 2] = h1;
        *(__nv_bfloat162*)&sAlo[r * SASTRIDE + c]     = l0;
        *(__nv_bfloat162*)&sAlo[r * SASTRIDE + c + 2] = l1;
    }
    __syncthreads();

    // ---- warp tiles: 8 warps = 4(m) x 2(n); warp tile 32x64 ----
    int wid = tid >> 5, lane = tid & 31;
    int warp_m = (wid >> 1) * 32;
    int warp_n = (wid & 1) * 64;
    int r = lane >> 2;
    int kq = (lane & 3) * 2;

    float acc[2][8][4];
#pragma unroll
    for (int mt = 0; mt < 2; mt++)
#pragma unroll
        for (int nt = 0; nt < 8; nt++)
#pragma unroll
            for (int j = 0; j < 4; j++) acc[mt][nt][j] = 0.f;

#pragma unroll
    for (int ks = 0; ks < 8; ks++) {
        int k0 = ks * 16;
        unsigned ahi[2][4], alo[2][4];
#pragma unroll
        for (int mt = 0; mt < 2; mt++) {
            int rb = (warp_m + mt * 16 + r) * SASTRIDE + k0 + kq;
            ahi[mt][0] = *(const unsigned*)&sAhi[rb];
            ahi[mt][1] = *(const unsigned*)&sAhi[rb + 8 * SASTRIDE];
            ahi[mt][2] = *(const unsigned*)&sAhi[rb + 8];
            ahi[mt][3] = *(const unsigned*)&sAhi[rb + 8 * SASTRIDE + 8];
            alo[mt][0] = *(const unsigned*)&sAlo[rb];
            alo[mt][1] = *(const unsigned*)&sAlo[rb + 8 * SASTRIDE];
            alo[mt][2] = *(const unsigned*)&sAlo[rb + 8];
            alo[mt][3] = *(const unsigned*)&sAlo[rb + 8 * SASTRIDE + 8];
        }
        unsigned bhi[8][2], blo[8][2];
#pragma unroll
        for (int nt = 0; nt < 8; nt++) {
            int nb = (warp_n + nt * 8 + r) * SASTRIDE + k0 + kq;
            bhi[nt][0] = *(const unsigned*)&sBhi[nb];
            bhi[nt][1] = *(const unsigned*)&sBhi[nb + 8];
            blo[nt][0] = *(const unsigned*)&sBlo[nb];
            blo[nt][1] = *(const unsigned*)&sBlo[nb + 8];
        }
#pragma unroll
        for (int mt = 0; mt < 2; mt++)
#pragma unroll
            for (int nt = 0; nt < 8; nt++) {
                mma16816(acc[mt][nt], ahi[mt], bhi[nt]);
                mma16816(acc[mt][nt], ahi[mt], blo[nt]);
                mma16816(acc[mt][nt], alo[mt], bhi[nt]);
            }
    }

    // ---- epilogue ----
#pragma unroll
    for (int mt = 0; mt < 2; mt++) {
        int row_lo = row0 + warp_m + mt * 16 + r;
        int row_hi = row_lo + 8;
        bool ok_lo = row_lo < nrows, ok_hi = row_hi < nrows;
        // bias (+ extra)
#pragma unroll
        for (int nt = 0; nt < 8; nt++) {
            int col = warp_n + nt * 8 + kq;
            float2 bs = *(const float2*)&bias[col];
            acc[mt][nt][0] += bs.x; acc[mt][nt][1] += bs.y;
            acc[mt][nt][2] += bs.x; acc[mt][nt][3] += bs.y;
            if (MODE == 1) {
                if (ok_lo) {
                    float2 e = __ldg((const float2*)&extra[(size_t)row_lo * CH + col]);
                    acc[mt][nt][0] += e.x; acc[mt][nt][1] += e.y;
                }
                if (ok_hi) {
                    float2 e = __ldg((const float2*)&extra[(size_t)row_hi * CH + col]);
                    acc[mt][nt][2] += e.x; acc[mt][nt][3] += e.y;
                }
            }
        }
        if (MODE == 2) {
#pragma unroll
            for (int hp = 0; hp < 4; hp++) {
                int n0 = hp * 2, n1 = n0 + 1;
                float s0 = acc[mt][n0][0] * acc[mt][n0][0] + acc[mt][n0][1] * acc[mt][n0][1]
                         + acc[mt][n1][0] * acc[mt][n1][0] + acc[mt][n1][1] * acc[mt][n1][1];
                float s1 = acc[mt][n0][2] * acc[mt][n0][2] + acc[mt][n0][3] * acc[mt][n0][3]
                         + acc[mt][n1][2] * acc[mt][n1][2] + acc[mt][n1][3] * acc[mt][n1][3];
                s0 += __shfl_xor_sync(0xFFFFFFFFu, s0, 1);
                s0 += __shfl_xor_sync(0xFFFFFFFFu, s0, 2);
                s1 += __shfl_xor_sync(0xFFFFFFFFu, s1, 1);
                s1 += __shfl_xor_sync(0xFFFFFFFFu, s1, 2);
                float i0 = 1.f / fmaxf(sqrtf(s0), 1e-12f);
                float i1 = 1.f / fmaxf(sqrtf(s1), 1e-12f);
                acc[mt][n0][0] *= i0; acc[mt][n0][1] *= i0;
                acc[mt][n1][0] *= i0; acc[mt][n1][1] *= i0;
                acc[mt][n0][2] *= i1; acc[mt][n0][3] *= i1;
                acc[mt][n1][2] *= i1; acc[mt][n1][3] *= i1;
            }
        }
#pragma unroll
        for (int nt = 0; nt < 8; nt++) {
            int col = warp_n + nt * 8 + kq;
            if (ok_lo)
                *(float2*)&C[(size_t)row_lo * CH + col] =
                    make_float2(acc[mt][nt][0], acc[mt][nt][1]);
            if (ok_hi)
                *(float2*)&C[(size_t)row_hi * CH + col] =
                    make_float2(acc[mt][nt][2], acc[mt][nt][3]);
        }
    }
}

// ---------------- counting sort of map entries by q_idx --------------------
__global__ void __launch_bounds__(256) hist_kernel(const int* __restrict__ kq, int M) {
    int i = blockIdx.x * blockDim.x + threadIdx.x;
    if (i < M) atomicAdd(&g_cnt[__ldg(&kq[M + i])], 1);
}

#define SCAN_T 1024
__global__ void __launch_bounds__(SCAN_T) scan_kernel(int n) {
    __shared__ int ssum[SCAN_T];
    int t = threadIdx.x;
    int chunk = (n + SCAN_T - 1) / SCAN_T;
    int beg = t * chunk, end = min(beg + chunk, n);
    int s = 0;
    for (int i = beg; i < end; i++) s += g_cnt[i];
    ssum[t] = s;
    __syncthreads();
    for (int o = 1; o < SCAN_T; o <<= 1) {
        int v = (t >= o) ? ssum[t - o] : 0;
        __syncthreads();
        ssum[t] += v;
        __syncthreads();
    }
    int run = (t == 0) ? 0 : ssum[t - 1];
    for (int i = beg; i < end; i++) {
        g_off[i] = run; g_cur[i] = run;
        run += g_cnt[i];
    }
}

__global__ void __launch_bounds__(256) place_kernel(const int* __restrict__ kq, int M) {
    int i = blockIdx.x * blockDim.x + threadIdx.x;
    if (i < M) {
        int q = __ldg(&kq[M + i]);
        int pos = atomicAdd(&g_cur[q], 1);
        g_sorted[pos] = __ldg(&kq[i]);
    }
}

// ---------------- segment gather: warp per query, batched, no atomics ------
__global__ void __launch_bounds__(256) gather_kernel(int n) {
    int gw = (blockIdx.x * blockDim.x + threadIdx.x) >> 5;
    if (gw >= n) return;
    int lane = threadIdx.x & 31;
    int c4 = lane * 4;
    int beg = __ldg(&g_off[gw]);
    int cnt = __ldg(&g_cnt[gw]);
    float4 qv = *(const float4*)&g_q[(size_t)gw * CH + c4];
    float4 acc = make_float4(0.f, 0.f, 0.f, 0.f);

    int i = 0;
#pragma unroll 2
    for (; i + 4 <= cnt; i += 4) {
        int key[4], kern[4];
#pragma unroll
        for (int j = 0; j < 4; j++) {
            int e = __ldg(&g_sorted[beg + i + j]);
            key[j]  = e / KVOL;
            kern[j] = e - key[j] * KVOL;
        }
        float4 v[4];
#pragma unroll
        for (int j = 0; j < 4; j++)
            v[j] = __ldg((const float4*)&g_v[(size_t)key[j] * CH + c4]);
        float s[4];
#pragma unroll
        for (int j = 0; j < 4; j++) {
            float4 p = __ldg((const float4*)&g_npe[kern[j] * CH + c4]);
            float t = qv.x * p.x + qv.y * p.y + qv.z * p.z + qv.w * p.w;
            t += __shfl_xor_sync(0xFFFFFFFFu, t, 1);
            t += __shfl_xor_sync(0xFFFFFFFFu, t, 2);
            s[j] = t;
        }
#pragma unroll
        for (int j = 0; j < 4; j++) {
            acc.x = fmaf(s[j], v[j].x, acc.x);
            acc.y = fmaf(s[j], v[j].y, acc.y);
            acc.z = fmaf(s[j], v[j].z, acc.z);
            acc.w = fmaf(s[j], v[j].w, acc.w);
        }
    }
    for (; i < cnt; i++) {
        int e = __ldg(&g_sorted[beg + i]);
        int key = e / KVOL;
        int kern = e - key * KVOL;
        float4 v = __ldg((const float4*)&g_v[(size_t)key * CH + c4]);
        float4 p = __ldg((const float4*)&g_npe[kern * CH + c4]);
        float t = qv.x * p.x + qv.y * p.y + qv.z * p.z + qv.w * p.w;
        t += __shfl_xor_sync(0xFFFFFFFFu, t, 1);
        t += __shfl_xor_sync(0xFFFFFFFFu, t, 2);
        acc.x = fmaf(t, v.x, acc.x);
        acc.y = fmaf(t, v.y, acc.y);
        acc.z = fmaf(t, v.z, acc.z);
        acc.w = fmaf(t, v.w, acc.w);
    }
    *(float4*)&g_acc[(size_t)gw * CH + c4] = acc;
}

// ---------------- host launch ----------------------------------------------
extern "C" void kernel_launch(void* const* d_in, const int* in_sizes, int n_in,
                              void* d_out, int out_size) {
    const float* feats   = (const float*)d_in[0];
    const float* points  = (const float*)d_in[1];
    const int*   kq      = (const int*)d_in[2];
    const float* W1 = (const float*)d_in[3];
    const float* g1 = (const float*)d_in[4];
    const float* b1 = (const float*)d_in[5];
    const float* W2 = (const float*)d_in[6];
    const float* g2 = (const float*)d_in[7];
    const float* b2 = (const float*)d_in[8];
    const float* W3 = (const float*)d_in[9];
    const float* b3 = (const float*)d_in[10];
    const float* Wq = (const float*)d_in[11];
    const float* bq = (const float*)d_in[12];
    const float* Wv = (const float*)d_in[13];
    const float* bv = (const float*)d_in[14];
    const float* pos_enc = (const float*)d_in[15];
    const float* Wo = (const float*)d_in[16];
    const float* bo = (const float*)d_in[17];

    int N = in_sizes[0] / CH;
    int M = in_sizes[2] / 2;

    cudaFuncSetAttribute((const void*)gemm_tc<0>,
                         cudaFuncAttributeMaxDynamicSharedMemorySize, TC_SMEM);
    cudaFuncSetAttribute((const void*)gemm_tc<1>,
                         cudaFuncAttributeMaxDynamicSharedMemorySize, TC_SMEM);
    cudaFuncSetAttribute((const void*)gemm_tc<2>,
                         cudaFuncAttributeMaxDynamicSharedMemorySize, TC_SMEM);

    float* h2p; float* xp; float* qp; float* vp; float* ap;
    __nv_bfloat16* whi; __nv_bfloat16* wlo;
    { void* t; cudaGetSymbolAddress(&t, g_h2);  h2p = (float*)t; }
    { void* t; cudaGetSymbolAddress(&t, g_x);   xp  = (float*)t; }
    { void* t; cudaGetSymbolAddress(&t, g_q);   qp  = (float*)t; }
    { void* t; cudaGetSymbolAddress(&t, g_v);   vp  = (float*)t; }
    { void* t; cudaGetSymbolAddress(&t, g_acc); ap  = (float*)t; }
    { void* t; cudaGetSymbolAddress(&t, g_Whi); whi = (__nv_bfloat16*)t; }
    { void* t; cudaGetSymbolAddress(&t, g_Wlo); wlo = (__nv_bfloat16*)t; }
    void* cntp = nullptr;
    cudaGetSymbolAddress(&cntp, g_cnt);
    cudaMemsetAsync(cntp, 0, (size_t)N * sizeof(int), 0);

    init_kernel<<<1, 256>>>(pos_enc);
    stats1_kernel<<<256, 256>>>(points, W1, N, W3, Wq, Wv, Wo);
    h2_kernel<<<(N + H2_PB - 1) / H2_PB, 256>>>(points, W1, g1, b1, W2, N);

    int gblocks = (N + 127) / 128;
    // x = relu(bn2(h2)) @ W3 + b3 + feats     (profiled slot)
    gemm_tc<1><<<gblocks, 256, TC_SMEM>>>(h2p, whi + 0 * CH * CH, wlo + 0 * CH * CH,
                                          b3, xp, feats, g2, b2, N);
    // q = l2norm16(x @ Wq + bq)
    gemm_tc<2><<<gblocks, 256, TC_SMEM>>>(xp, whi + 1 * CH * CH, wlo + 1 * CH * CH,
                                          bq, qp, nullptr, nullptr, nullptr, N);
    // v = x @ Wv + bv
    gemm_tc<0><<<gblocks, 256, TC_SMEM>>>(xp, whi + 2 * CH * CH, wlo + 2 * CH * CH,
                                          bv, vp, nullptr, nullptr, nullptr, N);

    // counting sort (after GEMMs; only needed before gather)
    hist_kernel<<<(M + 255) / 256, 256>>>(kq, M);
    scan_kernel<<<1, SCAN_T>>>(N);
    place_kernel<<<(M + 255) / 256, 256>>>(kq, M);

    // attention: segment gather, no atomics
    gather_kernel<<<(N + 7) / 8, 256>>>(N);

    // out = acc @ Wo + bo
    gemm_tc<0><<<gblocks, 256, TC_SMEM>>>(ap, whi + 3 * CH * CH, wlo + 3 * CH * CH,
                                          bo, (float*)d_out, nullptr, nullptr, nullptr, N);
}

// round 5
// speedup vs baseline: 1.3123x; 1.0197x over previous
#include <cuda_runtime.h>
#include <cuda_bf16.h>
#include <math.h>

#define N_MAX 100000
#define M_MAX 1600000
#define CH 128
#define KVOL 27
#define BN_EPS 1e-5f

// ---------------- scratch (device globals; no runtime allocation) ----------
__device__ float g_h2 [(size_t)N_MAX * CH];
__device__ float g_x  [(size_t)N_MAX * CH];
__device__ float g_q  [(size_t)N_MAX * CH];
__device__ float g_v  [(size_t)N_MAX * CH];
__device__ float g_acc[(size_t)N_MAX * CH];
__device__ float g_npe[KVOL * CH];
__device__ float g_s1[8];
__device__ float g_s2[2 * CH];
__device__ int   g_cnt[N_MAX];
__device__ int   g_off[N_MAX];
__device__ int   g_cur[N_MAX];
__device__ int   g_sorted[M_MAX];
// weight panels, transposed to [n][k] K-major, bf16 split hi/lo
// index: 0=W3, 1=Wq, 2=Wv, 3=Wo
__device__ __nv_bfloat16 g_Whi[4][CH * CH];
__device__ __nv_bfloat16 g_Wlo[4][CH * CH];

// ---------------- init: zero stats + normalize pos_enc ---------------------
__global__ void init_kernel(const float* __restrict__ pos_enc) {
    int tid = threadIdx.x;
    if (tid < 8)  g_s1[tid] = 0.f;
    if (tid < 256) g_s2[tid] = 0.f;
    if (tid < KVOL * 8) {
        const float* src = pos_enc + tid * 16;
        float v[16]; float s = 0.f;
#pragma unroll
        for (int i = 0; i < 16; i++) { v[i] = src[i]; s += v[i] * v[i]; }
        float inv = 1.f / fmaxf(sqrtf(s), 1e-12f);
#pragma unroll
        for (int i = 0; i < 16; i++) g_npe[tid * 16 + i] = v[i] * inv;
    }
}

// ---------------- stats for BN1 + weight split/transpose -------------------
// grid MUST be 256 blocks x 256 threads (65536 = 4 * 128 * 128)
__global__ void __launch_bounds__(256) stats1_kernel(
        const float* __restrict__ points, const float* __restrict__ W1, int n,
        const float* __restrict__ W3, const float* __restrict__ Wq,
        const float* __restrict__ Wv, const float* __restrict__ Wo) {
    {
        int gt = blockIdx.x * 256 + threadIdx.x;   // 0..65535
        int w = gt >> 14;                          // 0..3
        int e = gt & 16383;
        int k = e >> 7, nn = e & 127;
        const float* Wsrc = (w == 0) ? W3 : (w == 1) ? Wq : (w == 2) ? Wv : Wo;
        float x = __ldg(&Wsrc[k * CH + nn]);
        __nv_bfloat16 hi = __float2bfloat16(x);
        __nv_bfloat16 lo = __float2bfloat16(x - __bfloat162float(hi));
        g_Whi[w][nn * CH + k] = hi;
        g_Wlo[w][nn * CH + k] = lo;
    }
    __shared__ float sh[6];
    if (threadIdx.x < 6) sh[threadIdx.x] = 0.f;
    __syncthreads();
    float w[9];
#pragma unroll
    for (int i = 0; i < 9; i++) w[i] = __ldg(&W1[i]);
    float s[3] = {0.f, 0.f, 0.f}, q[3] = {0.f, 0.f, 0.f};
    for (int i = blockIdx.x * blockDim.x + threadIdx.x; i < n;
         i += gridDim.x * blockDim.x) {
        float px = points[i * 3 + 0], py = points[i * 3 + 1], pz = points[i * 3 + 2];
#pragma unroll
        for (int j = 0; j < 3; j++) {
            float h = px * w[j] + py * w[3 + j] + pz * w[6 + j];
            s[j] += h; q[j] += h * h;
        }
    }
#pragma unroll
    for (int o = 16; o; o >>= 1) {
#pragma unroll
        for (int j = 0; j < 3; j++) {
            s[j] += __shfl_down_sync(0xFFFFFFFFu, s[j], o);
            q[j] += __shfl_down_sync(0xFFFFFFFFu, q[j], o);
        }
    }
    if ((threadIdx.x & 31) == 0) {
#pragma unroll
        for (int j = 0; j < 3; j++) {
            atomicAdd(&sh[j], s[j]);
            atomicAdd(&sh[3 + j], q[j]);
        }
    }
    __syncthreads();
    if (threadIdx.x < 6) atomicAdd(&g_s1[threadIdx.x], sh[threadIdx.x]);
}

// ---------------- h2 = relu(bn1(points@W1)) @ W2, + BN2 stats --------------
#define H2_PB 128
__global__ void __launch_bounds__(256) h2_kernel(
        const float* __restrict__ points, const float* __restrict__ W1,
        const float* __restrict__ g1, const float* __restrict__ b1,
        const float* __restrict__ W2, int n) {
    __shared__ float ssum[CH], ssq[CH];
    int tid = threadIdx.x;
    if (tid < CH) { ssum[tid] = 0.f; ssq[tid] = 0.f; }
    __syncthreads();

    float w1[9];
#pragma unroll
    for (int i = 0; i < 9; i++) w1[i] = __ldg(&W1[i]);
    float invn = 1.f / (float)n;
    float sc[3], shf[3];
#pragma unroll
    for (int j = 0; j < 3; j++) {
        float mu  = g_s1[j] * invn;
        float var = g_s1[3 + j] * invn - mu * mu;
        float rs  = rsqrtf(var + BN_EPS);
        float s   = rs * __ldg(&g1[j]);
        sc[j] = s; shf[j] = __ldg(&b1[j]) - mu * s;
    }
    int lane = tid & 31, wid = tid >> 5;
    int c0 = lane * 4;
    float w2a[4], w2b[4], w2c[4];
#pragma unroll
    for (int i = 0; i < 4; i++) {
        w2a[i] = __ldg(&W2[0 * CH + c0 + i]);
        w2b[i] = __ldg(&W2[1 * CH + c0 + i]);
        w2c[i] = __ldg(&W2[2 * CH + c0 + i]);
    }
    float ls[4] = {0, 0, 0, 0}, lq[4] = {0, 0, 0, 0};
    int base = blockIdx.x * H2_PB;
    int nend = min(base + H2_PB, n);
    for (int p = base + wid; p < nend; p += 8) {
        float px = __ldg(&points[p * 3 + 0]);
        float py = __ldg(&points[p * 3 + 1]);
        float pz = __ldg(&points[p * 3 + 2]);
        float a[3];
#pragma unroll
        for (int j = 0; j < 3; j++) {
            float h = px * w1[j] + py * w1[3 + j] + pz * w1[6 + j];
            a[j] = fmaxf(h * sc[j] + shf[j], 0.f);
        }
        float o[4];
#pragma unroll
        for (int i = 0; i < 4; i++) {
            o[i] = a[0] * w2a[i] + a[1] * w2b[i] + a[2] * w2c[i];
            ls[i] += o[i]; lq[i] += o[i] * o[i];
        }
        float4 o4 = make_float4(o[0], o[1], o[2], o[3]);
        *(float4*)&g_h2[(size_t)p * CH + c0] = o4;
    }
#pragma unroll
    for (int i = 0; i < 4; i++) {
        atomicAdd(&ssum[c0 + i], ls[i]);
        atomicAdd(&ssq[c0 + i], lq[i]);
    }
    __syncthreads();
    if (tid < CH) {
        atomicAdd(&g_s2[tid], ssum[tid]);
        atomicAdd(&g_s2[CH + tid], ssq[tid]);
    }
}

// ---------------- tensor-core GEMM (bf16 split, fp32 accum) ----------------
// BM=64 block tile, 2 CTAs/SM for latency overlap.
// C[nrows,128] = f(A)[nrows,128] @ W[128,128] + bias, epilogue per MODE.
// MODE 0: plain    MODE 1: A'=relu(bn2(A)), +extra   MODE 2: l2norm per 16ch
#define SASTRIDE 136
#define BM 64
#define TC_SMEM ((2 * BM * SASTRIDE + 2 * 128 * SASTRIDE) * 2 + 256 * 4)

__device__ __forceinline__ void mma16816(float* c, const unsigned* a, const unsigned* b) {
    asm volatile(
        "mma.sync.aligned.m16n8k16.row.col.f32.bf16.bf16.f32 "
        "{%0,%1,%2,%3}, {%4,%5,%6,%7}, {%8,%9}, {%0,%1,%2,%3};"
        : "+f"(c[0]), "+f"(c[1]), "+f"(c[2]), "+f"(c[3])
        : "r"(a[0]), "r"(a[1]), "r"(a[2]), "r"(a[3]), "r"(b[0]), "r"(b[1]));
}

template <int MODE>
__global__ void __launch_bounds__(256, 2) gemm_tc(
        const float* __restrict__ A, const __nv_bfloat16* __restrict__ Bhi,
        const __nv_bfloat16* __restrict__ Blo, const float* __restrict__ bias,
        float* __restrict__ C, const float* __restrict__ extra,
        const float* __restrict__ gamma, const float* __restrict__ beta,
        int nrows) {
    extern __shared__ char smraw[];
    __nv_bfloat16* sAhi = (__nv_bfloat16*)smraw;
    __nv_bfloat16* sAlo = sAhi + BM * SASTRIDE;
    __nv_bfloat16* sBhi = sAlo + BM * SASTRIDE;
    __nv_bfloat16* sBlo = sBhi + 128 * SASTRIDE;
    float* s_sc = (float*)(sBlo + 128 * SASTRIDE);
    float* s_sh = s_sc + CH;

    int tid = threadIdx.x;
    int row0 = blockIdx.x * BM;

    // ---- load B panels ([n][k] bf16, 16 uint4 per row) ----
#pragma unroll
    for (int i = 0; i < 8; i++) {
        int g = i * 256 + tid;           // uint4 index, 2048 total
        int nn = g >> 4;
        int kk = (g & 15) * 8;
        *(uint4*)&sBhi[nn * SASTRIDE + kk] = __ldg((const uint4*)&Bhi[nn * CH + kk]);
        *(uint4*)&sBlo[nn * SASTRIDE + kk] = __ldg((const uint4*)&Blo[nn * CH + kk]);
    }
    if (MODE == 1 && tid < CH) {
        float invn = 1.f / (float)nrows;
        float mu  = g_s2[tid] * invn;
        float var = g_s2[CH + tid] * invn - mu * mu;
        float rs  = rsqrtf(var + BN_EPS);
        float s   = rs * __ldg(&gamma[tid]);
        s_sc[tid] = s; s_sh[tid] = __ldg(&beta[tid]) - mu * s;
    }
    __syncthreads();

    // ---- load A tile (BM rows), transform, split to bf16 hi/lo ----
#pragma unroll
    for (int i = 0; i < BM / 8; i++) {
        int g = i * 256 + tid;           // float4 index, BM*32 total
        int r = g >> 5;
        int c = (g & 31) * 4;
        float4 a = make_float4(0.f, 0.f, 0.f, 0.f);
        if (row0 + r < nrows)
            a = __ldg((const float4*)&A[(size_t)(row0 + r) * CH + c]);
        if (MODE == 1) {
            a.x = fmaxf(a.x * s_sc[c + 0] + s_sh[c + 0], 0.f);
            a.y = fmaxf(a.y * s_sc[c + 1] + s_sh[c + 1], 0.f);
            a.z = fmaxf(a.z * s_sc[c + 2] + s_sh[c + 2], 0.f);
            a.w = fmaxf(a.w * s_sc[c + 3] + s_sh[c + 3], 0.f);
        }
        __nv_bfloat162 h0 = __floats2bfloat162_rn(a.x, a.y);
        __nv_bfloat162 h1 = __floats2bfloat162_rn(a.z, a.w);
        float2 h0f = __bfloat1622float2(h0);
        float2 h1f = __bfloat1622float2(h1);
        __nv_bfloat162 l0 = __floats2bfloat162_rn(a.x - h0f.x, a.y - h0f.y);
        __nv_bfloat162 l1 = __floats2bfloat162_rn(a.z - h1f.x, a.w - h1f.y);
        *(__nv_bfloat162*)&sAhi[r * SASTRIDE + c]     = h0;
        *(__nv_bfloat162*)&sAhi[r * SASTRIDE + c + 2] = h1;
        *(__nv_bfloat162*)&sAlo[r * SASTRIDE + c]     = l0;
        *(__nv_bfloat162*)&sAlo[r * SASTRIDE + c + 2] = l1;
    }
    __syncthreads();

    // ---- warp tiles: 8 warps = 4(m) x 2(n); warp tile 16x64 ----
    int wid = tid >> 5, lane = tid & 31;
    int warp_m = (wid >> 1) * 16;
    int warp_n = (wid & 1) * 64;
    int r = lane >> 2;
    int kq = (lane & 3) * 2;

    float acc[8][4];
#pragma unroll
    for (int nt = 0; nt < 8; nt++)
#pragma unroll
        for (int j = 0; j < 4; j++) acc[nt][j] = 0.f;

#pragma unroll
    for (int ks = 0; ks < 8; ks++) {
        int k0 = ks * 16;
        unsigned ahi[4], alo[4];
        {
            int rb = (warp_m + r) * SASTRIDE + k0 + kq;
            ahi[0] = *(const unsigned*)&sAhi[rb];
            ahi[1] = *(const unsigned*)&sAhi[rb + 8 * SASTRIDE];
            ahi[2] = *(const unsigned*)&sAhi[rb + 8];
            ahi[3] = *(const unsigned*)&sAhi[rb + 8 * SASTRIDE + 8];
            alo[0] = *(const unsigned*)&sAlo[rb];
            alo[1] = *(const unsigned*)&sAlo[rb + 8 * SASTRIDE];
            alo[2] = *(const unsigned*)&sAlo[rb + 8];
            alo[3] = *(const unsigned*)&sAlo[rb + 8 * SASTRIDE + 8];
        }
#pragma unroll
        for (int nt = 0; nt < 8; nt++) {
            int nb = (warp_n + nt * 8 + r) * SASTRIDE + k0 + kq;
            unsigned bhi[2], blo[2];
            bhi[0] = *(const unsigned*)&sBhi[nb];
            bhi[1] = *(const unsigned*)&sBhi[nb + 8];
            blo[0] = *(const unsigned*)&sBlo[nb];
            blo[1] = *(const unsigned*)&sBlo[nb + 8];
            mma16816(acc[nt], ahi, bhi);
            mma16816(acc[nt], ahi, blo);
            mma16816(acc[nt], alo, bhi);
        }
    }

    // ---- epilogue ----
    int row_lo = row0 + warp_m + r;
    int row_hi = row_lo + 8;
    bool ok_lo = row_lo < nrows, ok_hi = row_hi < nrows;
#pragma unroll
    for (int nt = 0; nt < 8; nt++) {
        int col = warp_n + nt * 8 + kq;
        float2 bs = *(const float2*)&bias[col];
        acc[nt][0] += bs.x; acc[nt][1] += bs.y;
        acc[nt][2] += bs.x; acc[nt][3] += bs.y;
        if (MODE == 1) {
            if (ok_lo) {
                float2 e = __ldg((const float2*)&extra[(size_t)row_lo * CH + col]);
                acc[nt][0] += e.x; acc[nt][1] += e.y;
            }
            if (ok_hi) {
                float2 e = __ldg((const float2*)&extra[(size_t)row_hi * CH + col]);
                acc[nt][2] += e.x; acc[nt][3] += e.y;
            }
        }
    }
    if (MODE == 2) {
#pragma unroll
        for (int hp = 0; hp < 4; hp++) {
            int n0 = hp * 2, n1 = n0 + 1;
            float s0 = acc[n0][0] * acc[n0][0] + acc[n0][1] * acc[n0][1]
                     + acc[n1][0] * acc[n1][0] + acc[n1][1] * acc[n1][1];
            float s1 = acc[n0][2] * acc[n0][2] + acc[n0][3] * acc[n0][3]
                     + acc[n1][2] * acc[n1][2] + acc[n1][3] * acc[n1][3];
            s0 += __shfl_xor_sync(0xFFFFFFFFu, s0, 1);
            s0 += __shfl_xor_sync(0xFFFFFFFFu, s0, 2);
            s1 += __shfl_xor_sync(0xFFFFFFFFu, s1, 1);
            s1 += __shfl_xor_sync(0xFFFFFFFFu, s1, 2);
            float i0 = 1.f / fmaxf(sqrtf(s0), 1e-12f);
            float i1 = 1.f / fmaxf(sqrtf(s1), 1e-12f);
            acc[n0][0] *= i0; acc[n0][1] *= i0;
            acc[n1][0] *= i0; acc[n1][1] *= i0;
            acc[n0][2] *= i1; acc[n0][3] *= i1;
            acc[n1][2] *= i1; acc[n1][3] *= i1;
        }
    }
#pragma unroll
    for (int nt = 0; nt < 8; nt++) {
        int col = warp_n + nt * 8 + kq;
        if (ok_lo)
            *(float2*)&C[(size_t)row_lo * CH + col] =
                make_float2(acc[nt][0], acc[nt][1]);
        if (ok_hi)
            *(float2*)&C[(size_t)row_hi * CH + col] =
                make_float2(acc[nt][2], acc[nt][3]);
    }
}

// ---------------- counting sort of map entries by q_idx --------------------
__global__ void __launch_bounds__(256) hist_kernel(const int* __restrict__ kq, int M) {
    int i = blockIdx.x * blockDim.x + threadIdx.x;
    if (i < M) atomicAdd(&g_cnt[__ldg(&kq[M + i])], 1);
}

#define SCAN_T 1024
__global__ void __launch_bounds__(SCAN_T) scan_kernel(int n) {
    __shared__ int ssum[SCAN_T];
    int t = threadIdx.x;
    int chunk = (n + SCAN_T - 1) / SCAN_T;
    int beg = t * chunk, end = min(beg + chunk, n);
    int s = 0;
    for (int i = beg; i < end; i++) s += g_cnt[i];
    ssum[t] = s;
    __syncthreads();
    for (int o = 1; o < SCAN_T; o <<= 1) {
        int v = (t >= o) ? ssum[t - o] : 0;
        __syncthreads();
        ssum[t] += v;
        __syncthreads();
    }
    int run = (t == 0) ? 0 : ssum[t - 1];
    for (int i = beg; i < end; i++) {
        g_off[i] = run; g_cur[i] = run;
        run += g_cnt[i];
    }
}

__global__ void __launch_bounds__(256) place_kernel(const int* __restrict__ kq, int M) {
    int i = blockIdx.x * blockDim.x + threadIdx.x;
    if (i < M) {
        int q = __ldg(&kq[M + i]);
        int pos = atomicAdd(&g_cur[q], 1);
        g_sorted[pos] = __ldg(&kq[i]);
    }
}

// ---------------- segment gather: warp per query, batched, no atomics ------
// Streaming cache hints keep L2 capacity for the 16x-reused v rows.
__global__ void __launch_bounds__(256) gather_kernel(int n) {
    int gw = (blockIdx.x * blockDim.x + threadIdx.x) >> 5;
    if (gw >= n) return;
    int lane = threadIdx.x & 31;
    int c4 = lane * 4;
    int beg = __ldg(&g_off[gw]);
    int cnt = __ldg(&g_cnt[gw]);
    float4 qv = __ldcs((const float4*)&g_q[(size_t)gw * CH + c4]);  // once-read
    float4 acc = make_float4(0.f, 0.f, 0.f, 0.f);

    int i = 0;
#pragma unroll 2
    for (; i + 4 <= cnt; i += 4) {
        int key[4], kern[4];
#pragma unroll
        for (int j = 0; j < 4; j++) {
            int e = __ldg(&g_sorted[beg + i + j]);
            key[j]  = e / KVOL;
            kern[j] = e - key[j] * KVOL;
        }
        float4 v[4];
#pragma unroll
        for (int j = 0; j < 4; j++)
            v[j] = __ldg((const float4*)&g_v[(size_t)key[j] * CH + c4]);
        float s[4];
#pragma unroll
        for (int j = 0; j < 4; j++) {
            float4 p = __ldg((const float4*)&g_npe[kern[j] * CH + c4]);
            float t = qv.x * p.x + qv.y * p.y + qv.z * p.z + qv.w * p.w;
            t += __shfl_xor_sync(0xFFFFFFFFu, t, 1);
            t += __shfl_xor_sync(0xFFFFFFFFu, t, 2);
            s[j] = t;
        }
#pragma unroll
        for (int j = 0; j < 4; j++) {
            acc.x = fmaf(s[j], v[j].x, acc.x);
            acc.y = fmaf(s[j], v[j].y, acc.y);
            acc.z = fmaf(s[j], v[j].z, acc.z);
            acc.w = fmaf(s[j], v[j].w, acc.w);
        }
    }
    for (; i < cnt; i++) {
        int e = __ldg(&g_sorted[beg + i]);
        int key = e / KVOL;
        int kern = e - key * KVOL;
        float4 v = __ldg((const float4*)&g_v[(size_t)key * CH + c4]);
        float4 p = __ldg((const float4*)&g_npe[kern * CH + c4]);
        float t = qv.x * p.x + qv.y * p.y + qv.z * p.z + qv.w * p.w;
        t += __shfl_xor_sync(0xFFFFFFFFu, t, 1);
        t += __shfl_xor_sync(0xFFFFFFFFu, t, 2);
        acc.x = fmaf(t, v.x, acc.x);
        acc.y = fmaf(t, v.y, acc.y);
        acc.z = fmaf(t, v.z, acc.z);
        acc.w = fmaf(t, v.w, acc.w);
    }
    __stcs((float4*)&g_acc[(size_t)gw * CH + c4], acc);  // once-written
}

// ---------------- host launch ----------------------------------------------
extern "C" void kernel_launch(void* const* d_in, const int* in_sizes, int n_in,
                              void* d_out, int out_size) {
    const float* feats   = (const float*)d_in[0];
    const float* points  = (const float*)d_in[1];
    const int*   kq      = (const int*)d_in[2];
    const float* W1 = (const float*)d_in[3];
    const float* g1 = (const float*)d_in[4];
    const float* b1 = (const float*)d_in[5];
    const float* W2 = (const float*)d_in[6];
    const float* g2 = (const float*)d_in[7];
    const float* b2 = (const float*)d_in[8];
    const float* W3 = (const float*)d_in[9];
    const float* b3 = (const float*)d_in[10];
    const float* Wq = (const float*)d_in[11];
    const float* bq = (const float*)d_in[12];
    const float* Wv = (const float*)d_in[13];
    const float* bv = (const float*)d_in[14];
    const float* pos_enc = (const float*)d_in[15];
    const float* Wo = (const float*)d_in[16];
    const float* bo = (const float*)d_in[17];

    int N = in_sizes[0] / CH;
    int M = in_sizes[2] / 2;

    cudaFuncSetAttribute((const void*)gemm_tc<0>,
                         cudaFuncAttributeMaxDynamicSharedMemorySize, TC_SMEM);
    cudaFuncSetAttribute((const void*)gemm_tc<1>,
                         cudaFuncAttributeMaxDynamicSharedMemorySize, TC_SMEM);
    cudaFuncSetAttribute((const void*)gemm_tc<2>,
                         cudaFuncAttributeMaxDynamicSharedMemorySize, TC_SMEM);

    float* h2p; float* xp; float* qp; float* vp; float* ap;
    __nv_bfloat16* whi; __nv_bfloat16* wlo;
    { void* t; cudaGetSymbolAddress(&t, g_h2);  h2p = (float*)t; }
    { void* t; cudaGetSymbolAddress(&t, g_x);   xp  = (float*)t; }
    { void* t; cudaGetSymbolAddress(&t, g_q);   qp  = (float*)t; }
    { void* t; cudaGetSymbolAddress(&t, g_v);   vp  = (float*)t; }
    { void* t; cudaGetSymbolAddress(&t, g_acc); ap  = (float*)t; }
    { void* t; cudaGetSymbolAddress(&t, g_Whi); whi = (__nv_bfloat16*)t; }
    { void* t; cudaGetSymbolAddress(&t, g_Wlo); wlo = (__nv_bfloat16*)t; }
    void* cntp = nullptr;
    cudaGetSymbolAddress(&cntp, g_cnt);
    cudaMemsetAsync(cntp, 0, (size_t)N * sizeof(int), 0);

    init_kernel<<<1, 256>>>(pos_enc);
    stats1_kernel<<<256, 256>>>(points, W1, N, W3, Wq, Wv, Wo);
    h2_kernel<<<(N + H2_PB - 1) / H2_PB, 256>>>(points, W1, g1, b1, W2, N);

    int gblocks = (N + BM - 1) / BM;
    // x = relu(bn2(h2)) @ W3 + b3 + feats     (profiled slot)
    gemm_tc<1><<<gblocks, 256, TC_SMEM>>>(h2p, whi + 0 * CH * CH, wlo + 0 * CH * CH,
                                          b3, xp, feats, g2, b2, N);
    // q = l2norm16(x @ Wq + bq)
    gemm_tc<2><<<gblocks, 256, TC_SMEM>>>(xp, whi + 1 * CH * CH, wlo + 1 * CH * CH,
                                          bq, qp, nullptr, nullptr, nullptr, N);
    // v = x @ Wv + bv
    gemm_tc<0><<<gblocks, 256, TC_SMEM>>>(xp, whi + 2 * CH * CH, wlo + 2 * CH * CH,
                                          bv, vp, nullptr, nullptr, nullptr, N);

    // counting sort
    hist_kernel<<<(M + 255) / 256, 256>>>(kq, M);
    scan_kernel<<<1, SCAN_T>>>(N);
    place_kernel<<<(M + 255) / 256, 256>>>(kq, M);

    // attention: segment gather, no atomics
    gather_kernel<<<(N + 7) / 8, 256>>>(N);

    // out = acc @ Wo + bo
    gemm_tc<0><<<gblocks, 256, TC_SMEM>>>(ap, whi + 3 * CH * CH, wlo + 3 * CH * CH,
                                          bo, (float*)d_out, nullptr, nullptr, nullptr, N);
}

// round 6
// speedup vs baseline: 1.3247x; 1.0094x over previous
#include <cuda_runtime.h>
#include <cuda_bf16.h>
#include <math.h>

#define N_MAX 100000
#define M_MAX 1600000
#define CH 128
#define KVOL 27
#define BN_EPS 1e-5f

// ---------------- scratch (device globals; no runtime allocation) ----------
__device__ float g_x  [(size_t)N_MAX * CH];
__device__ float g_q  [(size_t)N_MAX * CH];
__device__ float g_v  [(size_t)N_MAX * CH];
__device__ float g_acc[(size_t)N_MAX * CH];
__device__ float g_npe[KVOL * CH];
__device__ float g_s1[8];
__device__ float g_s2[2 * CH];
__device__ float g_bn1[6];       // sc0..2, shf0..2
__device__ int   g_cnt[N_MAX];
__device__ int   g_off[N_MAX];
__device__ int   g_cur[N_MAX];
__device__ int   g_sorted[M_MAX];
// weight panels, transposed to [n][k] K-major, bf16 split hi/lo
// index: 0=W3, 1=Wq, 2=Wv, 3=Wo
__device__ __nv_bfloat16 g_Whi[4][CH * CH];
__device__ __nv_bfloat16 g_Wlo[4][CH * CH];

// ---------------- init: zero stats + normalize pos_enc ---------------------
__global__ void init_kernel(const float* __restrict__ pos_enc) {
    int tid = threadIdx.x;
    if (tid < 8)  g_s1[tid] = 0.f;
    if (tid < 256) g_s2[tid] = 0.f;
    if (tid < KVOL * 8) {
        const float* src = pos_enc + tid * 16;
        float v[16]; float s = 0.f;
#pragma unroll
        for (int i = 0; i < 16; i++) { v[i] = src[i]; s += v[i] * v[i]; }
        float inv = 1.f / fmaxf(sqrtf(s), 1e-12f);
#pragma unroll
        for (int i = 0; i < 16; i++) g_npe[tid * 16 + i] = v[i] * inv;
    }
}

// ---------------- stats for BN1 + weight split/transpose -------------------
// grid MUST be 256 blocks x 256 threads (65536 = 4 * 128 * 128)
__global__ void __launch_bounds__(256) stats1_kernel(
        const float* __restrict__ points, const float* __restrict__ W1, int n,
        const float* __restrict__ W3, const float* __restrict__ Wq,
        const float* __restrict__ Wv, const float* __restrict__ Wo) {
    {
        int gt = blockIdx.x * 256 + threadIdx.x;   // 0..65535
        int w = gt >> 14;                          // 0..3
        int e = gt & 16383;
        int k = e >> 7, nn = e & 127;
        const float* Wsrc = (w == 0) ? W3 : (w == 1) ? Wq : (w == 2) ? Wv : Wo;
        float x = __ldg(&Wsrc[k * CH + nn]);
        __nv_bfloat16 hi = __float2bfloat16(x);
        __nv_bfloat16 lo = __float2bfloat16(x - __bfloat162float(hi));
        g_Whi[w][nn * CH + k] = hi;
        g_Wlo[w][nn * CH + k] = lo;
    }
    __shared__ float sh[6];
    if (threadIdx.x < 6) sh[threadIdx.x] = 0.f;
    __syncthreads();
    float w[9];
#pragma unroll
    for (int i = 0; i < 9; i++) w[i] = __ldg(&W1[i]);
    float s[3] = {0.f, 0.f, 0.f}, q[3] = {0.f, 0.f, 0.f};
    for (int i = blockIdx.x * blockDim.x + threadIdx.x; i < n;
         i += gridDim.x * blockDim.x) {
        float px = points[i * 3 + 0], py = points[i * 3 + 1], pz = points[i * 3 + 2];
#pragma unroll
        for (int j = 0; j < 3; j++) {
            float h = px * w[j] + py * w[3 + j] + pz * w[6 + j];
            s[j] += h; q[j] += h * h;
        }
    }
#pragma unroll
    for (int o = 16; o; o >>= 1) {
#pragma unroll
        for (int j = 0; j < 3; j++) {
            s[j] += __shfl_down_sync(0xFFFFFFFFu, s[j], o);
            q[j] += __shfl_down_sync(0xFFFFFFFFu, q[j], o);
        }
    }
    if ((threadIdx.x & 31) == 0) {
#pragma unroll
        for (int j = 0; j < 3; j++) {
            atomicAdd(&sh[j], s[j]);
            atomicAdd(&sh[3 + j], q[j]);
        }
    }
    __syncthreads();
    if (threadIdx.x < 6) atomicAdd(&g_s1[threadIdx.x], sh[threadIdx.x]);
}

// ---------------- BN2 stats only (h2 recomputed later, never stored) -------
#define H2_PB 128
__global__ void __launch_bounds__(256) h2_kernel(
        const float* __restrict__ points, const float* __restrict__ W1,
        const float* __restrict__ g1, const float* __restrict__ b1,
        const float* __restrict__ W2, int n) {
    __shared__ float ssum[CH], ssq[CH];
    int tid = threadIdx.x;
    if (tid < CH) { ssum[tid] = 0.f; ssq[tid] = 0.f; }
    __syncthreads();

    float w1[9];
#pragma unroll
    for (int i = 0; i < 9; i++) w1[i] = __ldg(&W1[i]);
    float invn = 1.f / (float)n;
    float sc[3], shf[3];
#pragma unroll
    for (int j = 0; j < 3; j++) {
        float mu  = g_s1[j] * invn;
        float var = g_s1[3 + j] * invn - mu * mu;
        float rs  = rsqrtf(var + BN_EPS);
        float s   = rs * __ldg(&g1[j]);
        sc[j] = s; shf[j] = __ldg(&b1[j]) - mu * s;
    }
    if (blockIdx.x == 0 && tid < 3) {       // publish bn1 affine for gemm1
        g_bn1[tid] = sc[tid];
        g_bn1[3 + tid] = shf[tid];
    }
    int lane = tid & 31, wid = tid >> 5;
    int c0 = lane * 4;
    float w2a[4], w2b[4], w2c[4];
#pragma unroll
    for (int i = 0; i < 4; i++) {
        w2a[i] = __ldg(&W2[0 * CH + c0 + i]);
        w2b[i] = __ldg(&W2[1 * CH + c0 + i]);
        w2c[i] = __ldg(&W2[2 * CH + c0 + i]);
    }
    float ls[4] = {0, 0, 0, 0}, lq[4] = {0, 0, 0, 0};
    int base = blockIdx.x * H2_PB;
    int nend = min(base + H2_PB, n);
    for (int p = base + wid; p < nend; p += 8) {
        float px = __ldg(&points[p * 3 + 0]);
        float py = __ldg(&points[p * 3 + 1]);
        float pz = __ldg(&points[p * 3 + 2]);
        float a[3];
#pragma unroll
        for (int j = 0; j < 3; j++) {
            float h = px * w1[j] + py * w1[3 + j] + pz * w1[6 + j];
            a[j] = fmaxf(h * sc[j] + shf[j], 0.f);
        }
#pragma unroll
        for (int i = 0; i < 4; i++) {
            float o = a[0] * w2a[i] + a[1] * w2b[i] + a[2] * w2c[i];
            ls[i] += o; lq[i] += o * o;
        }
    }
#pragma unroll
    for (int i = 0; i < 4; i++) {
        atomicAdd(&ssum[c0 + i], ls[i]);
        atomicAdd(&ssq[c0 + i], lq[i]);
    }
    __syncthreads();
    if (tid < CH) {
        atomicAdd(&g_s2[tid], ssum[tid]);
        atomicAdd(&g_s2[CH + tid], ssq[tid]);
    }
}

// ---------------- tensor-core GEMM (bf16 split, fp32 accum, LDSM) ----------
// BM=64 block tile, 2 CTAs/SM.
// MODE 0: C = A@W + bias
// MODE 1: A' = relu(bn2(relu(bn1(points@W1))@W2)); C = A'@W + bias + extra
// MODE 2: C = l2norm_per16(A@W + bias)
#define SASTRIDE 136
#define BM 64
#define TC_SMEM ((2 * BM * SASTRIDE + 2 * 128 * SASTRIDE) * 2 + 256 * 4)
#define PAIRB (16 * SASTRIDE * 2)

#define LDSM4(R0, R1, R2, R3, ADDR) \
    asm volatile("ldmatrix.sync.aligned.m8n8.x4.shared.b16 {%0,%1,%2,%3}, [%4];" \
        : "=r"(R0), "=r"(R1), "=r"(R2), "=r"(R3) : "r"(ADDR))

__device__ __forceinline__ void mma16816(float* c, const unsigned* a, const unsigned* b) {
    asm volatile(
        "mma.sync.aligned.m16n8k16.row.col.f32.bf16.bf16.f32 "
        "{%0,%1,%2,%3}, {%4,%5,%6,%7}, {%8,%9}, {%0,%1,%2,%3};"
        : "+f"(c[0]), "+f"(c[1]), "+f"(c[2]), "+f"(c[3])
        : "r"(a[0]), "r"(a[1]), "r"(a[2]), "r"(a[3]), "r"(b[0]), "r"(b[1]));
}

template <int MODE>
__global__ void __launch_bounds__(256, 2) gemm_tc(
        const float* __restrict__ A, const __nv_bfloat16* __restrict__ Bhi,
        const __nv_bfloat16* __restrict__ Blo, const float* __restrict__ bias,
        float* __restrict__ C, const float* __restrict__ extra,
        const float* __restrict__ gamma, const float* __restrict__ beta,
        const float* __restrict__ points, const float* __restrict__ W1,
        const float* __restrict__ W2, int nrows) {
    extern __shared__ char smraw[];
    __nv_bfloat16* sAhi = (__nv_bfloat16*)smraw;
    __nv_bfloat16* sAlo = sAhi + BM * SASTRIDE;
    __nv_bfloat16* sBhi = sAlo + BM * SASTRIDE;
    __nv_bfloat16* sBlo = sBhi + 128 * SASTRIDE;
    float* s_sc = (float*)(sBlo + 128 * SASTRIDE);
    float* s_sh = s_sc + CH;

    int tid = threadIdx.x;
    int row0 = blockIdx.x * BM;

    // ---- load B panels ([n][k] bf16, 16 uint4 per row) ----
#pragma unroll
    for (int i = 0; i < 8; i++) {
        int g = i * 256 + tid;           // uint4 index, 2048 total
        int nn = g >> 4;
        int kk = (g & 15) * 8;
        *(uint4*)&sBhi[nn * SASTRIDE + kk] = __ldg((const uint4*)&Bhi[nn * CH + kk]);
        *(uint4*)&sBlo[nn * SASTRIDE + kk] = __ldg((const uint4*)&Blo[nn * CH + kk]);
    }
    if (MODE == 1 && tid < CH) {
        float invn = 1.f / (float)nrows;
        float mu  = g_s2[tid] * invn;
        float var = g_s2[CH + tid] * invn - mu * mu;
        float rs  = rsqrtf(var + BN_EPS);
        float s   = rs * __ldg(&gamma[tid]);
        s_sc[tid] = s; s_sh[tid] = __ldg(&beta[tid]) - mu * s;
    }
    __syncthreads();

    // ---- build A tile (BM rows) in bf16 hi/lo split ----
    if (MODE == 1) {
        // recompute h2 row segment from points, then bn2+relu
        float w1[9];
#pragma unroll
        for (int i = 0; i < 9; i++) w1[i] = __ldg(&W1[i]);
        float sc1[3], sh1[3];
#pragma unroll
        for (int j = 0; j < 3; j++) { sc1[j] = g_bn1[j]; sh1[j] = g_bn1[3 + j]; }
#pragma unroll
        for (int i = 0; i < BM / 8; i++) {
            int g = i * 256 + tid;       // (row, 4-col group), BM*32 total
            int r = g >> 5;
            int c = (g & 31) * 4;
            int row = row0 + r;
            float4 a = make_float4(0.f, 0.f, 0.f, 0.f);
            if (row < nrows) {
                float px = __ldg(&points[row * 3 + 0]);
                float py = __ldg(&points[row * 3 + 1]);
                float pz = __ldg(&points[row * 3 + 2]);
                float t[3];
#pragma unroll
                for (int j = 0; j < 3; j++) {
                    float h = px * w1[j] + py * w1[3 + j] + pz * w1[6 + j];
                    t[j] = fmaxf(h * sc1[j] + sh1[j], 0.f);
                }
                float4 w20 = __ldg((const float4*)&W2[0 * CH + c]);
                float4 w21 = __ldg((const float4*)&W2[1 * CH + c]);
                float4 w22 = __ldg((const float4*)&W2[2 * CH + c]);
                a.x = t[0] * w20.x + t[1] * w21.x + t[2] * w22.x;
                a.y = t[0] * w20.y + t[1] * w21.y + t[2] * w22.y;
                a.z = t[0] * w20.z + t[1] * w21.z + t[2] * w22.z;
                a.w = t[0] * w20.w + t[1] * w21.w + t[2] * w22.w;
                a.x = fmaxf(a.x * s_sc[c + 0] + s_sh[c + 0], 0.f);
                a.y = fmaxf(a.y * s_sc[c + 1] + s_sh[c + 1], 0.f);
                a.z = fmaxf(a.z * s_sc[c + 2] + s_sh[c + 2], 0.f);
                a.w = fmaxf(a.w * s_sc[c + 3] + s_sh[c + 3], 0.f);
            }
            __nv_bfloat162 h0 = __floats2bfloat162_rn(a.x, a.y);
            __nv_bfloat162 h1 = __floats2bfloat162_rn(a.z, a.w);
            float2 h0f = __bfloat1622float2(h0);
            float2 h1f = __bfloat1622float2(h1);
            __nv_bfloat162 l0 = __floats2bfloat162_rn(a.x - h0f.x, a.y - h0f.y);
            __nv_bfloat162 l1 = __floats2bfloat162_rn(a.z - h1f.x, a.w - h1f.y);
            *(__nv_bfloat162*)&sAhi[r * SASTRIDE + c]     = h0;
            *(__nv_bfloat162*)&sAhi[r * SASTRIDE + c + 2] = h1;
            *(__nv_bfloat162*)&sAlo[r * SASTRIDE + c]     = l0;
            *(__nv_bfloat162*)&sAlo[r * SASTRIDE + c + 2] = l1;
        }
    } else {
#pragma unroll
        for (int i = 0; i < BM / 8; i++) {
            int g = i * 256 + tid;
            int r = g >> 5;
            int c = (g & 31) * 4;
            float4 a = make_float4(0.f, 0.f, 0.f, 0.f);
            if (row0 + r < nrows)
                a = __ldg((const float4*)&A[(size_t)(row0 + r) * CH + c]);
            __nv_bfloat162 h0 = __floats2bfloat162_rn(a.x, a.y);
            __nv_bfloat162 h1 = __floats2bfloat162_rn(a.z, a.w);
            float2 h0f = __bfloat1622float2(h0);
            float2 h1f = __bfloat1622float2(h1);
            __nv_bfloat162 l0 = __floats2bfloat162_rn(a.x - h0f.x, a.y - h0f.y);
            __nv_bfloat162 l1 = __floats2bfloat162_rn(a.z - h1f.x, a.w - h1f.y);
            *(__nv_bfloat162*)&sAhi[r * SASTRIDE + c]     = h0;
            *(__nv_bfloat162*)&sAhi[r * SASTRIDE + c + 2] = h1;
            *(__nv_bfloat162*)&sAlo[r * SASTRIDE + c]     = l0;
            *(__nv_bfloat162*)&sAlo[r * SASTRIDE + c + 2] = l1;
        }
    }
    __syncthreads();

    // ---- warp tiles: 8 warps = 4(m) x 2(n); warp tile 16x64 ----
    int wid = tid >> 5, lane = tid & 31;
    int warp_m = (wid >> 1) * 16;
    int warp_n = (wid & 1) * 64;
    int r = lane >> 2;
    int kq = (lane & 3) * 2;

    // LDSM per-lane addresses
    unsigned uAhi = (unsigned)__cvta_generic_to_shared(sAhi);
    unsigned uAlo = (unsigned)__cvta_generic_to_shared(sAlo);
    unsigned uBhi = (unsigned)__cvta_generic_to_shared(sBhi);
    unsigned uBlo = (unsigned)__cvta_generic_to_shared(sBlo);
    int arow = warp_m + (lane & 15);
    int acol = (lane >> 4) * 8;
    unsigned aHi = uAhi + (unsigned)((arow * SASTRIDE + acol) * 2);
    unsigned aLo = uAlo + (unsigned)((arow * SASTRIDE + acol) * 2);
    int brow = warp_n + (lane & 7) + ((lane >> 4) & 1) * 8;
    int bcol = ((lane >> 3) & 1) * 8;
    unsigned bHi = uBhi + (unsigned)((brow * SASTRIDE + bcol) * 2);
    unsigned bLo = uBlo + (unsigned)((brow * SASTRIDE + bcol) * 2);

    float acc[8][4];
#pragma unroll
    for (int nt = 0; nt < 8; nt++)
#pragma unroll
        for (int j = 0; j < 4; j++) acc[nt][j] = 0.f;

#pragma unroll
    for (int ks = 0; ks < 8; ks++) {
        unsigned ko = ks * 32;           // 16 bf16 = 32 bytes per k-step
        unsigned ahi[4], alo[4];
        LDSM4(ahi[0], ahi[1], ahi[2], ahi[3], aHi + ko);
        LDSM4(alo[0], alo[1], alo[2], alo[3], aLo + ko);
#pragma unroll
        for (int p = 0; p < 4; p++) {
            unsigned bh[4], bl[4];
            LDSM4(bh[0], bh[1], bh[2], bh[3], bHi + p * PAIRB + ko);
            LDSM4(bl[0], bl[1], bl[2], bl[3], bLo + p * PAIRB + ko);
            mma16816(acc[2 * p],     ahi, bh);
            mma16816(acc[2 * p],     ahi, bl);
            mma16816(acc[2 * p],     alo, bh);
            mma16816(acc[2 * p + 1], ahi, bh + 2);
            mma16816(acc[2 * p + 1], ahi, bl + 2);
            mma16816(acc[2 * p + 1], alo, bh + 2);
        }
    }

    // ---- epilogue ----
    int row_lo = row0 + warp_m + r;
    int row_hi = row_lo + 8;
    bool ok_lo = row_lo < nrows, ok_hi = row_hi < nrows;
#pragma unroll
    for (int nt = 0; nt < 8; nt++) {
        int col = warp_n + nt * 8 + kq;
        float2 bs = *(const float2*)&bias[col];
        acc[nt][0] += bs.x; acc[nt][1] += bs.y;
        acc[nt][2] += bs.x; acc[nt][3] += bs.y;
        if (MODE == 1) {
            if (ok_lo) {
                float2 e = __ldg((const float2*)&extra[(size_t)row_lo * CH + col]);
                acc[nt][0] += e.x; acc[nt][1] += e.y;
            }
            if (ok_hi) {
                float2 e = __ldg((const float2*)&extra[(size_t)row_hi * CH + col]);
                acc[nt][2] += e.x; acc[nt][3] += e.y;
            }
        }
    }
    if (MODE == 2) {
#pragma unroll
        for (int hp = 0; hp < 4; hp++) {
            int n0 = hp * 2, n1 = n0 + 1;
            float s0 = acc[n0][0] * acc[n0][0] + acc[n0][1] * acc[n0][1]
                     + acc[n1][0] * acc[n1][0] + acc[n1][1] * acc[n1][1];
            float s1 = acc[n0][2] * acc[n0][2] + acc[n0][3] * acc[n0][3]
                     + acc[n1][2] * acc[n1][2] + acc[n1][3] * acc[n1][3];
            s0 += __shfl_xor_sync(0xFFFFFFFFu, s0, 1);
            s0 += __shfl_xor_sync(0xFFFFFFFFu, s0, 2);
            s1 += __shfl_xor_sync(0xFFFFFFFFu, s1, 1);
            s1 += __shfl_xor_sync(0xFFFFFFFFu, s1, 2);
            float i0 = 1.f / fmaxf(sqrtf(s0), 1e-12f);
            float i1 = 1.f / fmaxf(sqrtf(s1), 1e-12f);
            acc[n0][0] *= i0; acc[n0][1] *= i0;
            acc[n1][0] *= i0; acc[n1][1] *= i0;
            acc[n0][2] *= i1; acc[n0][3] *= i1;
            acc[n1][2] *= i1; acc[n1][3] *= i1;
        }
    }
#pragma unroll
    for (int nt = 0; nt < 8; nt++) {
        int col = warp_n + nt * 8 + kq;
        if (ok_lo)
            *(float2*)&C[(size_t)row_lo * CH + col] =
                make_float2(acc[nt][0], acc[nt][1]);
        if (ok_hi)
            *(float2*)&C[(size_t)row_hi * CH + col] =
                make_float2(acc[nt][2], acc[nt][3]);
    }
}

// ---------------- counting sort of map entries by q_idx --------------------
__global__ void __launch_bounds__(256) hist_kernel(const int* __restrict__ kq, int M) {
    int i = blockIdx.x * blockDim.x + threadIdx.x;
    if (i < M) atomicAdd(&g_cnt[__ldg(&kq[M + i])], 1);
}

#define SCAN_T 1024
__global__ void __launch_bounds__(SCAN_T) scan_kernel(int n) {
    __shared__ int ssum[SCAN_T];
    int t = threadIdx.x;
    int chunk = (n + SCAN_T - 1) / SCAN_T;
    int beg = t * chunk, end = min(beg + chunk, n);
    int s = 0;
    for (int i = beg; i < end; i++) s += g_cnt[i];
    ssum[t] = s;
    __syncthreads();
    for (int o = 1; o < SCAN_T; o <<= 1) {
        int v = (t >= o) ? ssum[t - o] : 0;
        __syncthreads();
        ssum[t] += v;
        __syncthreads();
    }
    int run = (t == 0) ? 0 : ssum[t - 1];
    for (int i = beg; i < end; i++) {
        g_off[i] = run; g_cur[i] = run;
        run += g_cnt[i];
    }
}

__global__ void __launch_bounds__(256) place_kernel(const int* __restrict__ kq, int M) {
    int i = blockIdx.x * blockDim.x + threadIdx.x;
    if (i < M) {
        int q = __ldg(&kq[M + i]);
        int pos = atomicAdd(&g_cur[q], 1);
        g_sorted[pos] = __ldg(&kq[i]);
    }
}

// ---------------- segment gather: warp per query, batched, no atomics ------
__global__ void __launch_bounds__(256) gather_kernel(int n) {
    int gw = (blockIdx.x * blockDim.x + threadIdx.x) >> 5;
    if (gw >= n) return;
    int lane = threadIdx.x & 31;
    int c4 = lane * 4;
    int beg = __ldg(&g_off[gw]);
    int cnt = __ldg(&g_cnt[gw]);
    float4 qv = __ldcs((const float4*)&g_q[(size_t)gw * CH + c4]);  // once-read
    float4 acc = make_float4(0.f, 0.f, 0.f, 0.f);

    int i = 0;
#pragma unroll 2
    for (; i + 4 <= cnt; i += 4) {
        int key[4], kern[4];
#pragma unroll
        for (int j = 0; j < 4; j++) {
            int e = __ldg(&g_sorted[beg + i + j]);
            key[j]  = e / KVOL;
            kern[j] = e - key[j] * KVOL;
        }
        float4 v[4];
#pragma unroll
        for (int j = 0; j < 4; j++)
            v[j] = __ldg((const float4*)&g_v[(size_t)key[j] * CH + c4]);
        float s[4];
#pragma unroll
        for (int j = 0; j < 4; j++) {
            float4 p = __ldg((const float4*)&g_npe[kern[j] * CH + c4]);
            float t = qv.x * p.x + qv.y * p.y + qv.z * p.z + qv.w * p.w;
            t += __shfl_xor_sync(0xFFFFFFFFu, t, 1);
            t += __shfl_xor_sync(0xFFFFFFFFu, t, 2);
            s[j] = t;
        }
#pragma unroll
        for (int j = 0; j < 4; j++) {
            acc.x = fmaf(s[j], v[j].x, acc.x);
            acc.y = fmaf(s[j], v[j].y, acc.y);
            acc.z = fmaf(s[j], v[j].z, acc.z);
            acc.w = fmaf(s[j], v[j].w, acc.w);
        }
    }
    for (; i < cnt; i++) {
        int e = __ldg(&g_sorted[beg + i]);
        int key = e / KVOL;
        int kern = e - key * KVOL;
        float4 v = __ldg((const float4*)&g_v[(size_t)key * CH + c4]);
        float4 p = __ldg((const float4*)&g_npe[kern * CH + c4]);
        float t = qv.x * p.x + qv.y * p.y + qv.z * p.z + qv.w * p.w;
        t += __shfl_xor_sync(0xFFFFFFFFu, t, 1);
        t += __shfl_xor_sync(0xFFFFFFFFu, t, 2);
        acc.x = fmaf(t, v.x, acc.x);
        acc.y = fmaf(t, v.y, acc.y);
        acc.z = fmaf(t, v.z, acc.z);
        acc.w = fmaf(t, v.w, acc.w);
    }
    __stcs((float4*)&g_acc[(size_t)gw * CH + c4], acc);  // once-written
}

// ---------------- host launch ----------------------------------------------
extern "C" void kernel_launch(void* const* d_in, const int* in_sizes, int n_in,
                              void* d_out, int out_size) {
    const float* feats   = (const float*)d_in[0];
    const float* points  = (const float*)d_in[1];
    const int*   kq      = (const int*)d_in[2];
    const float* W1 = (const float*)d_in[3];
    const float* g1 = (const float*)d_in[4];
    const float* b1 = (const float*)d_in[5];
    const float* W2 = (const float*)d_in[6];
    const float* g2 = (const float*)d_in[7];
    const float* b2 = (const float*)d_in[8];
    const float* W3 = (const float*)d_in[9];
    const float* b3 = (const float*)d_in[10];
    const float* Wq = (const float*)d_in[11];
    const float* bq = (const float*)d_in[12];
    const float* Wv = (const float*)d_in[13];
    const float* bv = (const float*)d_in[14];
    const float* pos_enc = (const float*)d_in[15];
    const float* Wo = (const float*)d_in[16];
    const float* bo = (const float*)d_in[17];

    int N = in_sizes[0] / CH;
    int M = in_sizes[2] / 2;

    cudaFuncSetAttribute((const void*)gemm_tc<0>,
                         cudaFuncAttributeMaxDynamicSharedMemorySize, TC_SMEM);
    cudaFuncSetAttribute((const void*)gemm_tc<1>,
                         cudaFuncAttributeMaxDynamicSharedMemorySize, TC_SMEM);
    cudaFuncSetAttribute((const void*)gemm_tc<2>,
                         cudaFuncAttributeMaxDynamicSharedMemorySize, TC_SMEM);

    float* xp; float* qp; float* vp; float* ap;
    __nv_bfloat16* whi; __nv_bfloat16* wlo;
    { void* t; cudaGetSymbolAddress(&t, g_x);   xp  = (float*)t; }
    { void* t; cudaGetSymbolAddress(&t, g_q);   qp  = (float*)t; }
    { void* t; cudaGetSymbolAddress(&t, g_v);   vp  = (float*)t; }
    { void* t; cudaGetSymbolAddress(&t, g_acc); ap  = (float*)t; }
    { void* t; cudaGetSymbolAddress(&t, g_Whi); whi = (__nv_bfloat16*)t; }
    { void* t; cudaGetSymbolAddress(&t, g_Wlo); wlo = (__nv_bfloat16*)t; }
    void* cntp = nullptr;
    cudaGetSymbolAddress(&cntp, g_cnt);
    cudaMemsetAsync(cntp, 0, (size_t)N * sizeof(int), 0);

    init_kernel<<<1, 256>>>(pos_enc);
    stats1_kernel<<<256, 256>>>(points, W1, N, W3, Wq, Wv, Wo);
    h2_kernel<<<(N + H2_PB - 1) / H2_PB, 256>>>(points, W1, g1, b1, W2, N);

    int gblocks = (N + BM - 1) / BM;
    // x = relu(bn2(h2(points))) @ W3 + b3 + feats   (h2 recomputed in-kernel)
    gemm_tc<1><<<gblocks, 256, TC_SMEM>>>(nullptr, whi + 0 * CH * CH, wlo + 0 * CH * CH,
                                          b3, xp, feats, g2, b2, points, W1, W2, N);
    // q = l2norm16(x @ Wq + bq)
    gemm_tc<2><<<gblocks, 256, TC_SMEM>>>(xp, whi + 1 * CH * CH, wlo + 1 * CH * CH,
                                          bq, qp, nullptr, nullptr, nullptr,
                                          nullptr, nullptr, nullptr, N);
    // v = x @ Wv + bv
    gemm_tc<0><<<gblocks, 256, TC_SMEM>>>(xp, whi + 2 * CH * CH, wlo + 2 * CH * CH,
                                          bv, vp, nullptr, nullptr, nullptr,
                                          nullptr, nullptr, nullptr, N);

    // counting sort
    hist_kernel<<<(M + 255) / 256, 256>>>(kq, M);
    scan_kernel<<<1, SCAN_T>>>(N);
    place_kernel<<<(M + 255) / 256, 256>>>(kq, M);

    // attention: segment gather, no atomics
    gather_kernel<<<(N + 7) / 8, 256>>>(N);

    // out = acc @ Wo + bo
    gemm_tc<0><<<gblocks, 256, TC_SMEM>>>(ap, whi + 3 * CH * CH, wlo + 3 * CH * CH,
                                          bo, (float*)d_out, nullptr, nullptr, nullptr,
                                          nullptr, nullptr, nullptr, N);
}

// round 7
// speedup vs baseline: 1.4137x; 1.0672x over previous
#include <cuda_runtime.h>
#include <cuda_bf16.h>
#include <math.h>

#define N_MAX 100000
#define M_MAX 1600000
#define CH 128
#define KVOL 27
#define BN_EPS 1e-5f

// ---------------- scratch (device globals; no runtime allocation) ----------
__device__ float g_x  [(size_t)N_MAX * CH];
__device__ float g_q  [(size_t)N_MAX * CH];
__device__ float g_v  [(size_t)N_MAX * CH];
__device__ float g_acc[(size_t)N_MAX * CH];
__device__ float g_npe[KVOL * CH];
__device__ float g_s1[8];
__device__ float g_s2[2 * CH];
__device__ float g_bn1[6];       // sc0..2, shf0..2
__device__ int   g_cnt[N_MAX];
__device__ int   g_off[N_MAX];
__device__ int   g_cur[N_MAX];
__device__ int   g_sorted[M_MAX];
// weight panels, transposed to [n][k] K-major, bf16 split hi/lo
// index: 0=W3, 1=Wq, 2=Wv, 3=Wo
__device__ __nv_bfloat16 g_Whi[4][CH * CH];
__device__ __nv_bfloat16 g_Wlo[4][CH * CH];

// ---------------- init: zero stats + normalize pos_enc ---------------------
__global__ void init_kernel(const float* __restrict__ pos_enc) {
    int tid = threadIdx.x;
    if (tid < 8)  g_s1[tid] = 0.f;
    if (tid < 256) g_s2[tid] = 0.f;
    if (tid < KVOL * 8) {
        const float* src = pos_enc + tid * 16;
        float v[16]; float s = 0.f;
#pragma unroll
        for (int i = 0; i < 16; i++) { v[i] = src[i]; s += v[i] * v[i]; }
        float inv = 1.f / fmaxf(sqrtf(s), 1e-12f);
#pragma unroll
        for (int i = 0; i < 16; i++) g_npe[tid * 16 + i] = v[i] * inv;
    }
}

// ---------------- stats for BN1 + weight prep + q-histogram (fused) --------
// grid MUST be 256 blocks x 256 threads (65536 = 4 * 128 * 128)
__global__ void __launch_bounds__(256) stats1_kernel(
        const float* __restrict__ points, const float* __restrict__ W1, int n,
        const float* __restrict__ W3, const float* __restrict__ Wq,
        const float* __restrict__ Wv, const float* __restrict__ Wo,
        const int* __restrict__ kq, int M) {
    int gid = blockIdx.x * 256 + threadIdx.x;      // 0..65535
    {
        int w = gid >> 14;
        int e = gid & 16383;
        int k = e >> 7, nn = e & 127;
        const float* Wsrc = (w == 0) ? W3 : (w == 1) ? Wq : (w == 2) ? Wv : Wo;
        float x = __ldg(&Wsrc[k * CH + nn]);
        __nv_bfloat16 hi = __float2bfloat16(x);
        __nv_bfloat16 lo = __float2bfloat16(x - __bfloat162float(hi));
        g_Whi[w][nn * CH + k] = hi;
        g_Wlo[w][nn * CH + k] = lo;
    }
    // fused histogram of q_idx
    for (int i = gid; i < M; i += 65536)
        atomicAdd(&g_cnt[__ldg(&kq[M + i])], 1);

    __shared__ float sh[6];
    if (threadIdx.x < 6) sh[threadIdx.x] = 0.f;
    __syncthreads();
    float w[9];
#pragma unroll
    for (int i = 0; i < 9; i++) w[i] = __ldg(&W1[i]);
    float s[3] = {0.f, 0.f, 0.f}, q[3] = {0.f, 0.f, 0.f};
    for (int i = gid; i < n; i += 65536) {
        float px = points[i * 3 + 0], py = points[i * 3 + 1], pz = points[i * 3 + 2];
#pragma unroll
        for (int j = 0; j < 3; j++) {
            float h = px * w[j] + py * w[3 + j] + pz * w[6 + j];
            s[j] += h; q[j] += h * h;
        }
    }
#pragma unroll
    for (int o = 16; o; o >>= 1) {
#pragma unroll
        for (int j = 0; j < 3; j++) {
            s[j] += __shfl_down_sync(0xFFFFFFFFu, s[j], o);
            q[j] += __shfl_down_sync(0xFFFFFFFFu, q[j], o);
        }
    }
    if ((threadIdx.x & 31) == 0) {
#pragma unroll
        for (int j = 0; j < 3; j++) {
            atomicAdd(&sh[j], s[j]);
            atomicAdd(&sh[3 + j], q[j]);
        }
    }
    __syncthreads();
    if (threadIdx.x < 6) atomicAdd(&g_s1[threadIdx.x], sh[threadIdx.x]);
}

// ---------------- BN2 stats only (h2 recomputed in gemm, never stored) -----
#define H2_PB 128
__global__ void __launch_bounds__(256) h2_kernel(
        const float* __restrict__ points, const float* __restrict__ W1,
        const float* __restrict__ g1, const float* __restrict__ b1,
        const float* __restrict__ W2, int n) {
    __shared__ float ssum[CH], ssq[CH];
    int tid = threadIdx.x;
    if (tid < CH) { ssum[tid] = 0.f; ssq[tid] = 0.f; }
    __syncthreads();

    float w1[9];
#pragma unroll
    for (int i = 0; i < 9; i++) w1[i] = __ldg(&W1[i]);
    float invn = 1.f / (float)n;
    float sc[3], shf[3];
#pragma unroll
    for (int j = 0; j < 3; j++) {
        float mu  = g_s1[j] * invn;
        float var = g_s1[3 + j] * invn - mu * mu;
        float rs  = rsqrtf(var + BN_EPS);
        float s   = rs * __ldg(&g1[j]);
        sc[j] = s; shf[j] = __ldg(&b1[j]) - mu * s;
    }
    if (blockIdx.x == 0 && tid < 3) {
        g_bn1[tid] = sc[tid];
        g_bn1[3 + tid] = shf[tid];
    }
    int lane = tid & 31, wid = tid >> 5;
    int c0 = lane * 4;
    float w2a[4], w2b[4], w2c[4];
#pragma unroll
    for (int i = 0; i < 4; i++) {
        w2a[i] = __ldg(&W2[0 * CH + c0 + i]);
        w2b[i] = __ldg(&W2[1 * CH + c0 + i]);
        w2c[i] = __ldg(&W2[2 * CH + c0 + i]);
    }
    float ls[4] = {0, 0, 0, 0}, lq[4] = {0, 0, 0, 0};
    int base = blockIdx.x * H2_PB;
    int nend = min(base + H2_PB, n);
    for (int p = base + wid; p < nend; p += 8) {
        float px = __ldg(&points[p * 3 + 0]);
        float py = __ldg(&points[p * 3 + 1]);
        float pz = __ldg(&points[p * 3 + 2]);
        float a[3];
#pragma unroll
        for (int j = 0; j < 3; j++) {
            float h = px * w1[j] + py * w1[3 + j] + pz * w1[6 + j];
            a[j] = fmaxf(h * sc[j] + shf[j], 0.f);
        }
#pragma unroll
        for (int i = 0; i < 4; i++) {
            float o = a[0] * w2a[i] + a[1] * w2b[i] + a[2] * w2c[i];
            ls[i] += o; lq[i] += o * o;
        }
    }
#pragma unroll
    for (int i = 0; i < 4; i++) {
        atomicAdd(&ssum[c0 + i], ls[i]);
        atomicAdd(&ssq[c0 + i], lq[i]);
    }
    __syncthreads();
    if (tid < CH) {
        atomicAdd(&g_s2[tid], ssum[tid]);
        atomicAdd(&g_s2[CH + tid], ssq[tid]);
    }
}

// ---------------- persistent tensor-core GEMM (bf16 split, LDSM) -----------
// B panels staged ONCE per CTA; BM=32 tiles looped with double-buffered A.
// MODE 0: C = A@W + bias
// MODE 1: A' = relu(bn2(relu(bn1(points@W1))@W2)); C = A'@W + bias + extra
// MODE 2: C = l2norm_per16(A@W + bias)
#define SASTRIDE 136
#define BM 32
#define SB_ELEMS (128 * SASTRIDE)
#define ABUF_ELEMS (BM * SASTRIDE)          // per hi/lo buffer
#define TC_SMEM ((2 * SB_ELEMS + 4 * ABUF_ELEMS) * 2 + 256 * 4)
#define GEMM_GRID 296

#define LDSM4(R0, R1, R2, R3, ADDR) \
    asm volatile("ldmatrix.sync.aligned.m8n8.x4.shared.b16 {%0,%1,%2,%3}, [%4];" \
        : "=r"(R0), "=r"(R1), "=r"(R2), "=r"(R3) : "r"(ADDR))

__device__ __forceinline__ void mma16816(float* c, const unsigned* a, const unsigned* b) {
    asm volatile(
        "mma.sync.aligned.m16n8k16.row.col.f32.bf16.bf16.f32 "
        "{%0,%1,%2,%3}, {%4,%5,%6,%7}, {%8,%9}, {%0,%1,%2,%3};"
        : "+f"(c[0]), "+f"(c[1]), "+f"(c[2]), "+f"(c[3])
        : "r"(a[0]), "r"(a[1]), "r"(a[2]), "r"(a[3]), "r"(b[0]), "r"(b[1]));
}

template <int MODE>
__global__ void __launch_bounds__(256, 2) gemm_p(
        const float* __restrict__ A, const __nv_bfloat16* __restrict__ Bhi,
        const __nv_bfloat16* __restrict__ Blo, const float* __restrict__ bias,
        float* __restrict__ C, const float* __restrict__ extra,
        const float* __restrict__ gamma, const float* __restrict__ beta,
        const float* __restrict__ points, const float* __restrict__ W1,
        const float* __restrict__ W2, int nrows) {
    extern __shared__ char smraw[];
    __nv_bfloat16* sBhi = (__nv_bfloat16*)smraw;
    __nv_bfloat16* sBlo = sBhi + SB_ELEMS;
    __nv_bfloat16* sA   = sBlo + SB_ELEMS;      // [buf][hi|lo]
    float* s_sc = (float*)(sA + 4 * ABUF_ELEMS);
    float* s_sh = s_sc + CH;

    int tid = threadIdx.x;

    // ---- stage B panels once ----
#pragma unroll
    for (int i = 0; i < 8; i++) {
        int g = i * 256 + tid;           // uint4 index, 2048 total
        int nn = g >> 4;
        int kk = (g & 15) * 8;
        *(uint4*)&sBhi[nn * SASTRIDE + kk] = __ldg((const uint4*)&Bhi[nn * CH + kk]);
        *(uint4*)&sBlo[nn * SASTRIDE + kk] = __ldg((const uint4*)&Blo[nn * CH + kk]);
    }
    if (MODE == 1 && tid < CH) {
        float invn = 1.f / (float)nrows;
        float mu  = g_s2[tid] * invn;
        float var = g_s2[CH + tid] * invn - mu * mu;
        float rs  = rsqrtf(var + BN_EPS);
        float s   = rs * __ldg(&gamma[tid]);
        s_sc[tid] = s; s_sh[tid] = __ldg(&beta[tid]) - mu * s;
    }
    __syncthreads();

    // ---- per-thread loop-invariant constants ----
    int rbase = tid >> 5;                // 0..7: handles rows rbase, +8, +16, +24
    int c = (tid & 31) * 4;              // fixed 4-col group
    float w1[9], sc1[3], sh1[3];
    float4 w20, w21, w22, sc4, sh4;
    if (MODE == 1) {
#pragma unroll
        for (int i = 0; i < 9; i++) w1[i] = __ldg(&W1[i]);
#pragma unroll
        for (int j = 0; j < 3; j++) { sc1[j] = g_bn1[j]; sh1[j] = g_bn1[3 + j]; }
        w20 = __ldg((const float4*)&W2[0 * CH + c]);
        w21 = __ldg((const float4*)&W2[1 * CH + c]);
        w22 = __ldg((const float4*)&W2[2 * CH + c]);
        sc4 = *(const float4*)&s_sc[c];
        sh4 = *(const float4*)&s_sh[c];
    }

    // warp tiling: 8 warps = 2(m) x 4(n); warp tile 16x32
    int wid = tid >> 5, lane = tid & 31;
    int warp_m = (wid & 1) * 16;
    int warp_n = (wid >> 1) * 32;
    int rq = lane >> 2;
    int kq = (lane & 3) * 2;

    unsigned uA   = (unsigned)__cvta_generic_to_shared(sA);
    unsigned uBhi = (unsigned)__cvta_generic_to_shared(sBhi);
    unsigned uBlo = (unsigned)__cvta_generic_to_shared(sBlo);
    int arow = warp_m + (lane & 15);
    int acol = (lane >> 4) * 8;
    unsigned aOff = (unsigned)((arow * SASTRIDE + acol) * 2);
    int brow = warp_n + (lane & 7) + ((lane >> 4) & 1) * 8;
    int bcol = ((lane >> 3) & 1) * 8;
    unsigned bHi = uBhi + (unsigned)((brow * SASTRIDE + bcol) * 2);
    unsigned bLo = uBlo + (unsigned)((brow * SASTRIDE + bcol) * 2);
    const unsigned BROW16 = 16 * SASTRIDE * 2;
    const unsigned ABUF_B = 2 * ABUF_ELEMS * 2;   // bytes per buffer (hi+lo)
    const unsigned ALO_B  = ABUF_ELEMS * 2;

    int ntiles = (nrows + BM - 1) / BM;
    int t = blockIdx.x;

    // ---- prefetch A values for first tile ----
    float4 pref[4];
#define LOAD_PREF(TT)                                                         \
    {                                                                         \
        _Pragma("unroll")                                                     \
        for (int i = 0; i < 4; i++) {                                         \
            int row = (TT) * BM + i * 8 + rbase;                              \
            float4 a = make_float4(0.f, 0.f, 0.f, 0.f);                       \
            if (row < nrows) {                                                \
                if (MODE == 1) {                                              \
                    float px = __ldg(&points[row * 3 + 0]);                   \
                    float py = __ldg(&points[row * 3 + 1]);                   \
                    float pz = __ldg(&points[row * 3 + 2]);                   \
                    float t0 = fmaxf(fmaf(px * w1[0] + py * w1[3] + pz * w1[6], sc1[0], sh1[0]), 0.f); \
                    float t1 = fmaxf(fmaf(px * w1[1] + py * w1[4] + pz * w1[7], sc1[1], sh1[1]), 0.f); \
                    float t2 = fmaxf(fmaf(px * w1[2] + py * w1[5] + pz * w1[8], sc1[2], sh1[2]), 0.f); \
                    a.x = fmaxf(fmaf(t0 * w20.x + t1 * w21.x + t2 * w22.x, sc4.x, sh4.x), 0.f); \
                    a.y = fmaxf(fmaf(t0 * w20.y + t1 * w21.y + t2 * w22.y, sc4.y, sh4.y), 0.f); \
                    a.z = fmaxf(fmaf(t0 * w20.z + t1 * w21.z + t2 * w22.z, sc4.z, sh4.z), 0.f); \
                    a.w = fmaxf(fmaf(t0 * w20.w + t1 * w21.w + t2 * w22.w, sc4.w, sh4.w), 0.f); \
                } else {                                                      \
                    a = __ldg((const float4*)&A[(size_t)row * CH + c]);       \
                }                                                             \
            }                                                                 \
            pref[i] = a;                                                      \
        }                                                                     \
    }
    if (t < ntiles) LOAD_PREF(t);

    int it = 0;
    while (t < ntiles) {
        int buf = it & 1;
        __nv_bfloat16* sAhi = sA + buf * 2 * ABUF_ELEMS;
        __nv_bfloat16* sAlo = sAhi + ABUF_ELEMS;
        // ---- store prefetched A tile (convert + split) ----
#pragma unroll
        for (int i = 0; i < 4; i++) {
            int r = i * 8 + rbase;
            float4 a = pref[i];
            __nv_bfloat162 h0 = __floats2bfloat162_rn(a.x, a.y);
            __nv_bfloat162 h1 = __floats2bfloat162_rn(a.z, a.w);
            float2 h0f = __bfloat1622float2(h0);
            float2 h1f = __bfloat1622float2(h1);
            __nv_bfloat162 l0 = __floats2bfloat162_rn(a.x - h0f.x, a.y - h0f.y);
            __nv_bfloat162 l1 = __floats2bfloat162_rn(a.z - h1f.x, a.w - h1f.y);
            *(__nv_bfloat162*)&sAhi[r * SASTRIDE + c]     = h0;
            *(__nv_bfloat162*)&sAhi[r * SASTRIDE + c + 2] = h1;
            *(__nv_bfloat162*)&sAlo[r * SASTRIDE + c]     = l0;
            *(__nv_bfloat162*)&sAlo[r * SASTRIDE + c + 2] = l1;
        }
        __syncthreads();

        int row_lo = t * BM + warp_m + rq;
        int row_hi = row_lo + 8;
        bool ok_lo = row_lo < nrows, ok_hi = row_hi < nrows;

        // ---- prefetch epilogue 'extra' for current tile (overlaps MMA) ----
        float2 ext[8];
        if (MODE == 1) {
#pragma unroll
            for (int nt = 0; nt < 4; nt++) {
                int col = warp_n + nt * 8 + kq;
                ext[nt]     = ok_lo ? __ldg((const float2*)&extra[(size_t)row_lo * CH + col])
                                    : make_float2(0.f, 0.f);
                ext[4 + nt] = ok_hi ? __ldg((const float2*)&extra[(size_t)row_hi * CH + col])
                                    : make_float2(0.f, 0.f);
            }
        }
        // ---- prefetch A for next tile (overlaps MMA) ----
        int tn = t + GEMM_GRID;
        if (tn < ntiles) LOAD_PREF(tn);

        // ---- MMA ----
        unsigned aHi = uA + buf * ABUF_B + aOff;
        unsigned aLo = aHi + ALO_B;
        float acc[4][4];
#pragma unroll
        for (int nt = 0; nt < 4; nt++)
#pragma unroll
            for (int j = 0; j < 4; j++) acc[nt][j] = 0.f;
#pragma unroll
        for (int ks = 0; ks < 8; ks++) {
            unsigned ko = ks * 32;
            unsigned ah[4], al[4];
            LDSM4(ah[0], ah[1], ah[2], ah[3], aHi + ko);
            LDSM4(al[0], al[1], al[2], al[3], aLo + ko);
            unsigned bh[8], bl[8];
            LDSM4(bh[0], bh[1], bh[2], bh[3], bHi + ko);
            LDSM4(bh[4], bh[5], bh[6], bh[7], bHi + BROW16 + ko);
            LDSM4(bl[0], bl[1], bl[2], bl[3], bLo + ko);
            LDSM4(bl[4], bl[5], bl[6], bl[7], bLo + BROW16 + ko);
#pragma unroll
            for (int nt = 0; nt < 4; nt++) {
                mma16816(acc[nt], ah, bh + 2 * nt);
                mma16816(acc[nt], ah, bl + 2 * nt);
                mma16816(acc[nt], al, bh + 2 * nt);
            }
        }

        // ---- epilogue ----
#pragma unroll
        for (int nt = 0; nt < 4; nt++) {
            int col = warp_n + nt * 8 + kq;
            float2 bs = *(const float2*)&bias[col];
            acc[nt][0] += bs.x; acc[nt][1] += bs.y;
            acc[nt][2] += bs.x; acc[nt][3] += bs.y;
            if (MODE == 1) {
                acc[nt][0] += ext[nt].x;     acc[nt][1] += ext[nt].y;
                acc[nt][2] += ext[4 + nt].x; acc[nt][3] += ext[4 + nt].y;
            }
        }
        if (MODE == 2) {
#pragma unroll
            for (int hp = 0; hp < 2; hp++) {
                int n0 = hp * 2, n1 = n0 + 1;
                float s0 = acc[n0][0] * acc[n0][0] + acc[n0][1] * acc[n0][1]
                         + acc[n1][0] * acc[n1][0] + acc[n1][1] * acc[n1][1];
                float s1 = acc[n0][2] * acc[n0][2] + acc[n0][3] * acc[n0][3]
                         + acc[n1][2] * acc[n1][2] + acc[n1][3] * acc[n1][3];
                s0 += __shfl_xor_sync(0xFFFFFFFFu, s0, 1);
                s0 += __shfl_xor_sync(0xFFFFFFFFu, s0, 2);
                s1 += __shfl_xor_sync(0xFFFFFFFFu, s1, 1);
                s1 += __shfl_xor_sync(0xFFFFFFFFu, s1, 2);
                float i0 = 1.f / fmaxf(sqrtf(s0), 1e-12f);
                float i1 = 1.f / fmaxf(sqrtf(s1), 1e-12f);
                acc[n0][0] *= i0; acc[n0][1] *= i0;
                acc[n1][0] *= i0; acc[n1][1] *= i0;
                acc[n0][2] *= i1; acc[n0][3] *= i1;
                acc[n1][2] *= i1; acc[n1][3] *= i1;
            }
        }
#pragma unroll
        for (int nt = 0; nt < 4; nt++) {
            int col = warp_n + nt * 8 + kq;
            if (ok_lo)
                *(float2*)&C[(size_t)row_lo * CH + col] =
                    make_float2(acc[nt][0], acc[nt][1]);
            if (ok_hi)
                *(float2*)&C[(size_t)row_hi * CH + col] =
                    make_float2(acc[nt][2], acc[nt][3]);
        }
        t = tn; ++it;
    }
#undef LOAD_PREF
}

// ---------------- counting sort scan + placement ----------------------------
#define SCAN_T 1024
__global__ void __launch_bounds__(SCAN_T) scan_kernel(int n) {
    __shared__ int ssum[SCAN_T];
    int t = threadIdx.x;
    int chunk = (n + SCAN_T - 1) / SCAN_T;
    int beg = t * chunk, end = min(beg + chunk, n);
    int s = 0;
    for (int i = beg; i < end; i++) s += g_cnt[i];
    ssum[t] = s;
    __syncthreads();
    for (int o = 1; o < SCAN_T; o <<= 1) {
        int v = (t >= o) ? ssum[t - o] : 0;
        __syncthreads();
        ssum[t] += v;
        __syncthreads();
    }
    int run = (t == 0) ? 0 : ssum[t - 1];
    for (int i = beg; i < end; i++) {
        g_off[i] = run; g_cur[i] = run;
        run += g_cnt[i];
    }
}

__global__ void __launch_bounds__(256) place_kernel(const int* __restrict__ kq, int M) {
    int i = blockIdx.x * blockDim.x + threadIdx.x;
    if (i < M) {
        int q = __ldg(&kq[M + i]);
        int pos = atomicAdd(&g_cur[q], 1);
        g_sorted[pos] = __ldg(&kq[i]);
    }
}

// ---------------- segment gather: warp per query, batched, no atomics ------
__global__ void __launch_bounds__(256) gather_kernel(int n) {
    int gw = (blockIdx.x * blockDim.x + threadIdx.x) >> 5;
    if (gw >= n) return;
    int lane = threadIdx.x & 31;
    int c4 = lane * 4;
    int beg = __ldg(&g_off[gw]);
    int cnt = __ldg(&g_cnt[gw]);
    float4 qv = __ldcs((const float4*)&g_q[(size_t)gw * CH + c4]);  // once-read
    float4 acc = make_float4(0.f, 0.f, 0.f, 0.f);

    int i = 0;
#pragma unroll 2
    for (; i + 4 <= cnt; i += 4) {
        int key[4], kern[4];
#pragma unroll
        for (int j = 0; j < 4; j++) {
            int e = __ldg(&g_sorted[beg + i + j]);
            key[j]  = e / KVOL;
            kern[j] = e - key[j] * KVOL;
        }
        float4 v[4];
#pragma unroll
        for (int j = 0; j < 4; j++)
            v[j] = __ldg((const float4*)&g_v[(size_t)key[j] * CH + c4]);
        float s[4];
#pragma unroll
        for (int j = 0; j < 4; j++) {
            float4 p = __ldg((const float4*)&g_npe[kern[j] * CH + c4]);
            float t = qv.x * p.x + qv.y * p.y + qv.z * p.z + qv.w * p.w;
            t += __shfl_xor_sync(0xFFFFFFFFu, t, 1);
            t += __shfl_xor_sync(0xFFFFFFFFu, t, 2);
            s[j] = t;
        }
#pragma unroll
        for (int j = 0; j < 4; j++) {
            acc.x = fmaf(s[j], v[j].x, acc.x);
            acc.y = fmaf(s[j], v[j].y, acc.y);
            acc.z = fmaf(s[j], v[j].z, acc.z);
            acc.w = fmaf(s[j], v[j].w, acc.w);
        }
    }
    for (; i < cnt; i++) {
        int e = __ldg(&g_sorted[beg + i]);
        int key = e / KVOL;
        int kern = e - key * KVOL;
        float4 v = __ldg((const float4*)&g_v[(size_t)key * CH + c4]);
        float4 p = __ldg((const float4*)&g_npe[kern * CH + c4]);
        float t = qv.x * p.x + qv.y * p.y + qv.z * p.z + qv.w * p.w;
        t += __shfl_xor_sync(0xFFFFFFFFu, t, 1);
        t += __shfl_xor_sync(0xFFFFFFFFu, t, 2);
        acc.x = fmaf(t, v.x, acc.x);
        acc.y = fmaf(t, v.y, acc.y);
        acc.z = fmaf(t, v.z, acc.z);
        acc.w = fmaf(t, v.w, acc.w);
    }
    __stcs((float4*)&g_acc[(size_t)gw * CH + c4], acc);  // once-written
}

// ---------------- host launch ----------------------------------------------
extern "C" void kernel_launch(void* const* d_in, const int* in_sizes, int n_in,
                              void* d_out, int out_size) {
    const float* feats   = (const float*)d_in[0];
    const float* points  = (const float*)d_in[1];
    const int*   kq      = (const int*)d_in[2];
    const float* W1 = (const float*)d_in[3];
    const float* g1 = (const float*)d_in[4];
    const float* b1 = (const float*)d_in[5];
    const float* W2 = (const float*)d_in[6];
    const float* g2 = (const float*)d_in[7];
    const float* b2 = (const float*)d_in[8];
    const float* W3 = (const float*)d_in[9];
    const float* b3 = (const float*)d_in[10];
    const float* Wq = (const float*)d_in[11];
    const float* bq = (const float*)d_in[12];
    const float* Wv = (const float*)d_in[13];
    const float* bv = (const float*)d_in[14];
    const float* pos_enc = (const float*)d_in[15];
    const float* Wo = (const float*)d_in[16];
    const float* bo = (const float*)d_in[17];

    int N = in_sizes[0] / CH;
    int M = in_sizes[2] / 2;

    cudaFuncSetAttribute((const void*)gemm_p<0>,
                         cudaFuncAttributeMaxDynamicSharedMemorySize, TC_SMEM);
    cudaFuncSetAttribute((const void*)gemm_p<1>,
                         cudaFuncAttributeMaxDynamicSharedMemorySize, TC_SMEM);
    cudaFuncSetAttribute((const void*)gemm_p<2>,
                         cudaFuncAttributeMaxDynamicSharedMemorySize, TC_SMEM);

    float* xp; float* qp; float* vp; float* ap;
    __nv_bfloat16* whi; __nv_bfloat16* wlo;
    { void* t; cudaGetSymbolAddress(&t, g_x);   xp  = (float*)t; }
    { void* t; cudaGetSymbolAddress(&t, g_q);   qp  = (float*)t; }
    { void* t; cudaGetSymbolAddress(&t, g_v);   vp  = (float*)t; }
    { void* t; cudaGetSymbolAddress(&t, g_acc); ap  = (float*)t; }
    { void* t; cudaGetSymbolAddress(&t, g_Whi); whi = (__nv_bfloat16*)t; }
    { void* t; cudaGetSymbolAddress(&t, g_Wlo); wlo = (__nv_bfloat16*)t; }
    void* cntp = nullptr;
    cudaGetSymbolAddress(&cntp, g_cnt);
    cudaMemsetAsync(cntp, 0, (size_t)N * sizeof(int), 0);

    init_kernel<<<1, 256>>>(pos_enc);
    stats1_kernel<<<256, 256>>>(points, W1, N, W3, Wq, Wv, Wo, kq, M);
    h2_kernel<<<(N + H2_PB - 1) / H2_PB, 256>>>(points, W1, g1, b1, W2, N);
    scan_kernel<<<1, SCAN_T>>>(N);
    place_kernel<<<(M + 255) / 256, 256>>>(kq, M);

    // x = relu(bn2(h2(points))) @ W3 + b3 + feats   (h2 recomputed in-kernel)
    gemm_p<1><<<GEMM_GRID, 256, TC_SMEM>>>(nullptr, whi + 0 * CH * CH, wlo + 0 * CH * CH,
                                           b3, xp, feats, g2, b2, points, W1, W2, N);
    // q = l2norm16(x @ Wq + bq)
    gemm_p<2><<<GEMM_GRID, 256, TC_SMEM>>>(xp, whi + 1 * CH * CH, wlo + 1 * CH * CH,
                                           bq, qp, nullptr, nullptr, nullptr,
                                           nullptr, nullptr, nullptr, N);
    // v = x @ Wv + bv
    gemm_p<0><<<GEMM_GRID, 256, TC_SMEM>>>(xp, whi + 2 * CH * CH, wlo + 2 * CH * CH,
                                           bv, vp, nullptr, nullptr, nullptr,
                                           nullptr, nullptr, nullptr, N);

    // attention: segment gather, no atomics
    gather_kernel<<<(N + 7) / 8, 256>>>(N);

    // out = acc @ Wo + bo
    gemm_p<0><<<GEMM_GRID, 256, TC_SMEM>>>(ap, whi + 3 * CH * CH, wlo + 3 * CH * CH,
                                           bo, (float*)d_out, nullptr, nullptr, nullptr,
                                           nullptr, nullptr, nullptr, N);
}

// round 8
// speedup vs baseline: 2.0922x; 1.4800x over previous
#include <cuda_runtime.h>
#include <cuda_bf16.h>
#include <math.h>

#define N_MAX 100000
#define M_MAX 1600000
#define CH 128
#define KVOL 27
#define BN_EPS 1e-5f

// ---------------- scratch (device globals; no runtime allocation) ----------
__device__ float g_x  [(size_t)N_MAX * CH];
__device__ float g_q  [(size_t)N_MAX * CH];
__device__ float g_v  [(size_t)N_MAX * CH];
__device__ float g_acc[(size_t)N_MAX * CH];
__device__ float g_npe[KVOL * CH];
__device__ float g_s1[8];
__device__ float g_s2[2 * CH];
__device__ float g_bn1[6];       // sc0..2, shf0..2
__device__ int   g_cnt[N_MAX];
__device__ int   g_off[N_MAX];
__device__ int   g_cur[N_MAX];
__device__ int   g_sorted[M_MAX];
__device__ int   g_bsum[128];
__device__ int   g_bbase[128];
// weight panels, transposed to [n][k] K-major, bf16 split hi/lo
// index: 0=W3, 1=Wq, 2=Wv, 3=Wo
__device__ __nv_bfloat16 g_Whi[4][CH * CH];
__device__ __nv_bfloat16 g_Wlo[4][CH * CH];

// ---------------- init: zero stats + normalize pos_enc ---------------------
__global__ void init_kernel(const float* __restrict__ pos_enc) {
    int tid = threadIdx.x;
    if (tid < 8)  g_s1[tid] = 0.f;
    if (tid < 256) g_s2[tid] = 0.f;
    if (tid < KVOL * 8) {
        const float* src = pos_enc + tid * 16;
        float v[16]; float s = 0.f;
#pragma unroll
        for (int i = 0; i < 16; i++) { v[i] = src[i]; s += v[i] * v[i]; }
        float inv = 1.f / fmaxf(sqrtf(s), 1e-12f);
#pragma unroll
        for (int i = 0; i < 16; i++) g_npe[tid * 16 + i] = v[i] * inv;
    }
}

// ---------------- stats for BN1 + weight prep + q-histogram (fused) --------
// grid MUST be 256 blocks x 256 threads (65536 = 4 * 128 * 128)
__global__ void __launch_bounds__(256) stats1_kernel(
        const float* __restrict__ points, const float* __restrict__ W1, int n,
        const float* __restrict__ W3, const float* __restrict__ Wq,
        const float* __restrict__ Wv, const float* __restrict__ Wo,
        const int* __restrict__ kq, int M) {
    int gid = blockIdx.x * 256 + threadIdx.x;      // 0..65535
    {
        int w = gid >> 14;
        int e = gid & 16383;
        int k = e >> 7, nn = e & 127;
        const float* Wsrc = (w == 0) ? W3 : (w == 1) ? Wq : (w == 2) ? Wv : Wo;
        float x = __ldg(&Wsrc[k * CH + nn]);
        __nv_bfloat16 hi = __float2bfloat16(x);
        __nv_bfloat16 lo = __float2bfloat16(x - __bfloat162float(hi));
        g_Whi[w][nn * CH + k] = hi;
        g_Wlo[w][nn * CH + k] = lo;
    }
    // fused histogram of q_idx
    for (int i = gid; i < M; i += 65536)
        atomicAdd(&g_cnt[__ldg(&kq[M + i])], 1);

    __shared__ float sh[6];
    if (threadIdx.x < 6) sh[threadIdx.x] = 0.f;
    __syncthreads();
    float w[9];
#pragma unroll
    for (int i = 0; i < 9; i++) w[i] = __ldg(&W1[i]);
    float s[3] = {0.f, 0.f, 0.f}, q[3] = {0.f, 0.f, 0.f};
    for (int i = gid; i < n; i += 65536) {
        float px = points[i * 3 + 0], py = points[i * 3 + 1], pz = points[i * 3 + 2];
#pragma unroll
        for (int j = 0; j < 3; j++) {
            float h = px * w[j] + py * w[3 + j] + pz * w[6 + j];
            s[j] += h; q[j] += h * h;
        }
    }
#pragma unroll
    for (int o = 16; o; o >>= 1) {
#pragma unroll
        for (int j = 0; j < 3; j++) {
            s[j] += __shfl_down_sync(0xFFFFFFFFu, s[j], o);
            q[j] += __shfl_down_sync(0xFFFFFFFFu, q[j], o);
        }
    }
    if ((threadIdx.x & 31) == 0) {
#pragma unroll
        for (int j = 0; j < 3; j++) {
            atomicAdd(&sh[j], s[j]);
            atomicAdd(&sh[3 + j], q[j]);
        }
    }
    __syncthreads();
    if (threadIdx.x < 6) atomicAdd(&g_s1[threadIdx.x], sh[threadIdx.x]);
}

// ---------------- BN2 stats only (h2 recomputed in gemm, never stored) -----
#define H2_PB 128
__global__ void __launch_bounds__(256) h2_kernel(
        const float* __restrict__ points, const float* __restrict__ W1,
        const float* __restrict__ g1, const float* __restrict__ b1,
        const float* __restrict__ W2, int n) {
    __shared__ float ssum[CH], ssq[CH];
    int tid = threadIdx.x;
    if (tid < CH) { ssum[tid] = 0.f; ssq[tid] = 0.f; }
    __syncthreads();

    float w1[9];
#pragma unroll
    for (int i = 0; i < 9; i++) w1[i] = __ldg(&W1[i]);
    float invn = 1.f / (float)n;
    float sc[3], shf[3];
#pragma unroll
    for (int j = 0; j < 3; j++) {
        float mu  = g_s1[j] * invn;
        float var = g_s1[3 + j] * invn - mu * mu;
        float rs  = rsqrtf(var + BN_EPS);
        float s   = rs * __ldg(&g1[j]);
        sc[j] = s; shf[j] = __ldg(&b1[j]) - mu * s;
    }
    if (blockIdx.x == 0 && tid < 3) {
        g_bn1[tid] = sc[tid];
        g_bn1[3 + tid] = shf[tid];
    }
    int lane = tid & 31, wid = tid >> 5;
    int c0 = lane * 4;
    float w2a[4], w2b[4], w2c[4];
#pragma unroll
    for (int i = 0; i < 4; i++) {
        w2a[i] = __ldg(&W2[0 * CH + c0 + i]);
        w2b[i] = __ldg(&W2[1 * CH + c0 + i]);
        w2c[i] = __ldg(&W2[2 * CH + c0 + i]);
    }
    float ls[4] = {0, 0, 0, 0}, lq[4] = {0, 0, 0, 0};
    int base = blockIdx.x * H2_PB;
    int nend = min(base + H2_PB, n);
    for (int p = base + wid; p < nend; p += 8) {
        float px = __ldg(&points[p * 3 + 0]);
        float py = __ldg(&points[p * 3 + 1]);
        float pz = __ldg(&points[p * 3 + 2]);
        float a[3];
#pragma unroll
        for (int j = 0; j < 3; j++) {
            float h = px * w1[j] + py * w1[3 + j] + pz * w1[6 + j];
            a[j] = fmaxf(h * sc[j] + shf[j], 0.f);
        }
#pragma unroll
        for (int i = 0; i < 4; i++) {
            float o = a[0] * w2a[i] + a[1] * w2b[i] + a[2] * w2c[i];
            ls[i] += o; lq[i] += o * o;
        }
    }
#pragma unroll
    for (int i = 0; i < 4; i++) {
        atomicAdd(&ssum[c0 + i], ls[i]);
        atomicAdd(&ssq[c0 + i], lq[i]);
    }
    __syncthreads();
    if (tid < CH) {
        atomicAdd(&g_s2[tid], ssum[tid]);
        atomicAdd(&g_s2[CH + tid], ssq[tid]);
    }
}

// ---------------- persistent tensor-core GEMM (bf16 split, LDSM) -----------
// B panels staged ONCE per CTA; BM=32 tiles looped with double-buffered A.
// MODE 0: C = A@W + bias
// MODE 1: A' = relu(bn2(relu(bn1(points@W1))@W2)); C = A'@W + bias + extra
// MODE 2: C = l2norm_per16(A@W + bias)
#define SASTRIDE 136
#define BM 32
#define SB_ELEMS (128 * SASTRIDE)
#define ABUF_ELEMS (BM * SASTRIDE)          // per hi/lo buffer
#define TC_SMEM ((2 * SB_ELEMS + 4 * ABUF_ELEMS) * 2 + 256 * 4)
#define GEMM_GRID 296

#define LDSM4(R0, R1, R2, R3, ADDR) \
    asm volatile("ldmatrix.sync.aligned.m8n8.x4.shared.b16 {%0,%1,%2,%3}, [%4];" \
        : "=r"(R0), "=r"(R1), "=r"(R2), "=r"(R3) : "r"(ADDR))

__device__ __forceinline__ void mma16816(float* c, const unsigned* a, const unsigned* b) {
    asm volatile(
        "mma.sync.aligned.m16n8k16.row.col.f32.bf16.bf16.f32 "
        "{%0,%1,%2,%3}, {%4,%5,%6,%7}, {%8,%9}, {%0,%1,%2,%3};"
        : "+f"(c[0]), "+f"(c[1]), "+f"(c[2]), "+f"(c[3])
        : "r"(a[0]), "r"(a[1]), "r"(a[2]), "r"(a[3]), "r"(b[0]), "r"(b[1]));
}

template <int MODE>
__global__ void __launch_bounds__(256, 2) gemm_p(
        const float* __restrict__ A, const __nv_bfloat16* __restrict__ Bhi,
        const __nv_bfloat16* __restrict__ Blo, const float* __restrict__ bias,
        float* __restrict__ C, const float* __restrict__ extra,
        const float* __restrict__ gamma, const float* __restrict__ beta,
        const float* __restrict__ points, const float* __restrict__ W1,
        const float* __restrict__ W2, int nrows) {
    extern __shared__ char smraw[];
    __nv_bfloat16* sBhi = (__nv_bfloat16*)smraw;
    __nv_bfloat16* sBlo = sBhi + SB_ELEMS;
    __nv_bfloat16* sA   = sBlo + SB_ELEMS;      // [buf][hi|lo]
    float* s_sc = (float*)(sA + 4 * ABUF_ELEMS);
    float* s_sh = s_sc + CH;

    int tid = threadIdx.x;

    // ---- stage B panels once ----
#pragma unroll
    for (int i = 0; i < 8; i++) {
        int g = i * 256 + tid;           // uint4 index, 2048 total
        int nn = g >> 4;
        int kk = (g & 15) * 8;
        *(uint4*)&sBhi[nn * SASTRIDE + kk] = __ldg((const uint4*)&Bhi[nn * CH + kk]);
        *(uint4*)&sBlo[nn * SASTRIDE + kk] = __ldg((const uint4*)&Blo[nn * CH + kk]);
    }
    if (MODE == 1 && tid < CH) {
        float invn = 1.f / (float)nrows;
        float mu  = g_s2[tid] * invn;
        float var = g_s2[CH + tid] * invn - mu * mu;
        float rs  = rsqrtf(var + BN_EPS);
        float s   = rs * __ldg(&gamma[tid]);
        s_sc[tid] = s; s_sh[tid] = __ldg(&beta[tid]) - mu * s;
    }
    __syncthreads();

    // ---- per-thread loop-invariant constants ----
    int rbase = tid >> 5;                // 0..7: handles rows rbase, +8, +16, +24
    int c = (tid & 31) * 4;              // fixed 4-col group
    float w1[9], sc1[3], sh1[3];
    float4 w20, w21, w22, sc4, sh4;
    if (MODE == 1) {
#pragma unroll
        for (int i = 0; i < 9; i++) w1[i] = __ldg(&W1[i]);
#pragma unroll
        for (int j = 0; j < 3; j++) { sc1[j] = g_bn1[j]; sh1[j] = g_bn1[3 + j]; }
        w20 = __ldg((const float4*)&W2[0 * CH + c]);
        w21 = __ldg((const float4*)&W2[1 * CH + c]);
        w22 = __ldg((const float4*)&W2[2 * CH + c]);
        sc4 = *(const float4*)&s_sc[c];
        sh4 = *(const float4*)&s_sh[c];
    }

    // warp tiling: 8 warps = 2(m) x 4(n); warp tile 16x32
    int wid = tid >> 5, lane = tid & 31;
    int warp_m = (wid & 1) * 16;
    int warp_n = (wid >> 1) * 32;
    int rq = lane >> 2;
    int kq = (lane & 3) * 2;

    unsigned uA   = (unsigned)__cvta_generic_to_shared(sA);
    unsigned uBhi = (unsigned)__cvta_generic_to_shared(sBhi);
    unsigned uBlo = (unsigned)__cvta_generic_to_shared(sBlo);
    int arow = warp_m + (lane & 15);
    int acol = (lane >> 4) * 8;
    unsigned aOff = (unsigned)((arow * SASTRIDE + acol) * 2);
    int brow = warp_n + (lane & 7) + ((lane >> 4) & 1) * 8;
    int bcol = ((lane >> 3) & 1) * 8;
    unsigned bHi = uBhi + (unsigned)((brow * SASTRIDE + bcol) * 2);
    unsigned bLo = uBlo + (unsigned)((brow * SASTRIDE + bcol) * 2);
    const unsigned BROW16 = 16 * SASTRIDE * 2;
    const unsigned ABUF_B = 2 * ABUF_ELEMS * 2;   // bytes per buffer (hi+lo)
    const unsigned ALO_B  = ABUF_ELEMS * 2;

    int ntiles = (nrows + BM - 1) / BM;
    int t = blockIdx.x;

    // ---- prefetch A values for first tile ----
    float4 pref[4];
#define LOAD_PREF(TT)                                                         \
    {                                                                         \
        _Pragma("unroll")                                                     \
        for (int i = 0; i < 4; i++) {                                         \
            int row = (TT) * BM + i * 8 + rbase;                              \
            float4 a = make_float4(0.f, 0.f, 0.f, 0.f);                       \
            if (row < nrows) {                                                \
                if (MODE == 1) {                                              \
                    float px = __ldg(&points[row * 3 + 0]);                   \
                    float py = __ldg(&points[row * 3 + 1]);                   \
                    float pz = __ldg(&points[row * 3 + 2]);                   \
                    float t0 = fmaxf(fmaf(px * w1[0] + py * w1[3] + pz * w1[6], sc1[0], sh1[0]), 0.f); \
                    float t1 = fmaxf(fmaf(px * w1[1] + py * w1[4] + pz * w1[7], sc1[1], sh1[1]), 0.f); \
                    float t2 = fmaxf(fmaf(px * w1[2] + py * w1[5] + pz * w1[8], sc1[2], sh1[2]), 0.f); \
                    a.x = fmaxf(fmaf(t0 * w20.x + t1 * w21.x + t2 * w22.x, sc4.x, sh4.x), 0.f); \
                    a.y = fmaxf(fmaf(t0 * w20.y + t1 * w21.y + t2 * w22.y, sc4.y, sh4.y), 0.f); \
                    a.z = fmaxf(fmaf(t0 * w20.z + t1 * w21.z + t2 * w22.z, sc4.z, sh4.z), 0.f); \
                    a.w = fmaxf(fmaf(t0 * w20.w + t1 * w21.w + t2 * w22.w, sc4.w, sh4.w), 0.f); \
                } else {                                                      \
                    a = __ldg((const float4*)&A[(size_t)row * CH + c]);       \
                }                                                             \
            }                                                                 \
            pref[i] = a;                                                      \
        }                                                                     \
    }
    if (t < ntiles) LOAD_PREF(t);

    int it = 0;
    while (t < ntiles) {
        int buf = it & 1;
        __nv_bfloat16* sAhi = sA + buf * 2 * ABUF_ELEMS;
        __nv_bfloat16* sAlo = sAhi + ABUF_ELEMS;
        // ---- store prefetched A tile (convert + split) ----
#pragma unroll
        for (int i = 0; i < 4; i++) {
            int r = i * 8 + rbase;
            float4 a = pref[i];
            __nv_bfloat162 h0 = __floats2bfloat162_rn(a.x, a.y);
            __nv_bfloat162 h1 = __floats2bfloat162_rn(a.z, a.w);
            float2 h0f = __bfloat1622float2(h0);
            float2 h1f = __bfloat1622float2(h1);
            __nv_bfloat162 l0 = __floats2bfloat162_rn(a.x - h0f.x, a.y - h0f.y);
            __nv_bfloat162 l1 = __floats2bfloat162_rn(a.z - h1f.x, a.w - h1f.y);
            *(__nv_bfloat162*)&sAhi[r * SASTRIDE + c]     = h0;
            *(__nv_bfloat162*)&sAhi[r * SASTRIDE + c + 2] = h1;
            *(__nv_bfloat162*)&sAlo[r * SASTRIDE + c]     = l0;
            *(__nv_bfloat162*)&sAlo[r * SASTRIDE + c + 2] = l1;
        }
        __syncthreads();

        int row_lo = t * BM + warp_m + rq;
        int row_hi = row_lo + 8;
        bool ok_lo = row_lo < nrows, ok_hi = row_hi < nrows;

        // ---- prefetch epilogue 'extra' for current tile (overlaps MMA) ----
        float2 ext[8];
        if (MODE == 1) {
#pragma unroll
            for (int nt = 0; nt < 4; nt++) {
                int col = warp_n + nt * 8 + kq;
                ext[nt]     = ok_lo ? __ldg((const float2*)&extra[(size_t)row_lo * CH + col])
                                    : make_float2(0.f, 0.f);
                ext[4 + nt] = ok_hi ? __ldg((const float2*)&extra[(size_t)row_hi * CH + col])
                                    : make_float2(0.f, 0.f);
            }
        }
        // ---- prefetch A for next tile (overlaps MMA) ----
        int tn = t + GEMM_GRID;
        if (tn < ntiles) LOAD_PREF(tn);

        // ---- MMA ----
        unsigned aHi = uA + buf * ABUF_B + aOff;
        unsigned aLo = aHi + ALO_B;
        float acc[4][4];
#pragma unroll
        for (int nt = 0; nt < 4; nt++)
#pragma unroll
            for (int j = 0; j < 4; j++) acc[nt][j] = 0.f;
#pragma unroll
        for (int ks = 0; ks < 8; ks++) {
            unsigned ko = ks * 32;
            unsigned ah[4], al[4];
            LDSM4(ah[0], ah[1], ah[2], ah[3], aHi + ko);
            LDSM4(al[0], al[1], al[2], al[3], aLo + ko);
            unsigned bh[8], bl[8];
            LDSM4(bh[0], bh[1], bh[2], bh[3], bHi + ko);
            LDSM4(bh[4], bh[5], bh[6], bh[7], bHi + BROW16 + ko);
            LDSM4(bl[0], bl[1], bl[2], bl[3], bLo + ko);
            LDSM4(bl[4], bl[5], bl[6], bl[7], bLo + BROW16 + ko);
#pragma unroll
            for (int nt = 0; nt < 4; nt++) {
                mma16816(acc[nt], ah, bh + 2 * nt);
                mma16816(acc[nt], ah, bl + 2 * nt);
                mma16816(acc[nt], al, bh + 2 * nt);
            }
        }

        // ---- epilogue ----
#pragma unroll
        for (int nt = 0; nt < 4; nt++) {
            int col = warp_n + nt * 8 + kq;
            float2 bs = *(const float2*)&bias[col];
            acc[nt][0] += bs.x; acc[nt][1] += bs.y;
            acc[nt][2] += bs.x; acc[nt][3] += bs.y;
            if (MODE == 1) {
                acc[nt][0] += ext[nt].x;     acc[nt][1] += ext[nt].y;
                acc[nt][2] += ext[4 + nt].x; acc[nt][3] += ext[4 + nt].y;
            }
        }
        if (MODE == 2) {
#pragma unroll
            for (int hp = 0; hp < 2; hp++) {
                int n0 = hp * 2, n1 = n0 + 1;
                float s0 = acc[n0][0] * acc[n0][0] + acc[n0][1] * acc[n0][1]
                         + acc[n1][0] * acc[n1][0] + acc[n1][1] * acc[n1][1];
                float s1 = acc[n0][2] * acc[n0][2] + acc[n0][3] * acc[n0][3]
                         + acc[n1][2] * acc[n1][2] + acc[n1][3] * acc[n1][3];
                s0 += __shfl_xor_sync(0xFFFFFFFFu, s0, 1);
                s0 += __shfl_xor_sync(0xFFFFFFFFu, s0, 2);
                s1 += __shfl_xor_sync(0xFFFFFFFFu, s1, 1);
                s1 += __shfl_xor_sync(0xFFFFFFFFu, s1, 2);
                float i0 = 1.f / fmaxf(sqrtf(s0), 1e-12f);
                float i1 = 1.f / fmaxf(sqrtf(s1), 1e-12f);
                acc[n0][0] *= i0; acc[n0][1] *= i0;
                acc[n1][0] *= i0; acc[n1][1] *= i0;
                acc[n0][2] *= i1; acc[n0][3] *= i1;
                acc[n1][2] *= i1; acc[n1][3] *= i1;
            }
        }
#pragma unroll
        for (int nt = 0; nt < 4; nt++) {
            int col = warp_n + nt * 8 + kq;
            if (ok_lo)
                *(float2*)&C[(size_t)row_lo * CH + col] =
                    make_float2(acc[nt][0], acc[nt][1]);
            if (ok_hi)
                *(float2*)&C[(size_t)row_hi * CH + col] =
                    make_float2(acc[nt][2], acc[nt][3]);
        }
        t = tn; ++it;
    }
#undef LOAD_PREF
}

// ---------------- multi-block exclusive scan of g_cnt -----------------------
#define SC_CHUNK 1024
__global__ void __launch_bounds__(SC_CHUNK) scan1_kernel(int n) {
    __shared__ int sm[SC_CHUNK];
    int t = threadIdx.x;
    int i = blockIdx.x * SC_CHUNK + t;
    int v = (i < n) ? g_cnt[i] : 0;
    sm[t] = v;
    __syncthreads();
#pragma unroll
    for (int o = 1; o < SC_CHUNK; o <<= 1) {
        int x = (t >= o) ? sm[t - o] : 0;
        __syncthreads();
        sm[t] += x;
        __syncthreads();
    }
    if (i < n) g_off[i] = sm[t] - v;              // local exclusive
    if (t == SC_CHUNK - 1) g_bsum[blockIdx.x] = sm[t];
}

__global__ void __launch_bounds__(128) scan2_kernel(int nb) {
    __shared__ int sm[128];
    int t = threadIdx.x;
    int v = (t < nb) ? g_bsum[t] : 0;
    sm[t] = v;
    __syncthreads();
#pragma unroll
    for (int o = 1; o < 128; o <<= 1) {
        int x = (t >= o) ? sm[t - o] : 0;
        __syncthreads();
        sm[t] += x;
        __syncthreads();
    }
    if (t < nb) g_bbase[t] = sm[t] - v;           // exclusive block base
}

__global__ void __launch_bounds__(SC_CHUNK) scan3_kernel(int n) {
    int i = blockIdx.x * SC_CHUNK + threadIdx.x;
    if (i < n) {
        int o = g_off[i] + g_bbase[blockIdx.x];
        g_off[i] = o;
        g_cur[i] = o;
    }
}

__global__ void __launch_bounds__(256) place_kernel(const int* __restrict__ kq, int M) {
    int i = blockIdx.x * blockDim.x + threadIdx.x;
    if (i < M) {
        int q = __ldg(&kq[M + i]);
        int pos = atomicAdd(&g_cur[q], 1);
        g_sorted[pos] = __ldg(&kq[i]);
    }
}

// ---------------- segment gather: warp per query, batched, no atomics ------
__global__ void __launch_bounds__(256) gather_kernel(int n) {
    int gw = (blockIdx.x * blockDim.x + threadIdx.x) >> 5;
    if (gw >= n) return;
    int lane = threadIdx.x & 31;
    int c4 = lane * 4;
    int beg = __ldg(&g_off[gw]);
    int cnt = __ldg(&g_cnt[gw]);
    float4 qv = __ldcs((const float4*)&g_q[(size_t)gw * CH + c4]);  // once-read
    float4 acc = make_float4(0.f, 0.f, 0.f, 0.f);

    int i = 0;
#pragma unroll 2
    for (; i + 4 <= cnt; i += 4) {
        int key[4], kern[4];
#pragma unroll
        for (int j = 0; j < 4; j++) {
            int e = __ldg(&g_sorted[beg + i + j]);
            key[j]  = e / KVOL;
            kern[j] = e - key[j] * KVOL;
        }
        float4 v[4];
#pragma unroll
        for (int j = 0; j < 4; j++)
            v[j] = __ldg((const float4*)&g_v[(size_t)key[j] * CH + c4]);
        float s[4];
#pragma unroll
        for (int j = 0; j < 4; j++) {
            float4 p = __ldg((const float4*)&g_npe[kern[j] * CH + c4]);
            float t = qv.x * p.x + qv.y * p.y + qv.z * p.z + qv.w * p.w;
            t += __shfl_xor_sync(0xFFFFFFFFu, t, 1);
            t += __shfl_xor_sync(0xFFFFFFFFu, t, 2);
            s[j] = t;
        }
#pragma unroll
        for (int j = 0; j < 4; j++) {
            acc.x = fmaf(s[j], v[j].x, acc.x);
            acc.y = fmaf(s[j], v[j].y, acc.y);
            acc.z = fmaf(s[j], v[j].z, acc.z);
            acc.w = fmaf(s[j], v[j].w, acc.w);
        }
    }
    for (; i < cnt; i++) {
        int e = __ldg(&g_sorted[beg + i]);
        int key = e / KVOL;
        int kern = e - key * KVOL;
        float4 v = __ldg((const float4*)&g_v[(size_t)key * CH + c4]);
        float4 p = __ldg((const float4*)&g_npe[kern * CH + c4]);
        float t = qv.x * p.x + qv.y * p.y + qv.z * p.z + qv.w * p.w;
        t += __shfl_xor_sync(0xFFFFFFFFu, t, 1);
        t += __shfl_xor_sync(0xFFFFFFFFu, t, 2);
        acc.x = fmaf(t, v.x, acc.x);
        acc.y = fmaf(t, v.y, acc.y);
        acc.z = fmaf(t, v.z, acc.z);
        acc.w = fmaf(t, v.w, acc.w);
    }
    __stcs((float4*)&g_acc[(size_t)gw * CH + c4], acc);  // once-written
}

// ---------------- host launch ----------------------------------------------
extern "C" void kernel_launch(void* const* d_in, const int* in_sizes, int n_in,
                              void* d_out, int out_size) {
    const float* feats   = (const float*)d_in[0];
    const float* points  = (const float*)d_in[1];
    const int*   kq      = (const int*)d_in[2];
    const float* W1 = (const float*)d_in[3];
    const float* g1 = (const float*)d_in[4];
    const float* b1 = (const float*)d_in[5];
    const float* W2 = (const float*)d_in[6];
    const float* g2 = (const float*)d_in[7];
    const float* b2 = (const float*)d_in[8];
    const float* W3 = (const float*)d_in[9];
    const float* b3 = (const float*)d_in[10];
    const float* Wq = (const float*)d_in[11];
    const float* bq = (const float*)d_in[12];
    const float* Wv = (const float*)d_in[13];
    const float* bv = (const float*)d_in[14];
    const float* pos_enc = (const float*)d_in[15];
    const float* Wo = (const float*)d_in[16];
    const float* bo = (const float*)d_in[17];

    int N = in_sizes[0] / CH;
    int M = in_sizes[2] / 2;

    cudaFuncSetAttribute((const void*)gemm_p<0>,
                         cudaFuncAttributeMaxDynamicSharedMemorySize, TC_SMEM);
    cudaFuncSetAttribute((const void*)gemm_p<1>,
                         cudaFuncAttributeMaxDynamicSharedMemorySize, TC_SMEM);
    cudaFuncSetAttribute((const void*)gemm_p<2>,
                         cudaFuncAttributeMaxDynamicSharedMemorySize, TC_SMEM);

    float* xp; float* qp; float* vp; float* ap;
    __nv_bfloat16* whi; __nv_bfloat16* wlo;
    { void* t; cudaGetSymbolAddress(&t, g_x);   xp  = (float*)t; }
    { void* t; cudaGetSymbolAddress(&t, g_q);   qp  = (float*)t; }
    { void* t; cudaGetSymbolAddress(&t, g_v);   vp  = (float*)t; }
    { void* t; cudaGetSymbolAddress(&t, g_acc); ap  = (float*)t; }
    { void* t; cudaGetSymbolAddress(&t, g_Whi); whi = (__nv_bfloat16*)t; }
    { void* t; cudaGetSymbolAddress(&t, g_Wlo); wlo = (__nv_bfloat16*)t; }
    void* cntp = nullptr;
    cudaGetSymbolAddress(&cntp, g_cnt);
    cudaMemsetAsync(cntp, 0, (size_t)N * sizeof(int), 0);

    int nsb = (N + SC_CHUNK - 1) / SC_CHUNK;      // scan blocks (<=128)

    init_kernel<<<1, 256>>>(pos_enc);
    stats1_kernel<<<256, 256>>>(points, W1, N, W3, Wq, Wv, Wo, kq, M);
    h2_kernel<<<(N + H2_PB - 1) / H2_PB, 256>>>(points, W1, g1, b1, W2, N);
    scan1_kernel<<<nsb, SC_CHUNK>>>(N);
    scan2_kernel<<<1, 128>>>(nsb);
    scan3_kernel<<<nsb, SC_CHUNK>>>(N);
    place_kernel<<<(M + 255) / 256, 256>>>(kq, M);

    // x = relu(bn2(h2(points))) @ W3 + b3 + feats   (h2 recomputed in-kernel)
    gemm_p<1><<<GEMM_GRID, 256, TC_SMEM>>>(nullptr, whi + 0 * CH * CH, wlo + 0 * CH * CH,
                                           b3, xp, feats, g2, b2, points, W1, W2, N);
    // q = l2norm16(x @ Wq + bq)
    gemm_p<2><<<GEMM_GRID, 256, TC_SMEM>>>(xp, whi + 1 * CH * CH, wlo + 1 * CH * CH,
                                           bq, qp, nullptr, nullptr, nullptr,
                                           nullptr, nullptr, nullptr, N);
    // v = x @ Wv + bv
    gemm_p<0><<<GEMM_GRID, 256, TC_SMEM>>>(xp, whi + 2 * CH * CH, wlo + 2 * CH * CH,
                                           bv, vp, nullptr, nullptr, nullptr,
                                           nullptr, nullptr, nullptr, N);

    // attention: segment gather, no atomics
    gather_kernel<<<(N + 7) / 8, 256>>>(N);

    // out = acc @ Wo + bo
    gemm_p<0><<<GEMM_GRID, 256, TC_SMEM>>>(ap, whi + 3 * CH * CH, wlo + 3 * CH * CH,
                                           bo, (float*)d_out, nullptr, nullptr, nullptr,
                                           nullptr, nullptr, nullptr, N);
}

// round 9
// speedup vs baseline: 2.1447x; 1.0251x over previous
#include <cuda_runtime.h>
#include <cuda_bf16.h>
#include <math.h>

#define N_MAX 100000
#define M_MAX 1600000
#define CH 128
#define KVOL 27
#define BN_EPS 1e-5f

// ---------------- scratch (device globals; no runtime allocation) ----------
__device__ float g_x  [(size_t)N_MAX * CH];
__device__ float g_q  [(size_t)N_MAX * CH];
__device__ float g_v  [(size_t)N_MAX * CH];
__device__ float g_acc[(size_t)N_MAX * CH];
__device__ float g_npe[KVOL * CH];
__device__ float g_s1[8];
__device__ float g_s2[2 * CH];
__device__ float g_bn1[6];       // sc0..2, shf0..2
__device__ int   g_cnt[N_MAX];
__device__ int   g_off[N_MAX];
__device__ int   g_cur[N_MAX];
__device__ int   g_sorted[M_MAX];
__device__ int   g_bsum[128];
__device__ int   g_bbase[128];
// weight panels, transposed to [n][k] K-major, bf16 split hi/lo
// index: 0=W3, 1=Wq, 2=Wv, 3=Wo
__device__ __nv_bfloat16 g_Whi[4][CH * CH];
__device__ __nv_bfloat16 g_Wlo[4][CH * CH];

// ---------------- init: zero stats + normalize pos_enc ---------------------
__global__ void init_kernel(const float* __restrict__ pos_enc) {
    int tid = threadIdx.x;
    if (tid < 8)  g_s1[tid] = 0.f;
    if (tid < 256) g_s2[tid] = 0.f;
    if (tid < KVOL * 8) {
        const float* src = pos_enc + tid * 16;
        float v[16]; float s = 0.f;
#pragma unroll
        for (int i = 0; i < 16; i++) { v[i] = src[i]; s += v[i] * v[i]; }
        float inv = 1.f / fmaxf(sqrtf(s), 1e-12f);
#pragma unroll
        for (int i = 0; i < 16; i++) g_npe[tid * 16 + i] = v[i] * inv;
    }
}

// ---------------- stats for BN1 + weight prep + q-histogram (fused) --------
// grid MUST be 256 blocks x 256 threads (65536 = 4 * 128 * 128)
__global__ void __launch_bounds__(256) stats1_kernel(
        const float* __restrict__ points, const float* __restrict__ W1, int n,
        const float* __restrict__ W3, const float* __restrict__ Wq,
        const float* __restrict__ Wv, const float* __restrict__ Wo,
        const int* __restrict__ kq, int M) {
    int gid = blockIdx.x * 256 + threadIdx.x;      // 0..65535
    {
        int w = gid >> 14;
        int e = gid & 16383;
        int k = e >> 7, nn = e & 127;
        const float* Wsrc = (w == 0) ? W3 : (w == 1) ? Wq : (w == 2) ? Wv : Wo;
        float x = __ldg(&Wsrc[k * CH + nn]);
        __nv_bfloat16 hi = __float2bfloat16(x);
        __nv_bfloat16 lo = __float2bfloat16(x - __bfloat162float(hi));
        g_Whi[w][nn * CH + k] = hi;
        g_Wlo[w][nn * CH + k] = lo;
    }
    // fused histogram of q_idx
    for (int i = gid; i < M; i += 65536)
        atomicAdd(&g_cnt[__ldg(&kq[M + i])], 1);

    __shared__ float sh[6];
    if (threadIdx.x < 6) sh[threadIdx.x] = 0.f;
    __syncthreads();
    float w[9];
#pragma unroll
    for (int i = 0; i < 9; i++) w[i] = __ldg(&W1[i]);
    float s[3] = {0.f, 0.f, 0.f}, q[3] = {0.f, 0.f, 0.f};
    for (int i = gid; i < n; i += 65536) {
        float px = points[i * 3 + 0], py = points[i * 3 + 1], pz = points[i * 3 + 2];
#pragma unroll
        for (int j = 0; j < 3; j++) {
            float h = px * w[j] + py * w[3 + j] + pz * w[6 + j];
            s[j] += h; q[j] += h * h;
        }
    }
#pragma unroll
    for (int o = 16; o; o >>= 1) {
#pragma unroll
        for (int j = 0; j < 3; j++) {
            s[j] += __shfl_down_sync(0xFFFFFFFFu, s[j], o);
            q[j] += __shfl_down_sync(0xFFFFFFFFu, q[j], o);
        }
    }
    if ((threadIdx.x & 31) == 0) {
#pragma unroll
        for (int j = 0; j < 3; j++) {
            atomicAdd(&sh[j], s[j]);
            atomicAdd(&sh[3 + j], q[j]);
        }
    }
    __syncthreads();
    if (threadIdx.x < 6) atomicAdd(&g_s1[threadIdx.x], sh[threadIdx.x]);
}

// ---------------- BN2 stats only (h2 recomputed in gemm, never stored) -----
#define H2_PB 128
__global__ void __launch_bounds__(256) h2_kernel(
        const float* __restrict__ points, const float* __restrict__ W1,
        const float* __restrict__ g1, const float* __restrict__ b1,
        const float* __restrict__ W2, int n) {
    __shared__ float ssum[CH], ssq[CH];
    int tid = threadIdx.x;
    if (tid < CH) { ssum[tid] = 0.f; ssq[tid] = 0.f; }
    __syncthreads();

    float w1[9];
#pragma unroll
    for (int i = 0; i < 9; i++) w1[i] = __ldg(&W1[i]);
    float invn = 1.f / (float)n;
    float sc[3], shf[3];
#pragma unroll
    for (int j = 0; j < 3; j++) {
        float mu  = g_s1[j] * invn;
        float var = g_s1[3 + j] * invn - mu * mu;
        float rs  = rsqrtf(var + BN_EPS);
        float s   = rs * __ldg(&g1[j]);
        sc[j] = s; shf[j] = __ldg(&b1[j]) - mu * s;
    }
    if (blockIdx.x == 0 && tid < 3) {
        g_bn1[tid] = sc[tid];
        g_bn1[3 + tid] = shf[tid];
    }
    int lane = tid & 31, wid = tid >> 5;
    int c0 = lane * 4;
    float w2a[4], w2b[4], w2c[4];
#pragma unroll
    for (int i = 0; i < 4; i++) {
        w2a[i] = __ldg(&W2[0 * CH + c0 + i]);
        w2b[i] = __ldg(&W2[1 * CH + c0 + i]);
        w2c[i] = __ldg(&W2[2 * CH + c0 + i]);
    }
    float ls[4] = {0, 0, 0, 0}, lq[4] = {0, 0, 0, 0};
    int base = blockIdx.x * H2_PB;
    int nend = min(base + H2_PB, n);
    for (int p = base + wid; p < nend; p += 8) {
        float px = __ldg(&points[p * 3 + 0]);
        float py = __ldg(&points[p * 3 + 1]);
        float pz = __ldg(&points[p * 3 + 2]);
        float a[3];
#pragma unroll
        for (int j = 0; j < 3; j++) {
            float h = px * w1[j] + py * w1[3 + j] + pz * w1[6 + j];
            a[j] = fmaxf(h * sc[j] + shf[j], 0.f);
        }
#pragma unroll
        for (int i = 0; i < 4; i++) {
            float o = a[0] * w2a[i] + a[1] * w2b[i] + a[2] * w2c[i];
            ls[i] += o; lq[i] += o * o;
        }
    }
#pragma unroll
    for (int i = 0; i < 4; i++) {
        atomicAdd(&ssum[c0 + i], ls[i]);
        atomicAdd(&ssq[c0 + i], lq[i]);
    }
    __syncthreads();
    if (tid < CH) {
        atomicAdd(&g_s2[tid], ssum[tid]);
        atomicAdd(&g_s2[CH + tid], ssq[tid]);
    }
}

// ---------------- persistent tensor-core GEMM (bf16 split, LDSM) -----------
// B panels staged ONCE per CTA; BM=32 tiles looped with double-buffered A.
// MODE 0: C = A@W + bias
// MODE 1: A' = relu(bn2(relu(bn1(points@W1))@W2)); C = A'@W + bias + extra
// MODE 2: C = l2norm_per16(A@W + bias)
#define SASTRIDE 136
#define BM 32
#define SB_ELEMS (128 * SASTRIDE)
#define ABUF_ELEMS (BM * SASTRIDE)          // per hi/lo buffer
#define TC_SMEM ((2 * SB_ELEMS + 4 * ABUF_ELEMS) * 2 + 256 * 4)
#define GEMM_GRID 296

#define LDSM4(R0, R1, R2, R3, ADDR) \
    asm volatile("ldmatrix.sync.aligned.m8n8.x4.shared.b16 {%0,%1,%2,%3}, [%4];" \
        : "=r"(R0), "=r"(R1), "=r"(R2), "=r"(R3) : "r"(ADDR))

__device__ __forceinline__ void mma16816(float* c, const unsigned* a, const unsigned* b) {
    asm volatile(
        "mma.sync.aligned.m16n8k16.row.col.f32.bf16.bf16.f32 "
        "{%0,%1,%2,%3}, {%4,%5,%6,%7}, {%8,%9}, {%0,%1,%2,%3};"
        : "+f"(c[0]), "+f"(c[1]), "+f"(c[2]), "+f"(c[3])
        : "r"(a[0]), "r"(a[1]), "r"(a[2]), "r"(a[3]), "r"(b[0]), "r"(b[1]));
}

template <int MODE>
__global__ void __launch_bounds__(256, 2) gemm_p(
        const float* __restrict__ A, const __nv_bfloat16* __restrict__ Bhi,
        const __nv_bfloat16* __restrict__ Blo, const float* __restrict__ bias,
        float* __restrict__ C, const float* __restrict__ extra,
        const float* __restrict__ gamma, const float* __restrict__ beta,
        const float* __restrict__ points, const float* __restrict__ W1,
        const float* __restrict__ W2, int nrows) {
    extern __shared__ char smraw[];
    __nv_bfloat16* sBhi = (__nv_bfloat16*)smraw;
    __nv_bfloat16* sBlo = sBhi + SB_ELEMS;
    __nv_bfloat16* sA   = sBlo + SB_ELEMS;      // [buf][hi|lo]
    float* s_sc = (float*)(sA + 4 * ABUF_ELEMS);
    float* s_sh = s_sc + CH;

    int tid = threadIdx.x;

    // ---- stage B panels once ----
#pragma unroll
    for (int i = 0; i < 8; i++) {
        int g = i * 256 + tid;           // uint4 index, 2048 total
        int nn = g >> 4;
        int kk = (g & 15) * 8;
        *(uint4*)&sBhi[nn * SASTRIDE + kk] = __ldg((const uint4*)&Bhi[nn * CH + kk]);
        *(uint4*)&sBlo[nn * SASTRIDE + kk] = __ldg((const uint4*)&Blo[nn * CH + kk]);
    }
    if (MODE == 1 && tid < CH) {
        float invn = 1.f / (float)nrows;
        float mu  = g_s2[tid] * invn;
        float var = g_s2[CH + tid] * invn - mu * mu;
        float rs  = rsqrtf(var + BN_EPS);
        float s   = rs * __ldg(&gamma[tid]);
        s_sc[tid] = s; s_sh[tid] = __ldg(&beta[tid]) - mu * s;
    }
    __syncthreads();

    // ---- per-thread loop-invariant constants ----
    int rbase = tid >> 5;                // 0..7: handles rows rbase, +8, +16, +24
    int c = (tid & 31) * 4;              // fixed 4-col group
    float w1[9], sc1[3], sh1[3];
    float4 w20, w21, w22, sc4, sh4;
    if (MODE == 1) {
#pragma unroll
        for (int i = 0; i < 9; i++) w1[i] = __ldg(&W1[i]);
#pragma unroll
        for (int j = 0; j < 3; j++) { sc1[j] = g_bn1[j]; sh1[j] = g_bn1[3 + j]; }
        w20 = __ldg((const float4*)&W2[0 * CH + c]);
        w21 = __ldg((const float4*)&W2[1 * CH + c]);
        w22 = __ldg((const float4*)&W2[2 * CH + c]);
        sc4 = *(const float4*)&s_sc[c];
        sh4 = *(const float4*)&s_sh[c];
    }

    // warp tiling: 8 warps = 2(m) x 4(n); warp tile 16x32
    int wid = tid >> 5, lane = tid & 31;
    int warp_m = (wid & 1) * 16;
    int warp_n = (wid >> 1) * 32;
    int rq = lane >> 2;
    int kq = (lane & 3) * 2;

    unsigned uA   = (unsigned)__cvta_generic_to_shared(sA);
    unsigned uBhi = (unsigned)__cvta_generic_to_shared(sBhi);
    unsigned uBlo = (unsigned)__cvta_generic_to_shared(sBlo);
    int arow = warp_m + (lane & 15);
    int acol = (lane >> 4) * 8;
    unsigned aOff = (unsigned)((arow * SASTRIDE + acol) * 2);
    int brow = warp_n + (lane & 7) + ((lane >> 4) & 1) * 8;
    int bcol = ((lane >> 3) & 1) * 8;
    unsigned bHi = uBhi + (unsigned)((brow * SASTRIDE + bcol) * 2);
    unsigned bLo = uBlo + (unsigned)((brow * SASTRIDE + bcol) * 2);
    const unsigned BROW16 = 16 * SASTRIDE * 2;
    const unsigned ABUF_B = 2 * ABUF_ELEMS * 2;   // bytes per buffer (hi+lo)
    const unsigned ALO_B  = ABUF_ELEMS * 2;

    int ntiles = (nrows + BM - 1) / BM;
    int t = blockIdx.x;

    // ---- prefetch A values for first tile ----
    float4 pref[4];
#define LOAD_PREF(TT)                                                         \
    {                                                                         \
        _Pragma("unroll")                                                     \
        for (int i = 0; i < 4; i++) {                                         \
            int row = (TT) * BM + i * 8 + rbase;                              \
            float4 a = make_float4(0.f, 0.f, 0.f, 0.f);                       \
            if (row < nrows) {                                                \
                if (MODE == 1) {                                              \
                    float px = __ldg(&points[row * 3 + 0]);                   \
                    float py = __ldg(&points[row * 3 + 1]);                   \
                    float pz = __ldg(&points[row * 3 + 2]);                   \
                    float t0 = fmaxf(fmaf(px * w1[0] + py * w1[3] + pz * w1[6], sc1[0], sh1[0]), 0.f); \
                    float t1 = fmaxf(fmaf(px * w1[1] + py * w1[4] + pz * w1[7], sc1[1], sh1[1]), 0.f); \
                    float t2 = fmaxf(fmaf(px * w1[2] + py * w1[5] + pz * w1[8], sc1[2], sh1[2]), 0.f); \
                    a.x = fmaxf(fmaf(t0 * w20.x + t1 * w21.x + t2 * w22.x, sc4.x, sh4.x), 0.f); \
                    a.y = fmaxf(fmaf(t0 * w20.y + t1 * w21.y + t2 * w22.y, sc4.y, sh4.y), 0.f); \
                    a.z = fmaxf(fmaf(t0 * w20.z + t1 * w21.z + t2 * w22.z, sc4.z, sh4.z), 0.f); \
                    a.w = fmaxf(fmaf(t0 * w20.w + t1 * w21.w + t2 * w22.w, sc4.w, sh4.w), 0.f); \
                } else {                                                      \
                    a = __ldg((const float4*)&A[(size_t)row * CH + c]);       \
                }                                                             \
            }                                                                 \
            pref[i] = a;                                                      \
        }                                                                     \
    }
    if (t < ntiles) LOAD_PREF(t);

    int it = 0;
    while (t < ntiles) {
        int buf = it & 1;
        __nv_bfloat16* sAhi = sA + buf * 2 * ABUF_ELEMS;
        __nv_bfloat16* sAlo = sAhi + ABUF_ELEMS;
        // ---- store prefetched A tile (convert + split) ----
#pragma unroll
        for (int i = 0; i < 4; i++) {
            int r = i * 8 + rbase;
            float4 a = pref[i];
            __nv_bfloat162 h0 = __floats2bfloat162_rn(a.x, a.y);
            __nv_bfloat162 h1 = __floats2bfloat162_rn(a.z, a.w);
            float2 h0f = __bfloat1622float2(h0);
            float2 h1f = __bfloat1622float2(h1);
            __nv_bfloat162 l0 = __floats2bfloat162_rn(a.x - h0f.x, a.y - h0f.y);
            __nv_bfloat162 l1 = __floats2bfloat162_rn(a.z - h1f.x, a.w - h1f.y);
            *(__nv_bfloat162*)&sAhi[r * SASTRIDE + c]     = h0;
            *(__nv_bfloat162*)&sAhi[r * SASTRIDE + c + 2] = h1;
            *(__nv_bfloat162*)&sAlo[r * SASTRIDE + c]     = l0;
            *(__nv_bfloat162*)&sAlo[r * SASTRIDE + c + 2] = l1;
        }
        __syncthreads();

        int row_lo = t * BM + warp_m + rq;
        int row_hi = row_lo + 8;
        bool ok_lo = row_lo < nrows, ok_hi = row_hi < nrows;

        // ---- prefetch epilogue 'extra' for current tile (overlaps MMA) ----
        float2 ext[8];
        if (MODE == 1) {
#pragma unroll
            for (int nt = 0; nt < 4; nt++) {
                int col = warp_n + nt * 8 + kq;
                ext[nt]     = ok_lo ? __ldg((const float2*)&extra[(size_t)row_lo * CH + col])
                                    : make_float2(0.f, 0.f);
                ext[4 + nt] = ok_hi ? __ldg((const float2*)&extra[(size_t)row_hi * CH + col])
                                    : make_float2(0.f, 0.f);
            }
        }
        // ---- prefetch A for next tile (overlaps MMA) ----
        int tn = t + GEMM_GRID;
        if (tn < ntiles) LOAD_PREF(tn);

        // ---- MMA ----
        unsigned aHi = uA + buf * ABUF_B + aOff;
        unsigned aLo = aHi + ALO_B;
        float acc[4][4];
#pragma unroll
        for (int nt = 0; nt < 4; nt++)
#pragma unroll
            for (int j = 0; j < 4; j++) acc[nt][j] = 0.f;
#pragma unroll
        for (int ks = 0; ks < 8; ks++) {
            unsigned ko = ks * 32;
            unsigned ah[4], al[4];
            LDSM4(ah[0], ah[1], ah[2], ah[3], aHi + ko);
            LDSM4(al[0], al[1], al[2], al[3], aLo + ko);
            unsigned bh[8], bl[8];
            LDSM4(bh[0], bh[1], bh[2], bh[3], bHi + ko);
            LDSM4(bh[4], bh[5], bh[6], bh[7], bHi + BROW16 + ko);
            LDSM4(bl[0], bl[1], bl[2], bl[3], bLo + ko);
            LDSM4(bl[4], bl[5], bl[6], bl[7], bLo + BROW16 + ko);
#pragma unroll
            for (int nt = 0; nt < 4; nt++) {
                mma16816(acc[nt], ah, bh + 2 * nt);
                mma16816(acc[nt], ah, bl + 2 * nt);
                mma16816(acc[nt], al, bh + 2 * nt);
            }
        }

        // ---- epilogue ----
#pragma unroll
        for (int nt = 0; nt < 4; nt++) {
            int col = warp_n + nt * 8 + kq;
            float2 bs = *(const float2*)&bias[col];
            acc[nt][0] += bs.x; acc[nt][1] += bs.y;
            acc[nt][2] += bs.x; acc[nt][3] += bs.y;
            if (MODE == 1) {
                acc[nt][0] += ext[nt].x;     acc[nt][1] += ext[nt].y;
                acc[nt][2] += ext[4 + nt].x; acc[nt][3] += ext[4 + nt].y;
            }
        }
        if (MODE == 2) {
#pragma unroll
            for (int hp = 0; hp < 2; hp++) {
                int n0 = hp * 2, n1 = n0 + 1;
                float s0 = acc[n0][0] * acc[n0][0] + acc[n0][1] * acc[n0][1]
                         + acc[n1][0] * acc[n1][0] + acc[n1][1] * acc[n1][1];
                float s1 = acc[n0][2] * acc[n0][2] + acc[n0][3] * acc[n0][3]
                         + acc[n1][2] * acc[n1][2] + acc[n1][3] * acc[n1][3];
                s0 += __shfl_xor_sync(0xFFFFFFFFu, s0, 1);
                s0 += __shfl_xor_sync(0xFFFFFFFFu, s0, 2);
                s1 += __shfl_xor_sync(0xFFFFFFFFu, s1, 1);
                s1 += __shfl_xor_sync(0xFFFFFFFFu, s1, 2);
                float i0 = 1.f / fmaxf(sqrtf(s0), 1e-12f);
                float i1 = 1.f / fmaxf(sqrtf(s1), 1e-12f);
                acc[n0][0] *= i0; acc[n0][1] *= i0;
                acc[n1][0] *= i0; acc[n1][1] *= i0;
                acc[n0][2] *= i1; acc[n0][3] *= i1;
                acc[n1][2] *= i1; acc[n1][3] *= i1;
            }
        }
#pragma unroll
        for (int nt = 0; nt < 4; nt++) {
            int col = warp_n + nt * 8 + kq;
            if (ok_lo)
                *(float2*)&C[(size_t)row_lo * CH + col] =
                    make_float2(acc[nt][0], acc[nt][1]);
            if (ok_hi)
                *(float2*)&C[(size_t)row_hi * CH + col] =
                    make_float2(acc[nt][2], acc[nt][3]);
        }
        t = tn; ++it;
    }
#undef LOAD_PREF
}

// ---------------- multi-block exclusive scan of g_cnt -----------------------
#define SC_CHUNK 1024
__global__ void __launch_bounds__(SC_CHUNK) scan1_kernel(int n) {
    __shared__ int sm[SC_CHUNK];
    int t = threadIdx.x;
    int i = blockIdx.x * SC_CHUNK + t;
    int v = (i < n) ? g_cnt[i] : 0;
    sm[t] = v;
    __syncthreads();
#pragma unroll
    for (int o = 1; o < SC_CHUNK; o <<= 1) {
        int x = (t >= o) ? sm[t - o] : 0;
        __syncthreads();
        sm[t] += x;
        __syncthreads();
    }
    if (i < n) g_off[i] = sm[t] - v;              // local exclusive
    if (t == SC_CHUNK - 1) g_bsum[blockIdx.x] = sm[t];
}

__global__ void __launch_bounds__(128) scan2_kernel(int nb) {
    __shared__ int sm[128];
    int t = threadIdx.x;
    int v = (t < nb) ? g_bsum[t] : 0;
    sm[t] = v;
    __syncthreads();
#pragma unroll
    for (int o = 1; o < 128; o <<= 1) {
        int x = (t >= o) ? sm[t - o] : 0;
        __syncthreads();
        sm[t] += x;
        __syncthreads();
    }
    if (t < nb) g_bbase[t] = sm[t] - v;           // exclusive block base
}

__global__ void __launch_bounds__(SC_CHUNK) scan3_kernel(int n) {
    int i = blockIdx.x * SC_CHUNK + threadIdx.x;
    if (i < n) {
        int o = g_off[i] + g_bbase[blockIdx.x];
        g_off[i] = o;
        g_cur[i] = o;
    }
}

__global__ void __launch_bounds__(256) place_kernel(const int* __restrict__ kq, int M) {
    int i = blockIdx.x * blockDim.x + threadIdx.x;
    if (i < M) {
        int q = __ldg(&kq[M + i]);
        int pos = atomicAdd(&g_cur[q], 1);
        g_sorted[pos] = __ldg(&kq[i]);
    }
}

// ---------------- persistent segment gather: warp per query ----------------
// npe staged in smem once per block; v via L1tex; no atomics.
#define GATHER_BLOCKS 592
__global__ void __launch_bounds__(256) gather_kernel(int n) {
    __shared__ float s_npe[KVOL * CH];
    for (int i = threadIdx.x; i < KVOL * CH / 4; i += 256)
        ((float4*)s_npe)[i] = ((const float4*)g_npe)[i];
    __syncthreads();

    int lane = threadIdx.x & 31;
    int c4 = lane * 4;
    int wid0 = (blockIdx.x * 256 + threadIdx.x) >> 5;
    const int nwarps = GATHER_BLOCKS * 8;

    for (int gw = wid0; gw < n; gw += nwarps) {
        int beg = __ldg(&g_off[gw]);
        int cnt = __ldg(&g_cnt[gw]);
        float4 qv = __ldcs((const float4*)&g_q[(size_t)gw * CH + c4]);  // once-read
        float4 acc = make_float4(0.f, 0.f, 0.f, 0.f);

        int i = 0;
#pragma unroll 2
        for (; i + 4 <= cnt; i += 4) {
            int key[4], kern[4];
#pragma unroll
            for (int j = 0; j < 4; j++) {
                int e = __ldg(&g_sorted[beg + i + j]);
                key[j]  = e / KVOL;
                kern[j] = e - key[j] * KVOL;
            }
            float4 v[4];
#pragma unroll
            for (int j = 0; j < 4; j++)
                v[j] = __ldg((const float4*)&g_v[(size_t)key[j] * CH + c4]);
            float s[4];
#pragma unroll
            for (int j = 0; j < 4; j++) {
                float4 p = *(const float4*)&s_npe[kern[j] * CH + c4];
                float t = qv.x * p.x + qv.y * p.y + qv.z * p.z + qv.w * p.w;
                t += __shfl_xor_sync(0xFFFFFFFFu, t, 1);
                t += __shfl_xor_sync(0xFFFFFFFFu, t, 2);   // 16-ch head dot
                s[j] = t;
            }
#pragma unroll
            for (int j = 0; j < 4; j++) {
                acc.x = fmaf(s[j], v[j].x, acc.x);
                acc.y = fmaf(s[j], v[j].y, acc.y);
                acc.z = fmaf(s[j], v[j].z, acc.z);
                acc.w = fmaf(s[j], v[j].w, acc.w);
            }
        }
        for (; i < cnt; i++) {
            int e = __ldg(&g_sorted[beg + i]);
            int key = e / KVOL;
            int kern = e - key * KVOL;
            float4 v = __ldg((const float4*)&g_v[(size_t)key * CH + c4]);
            float4 p = *(const float4*)&s_npe[kern * CH + c4];
            float t = qv.x * p.x + qv.y * p.y + qv.z * p.z + qv.w * p.w;
            t += __shfl_xor_sync(0xFFFFFFFFu, t, 1);
            t += __shfl_xor_sync(0xFFFFFFFFu, t, 2);
            acc.x = fmaf(t, v.x, acc.x);
            acc.y = fmaf(t, v.y, acc.y);
            acc.z = fmaf(t, v.z, acc.z);
            acc.w = fmaf(t, v.w, acc.w);
        }
        __stcs((float4*)&g_acc[(size_t)gw * CH + c4], acc);  // once-written
    }
}

// ---------------- host launch ----------------------------------------------
extern "C" void kernel_launch(void* const* d_in, const int* in_sizes, int n_in,
                              void* d_out, int out_size) {
    const float* feats   = (const float*)d_in[0];
    const float* points  = (const float*)d_in[1];
    const int*   kq      = (const int*)d_in[2];
    const float* W1 = (const float*)d_in[3];
    const float* g1 = (const float*)d_in[4];
    const float* b1 = (const float*)d_in[5];
    const float* W2 = (const float*)d_in[6];
    const float* g2 = (const float*)d_in[7];
    const float* b2 = (const float*)d_in[8];
    const float* W3 = (const float*)d_in[9];
    const float* b3 = (const float*)d_in[10];
    const float* Wq = (const float*)d_in[11];
    const float* bq = (const float*)d_in[12];
    const float* Wv = (const float*)d_in[13];
    const float* bv = (const float*)d_in[14];
    const float* pos_enc = (const float*)d_in[15];
    const float* Wo = (const float*)d_in[16];
    const float* bo = (const float*)d_in[17];

    int N = in_sizes[0] / CH;
    int M = in_sizes[2] / 2;

    cudaFuncSetAttribute((const void*)gemm_p<0>,
                         cudaFuncAttributeMaxDynamicSharedMemorySize, TC_SMEM);
    cudaFuncSetAttribute((const void*)gemm_p<1>,
                         cudaFuncAttributeMaxDynamicSharedMemorySize, TC_SMEM);
    cudaFuncSetAttribute((const void*)gemm_p<2>,
                         cudaFuncAttributeMaxDynamicSharedMemorySize, TC_SMEM);

    float* xp; float* qp; float* vp; float* ap;
    __nv_bfloat16* whi; __nv_bfloat16* wlo;
    { void* t; cudaGetSymbolAddress(&t, g_x);   xp  = (float*)t; }
    { void* t; cudaGetSymbolAddress(&t, g_q);   qp  = (float*)t; }
    { void* t; cudaGetSymbolAddress(&t, g_v);   vp  = (float*)t; }
    { void* t; cudaGetSymbolAddress(&t, g_acc); ap  = (float*)t; }
    { void* t; cudaGetSymbolAddress(&t, g_Whi); whi = (__nv_bfloat16*)t; }
    { void* t; cudaGetSymbolAddress(&t, g_Wlo); wlo = (__nv_bfloat16*)t; }
    void* cntp = nullptr;
    cudaGetSymbolAddress(&cntp, g_cnt);
    cudaMemsetAsync(cntp, 0, (size_t)N * sizeof(int), 0);

    int nsb = (N + SC_CHUNK - 1) / SC_CHUNK;      // scan blocks (<=128)

    init_kernel<<<1, 256>>>(pos_enc);
    stats1_kernel<<<256, 256>>>(points, W1, N, W3, Wq, Wv, Wo, kq, M);
    h2_kernel<<<(N + H2_PB - 1) / H2_PB, 256>>>(points, W1, g1, b1, W2, N);
    scan1_kernel<<<nsb, SC_CHUNK>>>(N);
    scan2_kernel<<<1, 128>>>(nsb);
    scan3_kernel<<<nsb, SC_CHUNK>>>(N);
    place_kernel<<<(M + 255) / 256, 256>>>(kq, M);

    // x = relu(bn2(h2(points))) @ W3 + b3 + feats   (h2 recomputed in-kernel)
    gemm_p<1><<<GEMM_GRID, 256, TC_SMEM>>>(nullptr, whi + 0 * CH * CH, wlo + 0 * CH * CH,
                                           b3, xp, feats, g2, b2, points, W1, W2, N);
    // q = l2norm16(x @ Wq + bq)
    gemm_p<2><<<GEMM_GRID, 256, TC_SMEM>>>(xp, whi + 1 * CH * CH, wlo + 1 * CH * CH,
                                           bq, qp, nullptr, nullptr, nullptr,
                                           nullptr, nullptr, nullptr, N);
    // v = x @ Wv + bv
    gemm_p<0><<<GEMM_GRID, 256, TC_SMEM>>>(xp, whi + 2 * CH * CH, wlo + 2 * CH * CH,
                                           bv, vp, nullptr, nullptr, nullptr,
                                           nullptr, nullptr, nullptr, N);

    // attention: persistent segment gather, npe in smem, no atomics
    gather_kernel<<<GATHER_BLOCKS, 256>>>(N);

    // out = acc @ Wo + bo
    gemm_p<0><<<GEMM_GRID, 256, TC_SMEM>>>(ap, whi + 3 * CH * CH, wlo + 3 * CH * CH,
                                           bo, (float*)d_out, nullptr, nullptr, nullptr,
                                           nullptr, nullptr, nullptr, N);
}

// round 10
// speedup vs baseline: 2.1593x; 1.0068x over previous
#include <cuda_runtime.h>
#include <cuda_bf16.h>
#include <cuda_fp16.h>
#include <math.h>

#define N_MAX 100000
#define M_MAX 1600000
#define CH 128
#define KVOL 27
#define BN_EPS 1e-5f

// ---------------- scratch (device globals; no runtime allocation) ----------
__device__ float g_x  [(size_t)N_MAX * CH];
__device__ float g_q  [(size_t)N_MAX * CH];
__device__ __half g_vh[(size_t)N_MAX * CH];   // v in fp16 (halves gather traffic)
__device__ float g_acc[(size_t)N_MAX * CH];
__device__ float g_npe[KVOL * CH];
__device__ float g_s1[8];
__device__ float g_s2[2 * CH];
__device__ float g_bn1[6];       // sc0..2, shf0..2
__device__ int   g_cnt[N_MAX];
__device__ int   g_off[N_MAX];
__device__ int   g_cur[N_MAX];
__device__ int   g_sorted[M_MAX];
__device__ int   g_bsum[128];
__device__ int   g_bbase[128];
// weight panels, transposed to [n][k] K-major, bf16 split hi/lo
// index: 0=W3, 1=Wq, 2=Wv, 3=Wo
__device__ __nv_bfloat16 g_Whi[4][CH * CH];
__device__ __nv_bfloat16 g_Wlo[4][CH * CH];

// ---------------- init: zero stats + normalize pos_enc ---------------------
__global__ void init_kernel(const float* __restrict__ pos_enc) {
    int tid = threadIdx.x;
    if (tid < 8)  g_s1[tid] = 0.f;
    if (tid < 256) g_s2[tid] = 0.f;
    if (tid < KVOL * 8) {
        const float* src = pos_enc + tid * 16;
        float v[16]; float s = 0.f;
#pragma unroll
        for (int i = 0; i < 16; i++) { v[i] = src[i]; s += v[i] * v[i]; }
        float inv = 1.f / fmaxf(sqrtf(s), 1e-12f);
#pragma unroll
        for (int i = 0; i < 16; i++) g_npe[tid * 16 + i] = v[i] * inv;
    }
}

// ---------------- stats for BN1 + weight prep + q-histogram (fused) --------
// grid MUST be 256 blocks x 256 threads (65536 = 4 * 128 * 128)
__global__ void __launch_bounds__(256) stats1_kernel(
        const float* __restrict__ points, const float* __restrict__ W1, int n,
        const float* __restrict__ W3, const float* __restrict__ Wq,
        const float* __restrict__ Wv, const float* __restrict__ Wo,
        const int* __restrict__ kq, int M) {
    int gid = blockIdx.x * 256 + threadIdx.x;      // 0..65535
    {
        int w = gid >> 14;
        int e = gid & 16383;
        int k = e >> 7, nn = e & 127;
        const float* Wsrc = (w == 0) ? W3 : (w == 1) ? Wq : (w == 2) ? Wv : Wo;
        float x = __ldg(&Wsrc[k * CH + nn]);
        __nv_bfloat16 hi = __float2bfloat16(x);
        __nv_bfloat16 lo = __float2bfloat16(x - __bfloat162float(hi));
        g_Whi[w][nn * CH + k] = hi;
        g_Wlo[w][nn * CH + k] = lo;
    }
    // fused histogram of q_idx
    for (int i = gid; i < M; i += 65536)
        atomicAdd(&g_cnt[__ldg(&kq[M + i])], 1);

    __shared__ float sh[6];
    if (threadIdx.x < 6) sh[threadIdx.x] = 0.f;
    __syncthreads();
    float w[9];
#pragma unroll
    for (int i = 0; i < 9; i++) w[i] = __ldg(&W1[i]);
    float s[3] = {0.f, 0.f, 0.f}, q[3] = {0.f, 0.f, 0.f};
    for (int i = gid; i < n; i += 65536) {
        float px = points[i * 3 + 0], py = points[i * 3 + 1], pz = points[i * 3 + 2];
#pragma unroll
        for (int j = 0; j < 3; j++) {
            float h = px * w[j] + py * w[3 + j] + pz * w[6 + j];
            s[j] += h; q[j] += h * h;
        }
    }
#pragma unroll
    for (int o = 16; o; o >>= 1) {
#pragma unroll
        for (int j = 0; j < 3; j++) {
            s[j] += __shfl_down_sync(0xFFFFFFFFu, s[j], o);
            q[j] += __shfl_down_sync(0xFFFFFFFFu, q[j], o);
        }
    }
    if ((threadIdx.x & 31) == 0) {
#pragma unroll
        for (int j = 0; j < 3; j++) {
            atomicAdd(&sh[j], s[j]);
            atomicAdd(&sh[3 + j], q[j]);
        }
    }
    __syncthreads();
    if (threadIdx.x < 6) atomicAdd(&g_s1[threadIdx.x], sh[threadIdx.x]);
}

// ---------------- BN2 stats only (h2 recomputed in gemm, never stored) -----
#define H2_PB 128
__global__ void __launch_bounds__(256) h2_kernel(
        const float* __restrict__ points, const float* __restrict__ W1,
        const float* __restrict__ g1, const float* __restrict__ b1,
        const float* __restrict__ W2, int n) {
    __shared__ float ssum[CH], ssq[CH];
    int tid = threadIdx.x;
    if (tid < CH) { ssum[tid] = 0.f; ssq[tid] = 0.f; }
    __syncthreads();

    float w1[9];
#pragma unroll
    for (int i = 0; i < 9; i++) w1[i] = __ldg(&W1[i]);
    float invn = 1.f / (float)n;
    float sc[3], shf[3];
#pragma unroll
    for (int j = 0; j < 3; j++) {
        float mu  = g_s1[j] * invn;
        float var = g_s1[3 + j] * invn - mu * mu;
        float rs  = rsqrtf(var + BN_EPS);
        float s   = rs * __ldg(&g1[j]);
        sc[j] = s; shf[j] = __ldg(&b1[j]) - mu * s;
    }
    if (blockIdx.x == 0 && tid < 3) {
        g_bn1[tid] = sc[tid];
        g_bn1[3 + tid] = shf[tid];
    }
    int lane = tid & 31, wid = tid >> 5;
    int c0 = lane * 4;
    float w2a[4], w2b[4], w2c[4];
#pragma unroll
    for (int i = 0; i < 4; i++) {
        w2a[i] = __ldg(&W2[0 * CH + c0 + i]);
        w2b[i] = __ldg(&W2[1 * CH + c0 + i]);
        w2c[i] = __ldg(&W2[2 * CH + c0 + i]);
    }
    float ls[4] = {0, 0, 0, 0}, lq[4] = {0, 0, 0, 0};
    int base = blockIdx.x * H2_PB;
    int nend = min(base + H2_PB, n);
    for (int p = base + wid; p < nend; p += 8) {
        float px = __ldg(&points[p * 3 + 0]);
        float py = __ldg(&points[p * 3 + 1]);
        float pz = __ldg(&points[p * 3 + 2]);
        float a[3];
#pragma unroll
        for (int j = 0; j < 3; j++) {
            float h = px * w1[j] + py * w1[3 + j] + pz * w1[6 + j];
            a[j] = fmaxf(h * sc[j] + shf[j], 0.f);
        }
#pragma unroll
        for (int i = 0; i < 4; i++) {
            float o = a[0] * w2a[i] + a[1] * w2b[i] + a[2] * w2c[i];
            ls[i] += o; lq[i] += o * o;
        }
    }
#pragma unroll
    for (int i = 0; i < 4; i++) {
        atomicAdd(&ssum[c0 + i], ls[i]);
        atomicAdd(&ssq[c0 + i], lq[i]);
    }
    __syncthreads();
    if (tid < CH) {
        atomicAdd(&g_s2[tid], ssum[tid]);
        atomicAdd(&g_s2[CH + tid], ssq[tid]);
    }
}

// ---------------- persistent tensor-core GEMM (bf16 split, LDSM) -----------
// B panels staged ONCE per CTA; BM=32 tiles looped with double-buffered A.
// MODE 0: C = A@W + bias
// MODE 1: A' = relu(bn2(relu(bn1(points@W1))@W2)); C = A'@W + bias + extra
// MODE 2: C = l2norm_per16(A@W + bias)
// MODE 3: C = A@W + bias, stored as fp16
#define SASTRIDE 136
#define BM 32
#define SB_ELEMS (128 * SASTRIDE)
#define ABUF_ELEMS (BM * SASTRIDE)          // per hi/lo buffer
#define TC_SMEM ((2 * SB_ELEMS + 4 * ABUF_ELEMS) * 2 + 256 * 4)
#define GEMM_GRID 296

#define LDSM4(R0, R1, R2, R3, ADDR) \
    asm volatile("ldmatrix.sync.aligned.m8n8.x4.shared.b16 {%0,%1,%2,%3}, [%4];" \
        : "=r"(R0), "=r"(R1), "=r"(R2), "=r"(R3) : "r"(ADDR))

__device__ __forceinline__ void mma16816(float* c, const unsigned* a, const unsigned* b) {
    asm volatile(
        "mma.sync.aligned.m16n8k16.row.col.f32.bf16.bf16.f32 "
        "{%0,%1,%2,%3}, {%4,%5,%6,%7}, {%8,%9}, {%0,%1,%2,%3};"
        : "+f"(c[0]), "+f"(c[1]), "+f"(c[2]), "+f"(c[3])
        : "r"(a[0]), "r"(a[1]), "r"(a[2]), "r"(a[3]), "r"(b[0]), "r"(b[1]));
}

template <int MODE>
__global__ void __launch_bounds__(256, 2) gemm_p(
        const float* __restrict__ A, const __nv_bfloat16* __restrict__ Bhi,
        const __nv_bfloat16* __restrict__ Blo, const float* __restrict__ bias,
        float* __restrict__ C, const float* __restrict__ extra,
        const float* __restrict__ gamma, const float* __restrict__ beta,
        const float* __restrict__ points, const float* __restrict__ W1,
        const float* __restrict__ W2, int nrows) {
    extern __shared__ char smraw[];
    __nv_bfloat16* sBhi = (__nv_bfloat16*)smraw;
    __nv_bfloat16* sBlo = sBhi + SB_ELEMS;
    __nv_bfloat16* sA   = sBlo + SB_ELEMS;      // [buf][hi|lo]
    float* s_sc = (float*)(sA + 4 * ABUF_ELEMS);
    float* s_sh = s_sc + CH;

    int tid = threadIdx.x;

    // ---- stage B panels once ----
#pragma unroll
    for (int i = 0; i < 8; i++) {
        int g = i * 256 + tid;           // uint4 index, 2048 total
        int nn = g >> 4;
        int kk = (g & 15) * 8;
        *(uint4*)&sBhi[nn * SASTRIDE + kk] = __ldg((const uint4*)&Bhi[nn * CH + kk]);
        *(uint4*)&sBlo[nn * SASTRIDE + kk] = __ldg((const uint4*)&Blo[nn * CH + kk]);
    }
    if (MODE == 1 && tid < CH) {
        float invn = 1.f / (float)nrows;
        float mu  = g_s2[tid] * invn;
        float var = g_s2[CH + tid] * invn - mu * mu;
        float rs  = rsqrtf(var + BN_EPS);
        float s   = rs * __ldg(&gamma[tid]);
        s_sc[tid] = s; s_sh[tid] = __ldg(&beta[tid]) - mu * s;
    }
    __syncthreads();

    // ---- per-thread loop-invariant constants ----
    int rbase = tid >> 5;                // 0..7: handles rows rbase, +8, +16, +24
    int c = (tid & 31) * 4;              // fixed 4-col group
    float w1[9], sc1[3], sh1[3];
    float4 w20, w21, w22, sc4, sh4;
    if (MODE == 1) {
#pragma unroll
        for (int i = 0; i < 9; i++) w1[i] = __ldg(&W1[i]);
#pragma unroll
        for (int j = 0; j < 3; j++) { sc1[j] = g_bn1[j]; sh1[j] = g_bn1[3 + j]; }
        w20 = __ldg((const float4*)&W2[0 * CH + c]);
        w21 = __ldg((const float4*)&W2[1 * CH + c]);
        w22 = __ldg((const float4*)&W2[2 * CH + c]);
        sc4 = *(const float4*)&s_sc[c];
        sh4 = *(const float4*)&s_sh[c];
    }

    // warp tiling: 8 warps = 2(m) x 4(n); warp tile 16x32
    int wid = tid >> 5, lane = tid & 31;
    int warp_m = (wid & 1) * 16;
    int warp_n = (wid >> 1) * 32;
    int rq = lane >> 2;
    int kq = (lane & 3) * 2;

    unsigned uA   = (unsigned)__cvta_generic_to_shared(sA);
    unsigned uBhi = (unsigned)__cvta_generic_to_shared(sBhi);
    unsigned uBlo = (unsigned)__cvta_generic_to_shared(sBlo);
    int arow = warp_m + (lane & 15);
    int acol = (lane >> 4) * 8;
    unsigned aOff = (unsigned)((arow * SASTRIDE + acol) * 2);
    int brow = warp_n + (lane & 7) + ((lane >> 4) & 1) * 8;
    int bcol = ((lane >> 3) & 1) * 8;
    unsigned bHi = uBhi + (unsigned)((brow * SASTRIDE + bcol) * 2);
    unsigned bLo = uBlo + (unsigned)((brow * SASTRIDE + bcol) * 2);
    const unsigned BROW16 = 16 * SASTRIDE * 2;
    const unsigned ABUF_B = 2 * ABUF_ELEMS * 2;   // bytes per buffer (hi+lo)
    const unsigned ALO_B  = ABUF_ELEMS * 2;

    int ntiles = (nrows + BM - 1) / BM;
    int t = blockIdx.x;

    // ---- prefetch A values for first tile ----
    float4 pref[4];
#define LOAD_PREF(TT)                                                         \
    {                                                                         \
        _Pragma("unroll")                                                     \
        for (int i = 0; i < 4; i++) {                                         \
            int row = (TT) * BM + i * 8 + rbase;                              \
            float4 a = make_float4(0.f, 0.f, 0.f, 0.f);                       \
            if (row < nrows) {                                                \
                if (MODE == 1) {                                              \
                    float px = __ldg(&points[row * 3 + 0]);                   \
                    float py = __ldg(&points[row * 3 + 1]);                   \
                    float pz = __ldg(&points[row * 3 + 2]);                   \
                    float t0 = fmaxf(fmaf(px * w1[0] + py * w1[3] + pz * w1[6], sc1[0], sh1[0]), 0.f); \
                    float t1 = fmaxf(fmaf(px * w1[1] + py * w1[4] + pz * w1[7], sc1[1], sh1[1]), 0.f); \
                    float t2 = fmaxf(fmaf(px * w1[2] + py * w1[5] + pz * w1[8], sc1[2], sh1[2]), 0.f); \
                    a.x = fmaxf(fmaf(t0 * w20.x + t1 * w21.x + t2 * w22.x, sc4.x, sh4.x), 0.f); \
                    a.y = fmaxf(fmaf(t0 * w20.y + t1 * w21.y + t2 * w22.y, sc4.y, sh4.y), 0.f); \
                    a.z = fmaxf(fmaf(t0 * w20.z + t1 * w21.z + t2 * w22.z, sc4.z, sh4.z), 0.f); \
                    a.w = fmaxf(fmaf(t0 * w20.w + t1 * w21.w + t2 * w22.w, sc4.w, sh4.w), 0.f); \
                } else {                                                      \
                    a = __ldg((const float4*)&A[(size_t)row * CH + c]);       \
                }                                                             \
            }                                                                 \
            pref[i] = a;                                                      \
        }                                                                     \
    }
    if (t < ntiles) LOAD_PREF(t);

    int it = 0;
    while (t < ntiles) {
        int buf = it & 1;
        __nv_bfloat16* sAhi = sA + buf * 2 * ABUF_ELEMS;
        __nv_bfloat16* sAlo = sAhi + ABUF_ELEMS;
        // ---- store prefetched A tile (convert + split) ----
#pragma unroll
        for (int i = 0; i < 4; i++) {
            int r = i * 8 + rbase;
            float4 a = pref[i];
            __nv_bfloat162 h0 = __floats2bfloat162_rn(a.x, a.y);
            __nv_bfloat162 h1 = __floats2bfloat162_rn(a.z, a.w);
            float2 h0f = __bfloat1622float2(h0);
            float2 h1f = __bfloat1622float2(h1);
            __nv_bfloat162 l0 = __floats2bfloat162_rn(a.x - h0f.x, a.y - h0f.y);
            __nv_bfloat162 l1 = __floats2bfloat162_rn(a.z - h1f.x, a.w - h1f.y);
            *(__nv_bfloat162*)&sAhi[r * SASTRIDE + c]     = h0;
            *(__nv_bfloat162*)&sAhi[r * SASTRIDE + c + 2] = h1;
            *(__nv_bfloat162*)&sAlo[r * SASTRIDE + c]     = l0;
            *(__nv_bfloat162*)&sAlo[r * SASTRIDE + c + 2] = l1;
        }
        __syncthreads();

        int row_lo = t * BM + warp_m + rq;
        int row_hi = row_lo + 8;
        bool ok_lo = row_lo < nrows, ok_hi = row_hi < nrows;

        // ---- prefetch epilogue 'extra' for current tile (overlaps MMA) ----
        float2 ext[8];
        if (MODE == 1) {
#pragma unroll
            for (int nt = 0; nt < 4; nt++) {
                int col = warp_n + nt * 8 + kq;
                ext[nt]     = ok_lo ? __ldg((const float2*)&extra[(size_t)row_lo * CH + col])
                                    : make_float2(0.f, 0.f);
                ext[4 + nt] = ok_hi ? __ldg((const float2*)&extra[(size_t)row_hi * CH + col])
                                    : make_float2(0.f, 0.f);
            }
        }
        // ---- prefetch A for next tile (overlaps MMA) ----
        int tn = t + GEMM_GRID;
        if (tn < ntiles) LOAD_PREF(tn);

        // ---- MMA ----
        unsigned aHi = uA + buf * ABUF_B + aOff;
        unsigned aLo = aHi + ALO_B;
        float acc[4][4];
#pragma unroll
        for (int nt = 0; nt < 4; nt++)
#pragma unroll
            for (int j = 0; j < 4; j++) acc[nt][j] = 0.f;
#pragma unroll
        for (int ks = 0; ks < 8; ks++) {
            unsigned ko = ks * 32;
            unsigned ah[4], al[4];
            LDSM4(ah[0], ah[1], ah[2], ah[3], aHi + ko);
            LDSM4(al[0], al[1], al[2], al[3], aLo + ko);
            unsigned bh[8], bl[8];
            LDSM4(bh[0], bh[1], bh[2], bh[3], bHi + ko);
            LDSM4(bh[4], bh[5], bh[6], bh[7], bHi + BROW16 + ko);
            LDSM4(bl[0], bl[1], bl[2], bl[3], bLo + ko);
            LDSM4(bl[4], bl[5], bl[6], bl[7], bLo + BROW16 + ko);
#pragma unroll
            for (int nt = 0; nt < 4; nt++) {
                mma16816(acc[nt], ah, bh + 2 * nt);
                mma16816(acc[nt], ah, bl + 2 * nt);
                mma16816(acc[nt], al, bh + 2 * nt);
            }
        }

        // ---- epilogue ----
#pragma unroll
        for (int nt = 0; nt < 4; nt++) {
            int col = warp_n + nt * 8 + kq;
            float2 bs = *(const float2*)&bias[col];
            acc[nt][0] += bs.x; acc[nt][1] += bs.y;
            acc[nt][2] += bs.x; acc[nt][3] += bs.y;
            if (MODE == 1) {
                acc[nt][0] += ext[nt].x;     acc[nt][1] += ext[nt].y;
                acc[nt][2] += ext[4 + nt].x; acc[nt][3] += ext[4 + nt].y;
            }
        }
        if (MODE == 2) {
#pragma unroll
            for (int hp = 0; hp < 2; hp++) {
                int n0 = hp * 2, n1 = n0 + 1;
                float s0 = acc[n0][0] * acc[n0][0] + acc[n0][1] * acc[n0][1]
                         + acc[n1][0] * acc[n1][0] + acc[n1][1] * acc[n1][1];
                float s1 = acc[n0][2] * acc[n0][2] + acc[n0][3] * acc[n0][3]
                         + acc[n1][2] * acc[n1][2] + acc[n1][3] * acc[n1][3];
                s0 += __shfl_xor_sync(0xFFFFFFFFu, s0, 1);
                s0 += __shfl_xor_sync(0xFFFFFFFFu, s0, 2);
                s1 += __shfl_xor_sync(0xFFFFFFFFu, s1, 1);
                s1 += __shfl_xor_sync(0xFFFFFFFFu, s1, 2);
                float i0 = 1.f / fmaxf(sqrtf(s0), 1e-12f);
                float i1 = 1.f / fmaxf(sqrtf(s1), 1e-12f);
                acc[n0][0] *= i0; acc[n0][1] *= i0;
                acc[n1][0] *= i0; acc[n1][1] *= i0;
                acc[n0][2] *= i1; acc[n0][3] *= i1;
                acc[n1][2] *= i1; acc[n1][3] *= i1;
            }
        }
        if (MODE == 3) {
            __half* Ch = (__half*)C;
#pragma unroll
            for (int nt = 0; nt < 4; nt++) {
                int col = warp_n + nt * 8 + kq;
                if (ok_lo)
                    *(__half2*)&Ch[(size_t)row_lo * CH + col] =
                        __floats2half2_rn(acc[nt][0], acc[nt][1]);
                if (ok_hi)
                    *(__half2*)&Ch[(size_t)row_hi * CH + col] =
                        __floats2half2_rn(acc[nt][2], acc[nt][3]);
            }
        } else {
#pragma unroll
            for (int nt = 0; nt < 4; nt++) {
                int col = warp_n + nt * 8 + kq;
                if (ok_lo)
                    *(float2*)&C[(size_t)row_lo * CH + col] =
                        make_float2(acc[nt][0], acc[nt][1]);
                if (ok_hi)
                    *(float2*)&C[(size_t)row_hi * CH + col] =
                        make_float2(acc[nt][2], acc[nt][3]);
            }
        }
        t = tn; ++it;
    }
#undef LOAD_PREF
}

// ---------------- multi-block exclusive scan of g_cnt -----------------------
#define SC_CHUNK 1024
__global__ void __launch_bounds__(SC_CHUNK) scan1_kernel(int n) {
    __shared__ int sm[SC_CHUNK];
    int t = threadIdx.x;
    int i = blockIdx.x * SC_CHUNK + t;
    int v = (i < n) ? g_cnt[i] : 0;
    sm[t] = v;
    __syncthreads();
#pragma unroll
    for (int o = 1; o < SC_CHUNK; o <<= 1) {
        int x = (t >= o) ? sm[t - o] : 0;
        __syncthreads();
        sm[t] += x;
        __syncthreads();
    }
    if (i < n) g_off[i] = sm[t] - v;              // local exclusive
    if (t == SC_CHUNK - 1) g_bsum[blockIdx.x] = sm[t];
}

__global__ void __launch_bounds__(128) scan2_kernel(int nb) {
    __shared__ int sm[128];
    int t = threadIdx.x;
    int v = (t < nb) ? g_bsum[t] : 0;
    sm[t] = v;
    __syncthreads();
#pragma unroll
    for (int o = 1; o < 128; o <<= 1) {
        int x = (t >= o) ? sm[t - o] : 0;
        __syncthreads();
        sm[t] += x;
        __syncthreads();
    }
    if (t < nb) g_bbase[t] = sm[t] - v;           // exclusive block base
}

__global__ void __launch_bounds__(SC_CHUNK) scan3_kernel(int n) {
    int i = blockIdx.x * SC_CHUNK + threadIdx.x;
    if (i < n) {
        int o = g_off[i] + g_bbase[blockIdx.x];
        g_off[i] = o;
        g_cur[i] = o;
    }
}

__global__ void __launch_bounds__(256) place_kernel(const int* __restrict__ kq, int M) {
    int i = blockIdx.x * blockDim.x + threadIdx.x;
    if (i < M) {
        int q = __ldg(&kq[M + i]);
        int pos = atomicAdd(&g_cur[q], 1);
        g_sorted[pos] = __ldg(&kq[i]);
    }
}

// ---------------- persistent segment gather: warp per query ----------------
// npe staged in smem; v in fp16 (half traffic); no atomics.
#define GATHER_BLOCKS 592
__global__ void __launch_bounds__(256) gather_kernel(int n) {
    __shared__ float s_npe[KVOL * CH];
    for (int i = threadIdx.x; i < KVOL * CH / 4; i += 256)
        ((float4*)s_npe)[i] = ((const float4*)g_npe)[i];
    __syncthreads();

    int lane = threadIdx.x & 31;
    int c4 = lane * 4;
    int wid0 = (blockIdx.x * 256 + threadIdx.x) >> 5;
    const int nwarps = GATHER_BLOCKS * 8;

    for (int gw = wid0; gw < n; gw += nwarps) {
        int beg = __ldg(&g_off[gw]);
        int cnt = __ldg(&g_cnt[gw]);
        float4 qv = __ldcs((const float4*)&g_q[(size_t)gw * CH + c4]);  // once-read
        float4 acc = make_float4(0.f, 0.f, 0.f, 0.f);

        int i = 0;
#pragma unroll 2
        for (; i + 4 <= cnt; i += 4) {
            int key[4], kern[4];
#pragma unroll
            for (int j = 0; j < 4; j++) {
                int e = __ldg(&g_sorted[beg + i + j]);
                key[j]  = e / KVOL;
                kern[j] = e - key[j] * KVOL;
            }
            uint2 vh[4];
#pragma unroll
            for (int j = 0; j < 4; j++)
                vh[j] = __ldg((const uint2*)&g_vh[(size_t)key[j] * CH + c4]);
            float s[4];
#pragma unroll
            for (int j = 0; j < 4; j++) {
                float4 p = *(const float4*)&s_npe[kern[j] * CH + c4];
                float t = qv.x * p.x + qv.y * p.y + qv.z * p.z + qv.w * p.w;
                t += __shfl_xor_sync(0xFFFFFFFFu, t, 1);
                t += __shfl_xor_sync(0xFFFFFFFFu, t, 2);   // 16-ch head dot
                s[j] = t;
            }
#pragma unroll
            for (int j = 0; j < 4; j++) {
                float2 v0 = __half22float2(*(const __half2*)&vh[j].x);
                float2 v1 = __half22float2(*(const __half2*)&vh[j].y);
                acc.x = fmaf(s[j], v0.x, acc.x);
                acc.y = fmaf(s[j], v0.y, acc.y);
                acc.z = fmaf(s[j], v1.x, acc.z);
                acc.w = fmaf(s[j], v1.y, acc.w);
            }
        }
        for (; i < cnt; i++) {
            int e = __ldg(&g_sorted[beg + i]);
            int key = e / KVOL;
            int kern = e - key * KVOL;
            uint2 vh = __ldg((const uint2*)&g_vh[(size_t)key * CH + c4]);
            float4 p = *(const float4*)&s_npe[kern * CH + c4];
            float t = qv.x * p.x + qv.y * p.y + qv.z * p.z + qv.w * p.w;
            t += __shfl_xor_sync(0xFFFFFFFFu, t, 1);
            t += __shfl_xor_sync(0xFFFFFFFFu, t, 2);
            float2 v0 = __half22float2(*(const __half2*)&vh.x);
            float2 v1 = __half22float2(*(const __half2*)&vh.y);
            acc.x = fmaf(t, v0.x, acc.x);
            acc.y = fmaf(t, v0.y, acc.y);
            acc.z = fmaf(t, v1.x, acc.z);
            acc.w = fmaf(t, v1.y, acc.w);
        }
        __stcs((float4*)&g_acc[(size_t)gw * CH + c4], acc);  // once-written
    }
}

// ---------------- host launch ----------------------------------------------
extern "C" void kernel_launch(void* const* d_in, const int* in_sizes, int n_in,
                              void* d_out, int out_size) {
    const float* feats   = (const float*)d_in[0];
    const float* points  = (const float*)d_in[1];
    const int*   kq      = (const int*)d_in[2];
    const float* W1 = (const float*)d_in[3];
    const float* g1 = (const float*)d_in[4];
    const float* b1 = (const float*)d_in[5];
    const float* W2 = (const float*)d_in[6];
    const float* g2 = (const float*)d_in[7];
    const float* b2 = (const float*)d_in[8];
    const float* W3 = (const float*)d_in[9];
    const float* b3 = (const float*)d_in[10];
    const float* Wq = (const float*)d_in[11];
    const float* bq = (const float*)d_in[12];
    const float* Wv = (const float*)d_in[13];
    const float* bv = (const float*)d_in[14];
    const float* pos_enc = (const float*)d_in[15];
    const float* Wo = (const float*)d_in[16];
    const float* bo = (const float*)d_in[17];

    int N = in_sizes[0] / CH;
    int M = in_sizes[2] / 2;

    cudaFuncSetAttribute((const void*)gemm_p<0>,
                         cudaFuncAttributeMaxDynamicSharedMemorySize, TC_SMEM);
    cudaFuncSetAttribute((const void*)gemm_p<1>,
                         cudaFuncAttributeMaxDynamicSharedMemorySize, TC_SMEM);
    cudaFuncSetAttribute((const void*)gemm_p<2>,
                         cudaFuncAttributeMaxDynamicSharedMemorySize, TC_SMEM);
    cudaFuncSetAttribute((const void*)gemm_p<3>,
                         cudaFuncAttributeMaxDynamicSharedMemorySize, TC_SMEM);

    float* xp; float* qp; float* ap; __half* vhp;
    __nv_bfloat16* whi; __nv_bfloat16* wlo;
    { void* t; cudaGetSymbolAddress(&t, g_x);   xp  = (float*)t; }
    { void* t; cudaGetSymbolAddress(&t, g_q);   qp  = (float*)t; }
    { void* t; cudaGetSymbolAddress(&t, g_vh);  vhp = (__half*)t; }
    { void* t; cudaGetSymbolAddress(&t, g_acc); ap  = (float*)t; }
    { void* t; cudaGetSymbolAddress(&t, g_Whi); whi = (__nv_bfloat16*)t; }
    { void* t; cudaGetSymbolAddress(&t, g_Wlo); wlo = (__nv_bfloat16*)t; }
    void* cntp = nullptr;
    cudaGetSymbolAddress(&cntp, g_cnt);
    cudaMemsetAsync(cntp, 0, (size_t)N * sizeof(int), 0);

    int nsb = (N + SC_CHUNK - 1) / SC_CHUNK;      // scan blocks (<=128)

    init_kernel<<<1, 256>>>(pos_enc);
    stats1_kernel<<<256, 256>>>(points, W1, N, W3, Wq, Wv, Wo, kq, M);
    h2_kernel<<<(N + H2_PB - 1) / H2_PB, 256>>>(points, W1, g1, b1, W2, N);
    scan1_kernel<<<nsb, SC_CHUNK>>>(N);
    scan2_kernel<<<1, 128>>>(nsb);
    scan3_kernel<<<nsb, SC_CHUNK>>>(N);
    place_kernel<<<(M + 255) / 256, 256>>>(kq, M);

    // x = relu(bn2(h2(points))) @ W3 + b3 + feats   (h2 recomputed in-kernel)
    gemm_p<1><<<GEMM_GRID, 256, TC_SMEM>>>(nullptr, whi + 0 * CH * CH, wlo + 0 * CH * CH,
                                           b3, xp, feats, g2, b2, points, W1, W2, N);
    // q = l2norm16(x @ Wq + bq)
    gemm_p<2><<<GEMM_GRID, 256, TC_SMEM>>>(xp, whi + 1 * CH * CH, wlo + 1 * CH * CH,
                                           bq, qp, nullptr, nullptr, nullptr,
                                           nullptr, nullptr, nullptr, N);
    // v = x @ Wv + bv  -> fp16
    gemm_p<3><<<GEMM_GRID, 256, TC_SMEM>>>(xp, whi + 2 * CH * CH, wlo + 2 * CH * CH,
                                           bv, (float*)vhp, nullptr, nullptr, nullptr,
                                           nullptr, nullptr, nullptr, N);

    // attention: persistent segment gather, npe in smem, fp16 v, no atomics
    gather_kernel<<<GATHER_BLOCKS, 256>>>(N);

    // out = acc @ Wo + bo
    gemm_p<0><<<GEMM_GRID, 256, TC_SMEM>>>(ap, whi + 3 * CH * CH, wlo + 3 * CH * CH,
                                           bo, (float*)d_out, nullptr, nullptr, nullptr,
                                           nullptr, nullptr, nullptr, N);
}

// round 12
// speedup vs baseline: 2.2066x; 1.0219x over previous
#include <cuda_runtime.h>
#include <cuda_bf16.h>
#include <cuda_fp16.h>
#include <math.h>

#define N_MAX 100000
#define M_MAX 1600000
#define CH 128
#define KVOL 27
#define BN_EPS 1e-5f

// ---------------- scratch (device globals; no runtime allocation) ----------
__device__ float g_x  [(size_t)N_MAX * CH];
__device__ float g_q  [(size_t)N_MAX * CH];
__device__ __half g_vh[(size_t)N_MAX * CH];   // v in fp16
__device__ float g_acc[(size_t)N_MAX * CH];
__device__ float g_npe[KVOL * CH];
__device__ float g_s1[8];
__device__ float g_s2[2 * CH];
__device__ float g_bn1[6];       // sc0..2, shf0..2
__device__ int   g_cnt[N_MAX];
__device__ int   g_off[N_MAX];
__device__ int   g_cur[N_MAX];
__device__ int   g_sorted[M_MAX];   // encoded key*32 + kern
__device__ int   g_bsum[128];
__device__ int   g_bbase[128];
// weight panels, transposed to [n][k] K-major, bf16 split hi/lo (3-term)
// index: 0=W3, 1=Wq, 2=Wv, 3=Wo
__device__ __nv_bfloat16 g_Whi[4][CH * CH];
__device__ __nv_bfloat16 g_Wlo[4][CH * CH];

// ---------------- init: zero stats + normalize pos_enc ---------------------
__global__ void init_kernel(const float* __restrict__ pos_enc) {
    int tid = threadIdx.x;
    if (tid < 8)  g_s1[tid] = 0.f;
    if (tid < 256) g_s2[tid] = 0.f;
    if (tid < KVOL * 8) {
        const float* src = pos_enc + tid * 16;
        float v[16]; float s = 0.f;
#pragma unroll
        for (int i = 0; i < 16; i++) { v[i] = src[i]; s += v[i] * v[i]; }
        float inv = 1.f / fmaxf(sqrtf(s), 1e-12f);
#pragma unroll
        for (int i = 0; i < 16; i++) g_npe[tid * 16 + i] = v[i] * inv;
    }
}

// ---------------- stats for BN1 + weight prep + q-histogram (fused) --------
// grid MUST be 256 blocks x 256 threads (65536 = 4 * 128 * 128)
__global__ void __launch_bounds__(256) stats1_kernel(
        const float* __restrict__ points, const float* __restrict__ W1, int n,
        const float* __restrict__ W3, const float* __restrict__ Wq,
        const float* __restrict__ Wv, const float* __restrict__ Wo,
        const int* __restrict__ kq, int M) {
    int gid = blockIdx.x * 256 + threadIdx.x;      // 0..65535
    {
        int w = gid >> 14;
        int e = gid & 16383;
        int k = e >> 7, nn = e & 127;
        const float* Wsrc = (w == 0) ? W3 : (w == 1) ? Wq : (w == 2) ? Wv : Wo;
        float x = __ldg(&Wsrc[k * CH + nn]);
        __nv_bfloat16 hi = __float2bfloat16(x);
        __nv_bfloat16 lo = __float2bfloat16(x - __bfloat162float(hi));
        g_Whi[w][nn * CH + k] = hi;
        g_Wlo[w][nn * CH + k] = lo;
    }
    // fused histogram of q_idx
    for (int i = gid; i < M; i += 65536)
        atomicAdd(&g_cnt[__ldg(&kq[M + i])], 1);

    __shared__ float sh[6];
    if (threadIdx.x < 6) sh[threadIdx.x] = 0.f;
    __syncthreads();
    float w[9];
#pragma unroll
    for (int i = 0; i < 9; i++) w[i] = __ldg(&W1[i]);
    float s[3] = {0.f, 0.f, 0.f}, q[3] = {0.f, 0.f, 0.f};
    for (int i = gid; i < n; i += 65536) {
        float px = points[i * 3 + 0], py = points[i * 3 + 1], pz = points[i * 3 + 2];
#pragma unroll
        for (int j = 0; j < 3; j++) {
            float h = px * w[j] + py * w[3 + j] + pz * w[6 + j];
            s[j] += h; q[j] += h * h;
        }
    }
#pragma unroll
    for (int o = 16; o; o >>= 1) {
#pragma unroll
        for (int j = 0; j < 3; j++) {
            s[j] += __shfl_down_sync(0xFFFFFFFFu, s[j], o);
            q[j] += __shfl_down_sync(0xFFFFFFFFu, q[j], o);
        }
    }
    if ((threadIdx.x & 31) == 0) {
#pragma unroll
        for (int j = 0; j < 3; j++) {
            atomicAdd(&sh[j], s[j]);
            atomicAdd(&sh[3 + j], q[j]);
        }
    }
    __syncthreads();
    if (threadIdx.x < 6) atomicAdd(&g_s1[threadIdx.x], sh[threadIdx.x]);
}

// ---------------- BN2 stats only (h2 recomputed in gemm, never stored) -----
#define H2_PB 128
__global__ void __launch_bounds__(256) h2_kernel(
        const float* __restrict__ points, const float* __restrict__ W1,
        const float* __restrict__ g1, const float* __restrict__ b1,
        const float* __restrict__ W2, int n) {
    __shared__ float ssum[CH], ssq[CH];
    int tid = threadIdx.x;
    if (tid < CH) { ssum[tid] = 0.f; ssq[tid] = 0.f; }
    __syncthreads();

    float w1[9];
#pragma unroll
    for (int i = 0; i < 9; i++) w1[i] = __ldg(&W1[i]);
    float invn = 1.f / (float)n;
    float sc[3], shf[3];
#pragma unroll
    for (int j = 0; j < 3; j++) {
        float mu  = g_s1[j] * invn;
        float var = g_s1[3 + j] * invn - mu * mu;
        float rs  = rsqrtf(var + BN_EPS);
        float s   = rs * __ldg(&g1[j]);
        sc[j] = s; shf[j] = __ldg(&b1[j]) - mu * s;
    }
    if (blockIdx.x == 0 && tid < 3) {
        g_bn1[tid] = sc[tid];
        g_bn1[3 + tid] = shf[tid];
    }
    int lane = tid & 31, wid = tid >> 5;
    int c0 = lane * 4;
    float w2a[4], w2b[4], w2c[4];
#pragma unroll
    for (int i = 0; i < 4; i++) {
        w2a[i] = __ldg(&W2[0 * CH + c0 + i]);
        w2b[i] = __ldg(&W2[1 * CH + c0 + i]);
        w2c[i] = __ldg(&W2[2 * CH + c0 + i]);
    }
    float ls[4] = {0, 0, 0, 0}, lq[4] = {0, 0, 0, 0};
    int base = blockIdx.x * H2_PB;
    int nend = min(base + H2_PB, n);
    for (int p = base + wid; p < nend; p += 8) {
        float px = __ldg(&points[p * 3 + 0]);
        float py = __ldg(&points[p * 3 + 1]);
        float pz = __ldg(&points[p * 3 + 2]);
        float a[3];
#pragma unroll
        for (int j = 0; j < 3; j++) {
            float h = px * w1[j] + py * w1[3 + j] + pz * w1[6 + j];
            a[j] = fmaxf(h * sc[j] + shf[j], 0.f);
        }
#pragma unroll
        for (int i = 0; i < 4; i++) {
            float o = a[0] * w2a[i] + a[1] * w2b[i] + a[2] * w2c[i];
            ls[i] += o; lq[i] += o * o;
        }
    }
#pragma unroll
    for (int i = 0; i < 4; i++) {
        atomicAdd(&ssum[c0 + i], ls[i]);
        atomicAdd(&ssq[c0 + i], lq[i]);
    }
    __syncthreads();
    if (tid < CH) {
        atomicAdd(&g_s2[tid], ssum[tid]);
        atomicAdd(&g_s2[CH + tid], ssq[tid]);
    }
}

// ---------------- persistent tensor-core GEMM helpers ----------------------
#define SASTRIDE 136
#define BM 32
#define SB_ELEMS (128 * SASTRIDE)
#define ABUF_ELEMS (BM * SASTRIDE)
#define GEMM_GRID 296
#define QV_GRID 148
#define TC_SMEM_1 ((2 * SB_ELEMS + 4 * ABUF_ELEMS) * 2 + 256 * 4)
#define TC_SMEM_QV ((4 * SB_ELEMS + 4 * ABUF_ELEMS) * 2)

#define LDSM4(R0, R1, R2, R3, ADDR) \
    asm volatile("ldmatrix.sync.aligned.m8n8.x4.shared.b16 {%0,%1,%2,%3}, [%4];" \
        : "=r"(R0), "=r"(R1), "=r"(R2), "=r"(R3) : "r"(ADDR))

__device__ __forceinline__ void mma16816(float* c, const unsigned* a, const unsigned* b) {
    asm volatile(
        "mma.sync.aligned.m16n8k16.row.col.f32.bf16.bf16.f32 "
        "{%0,%1,%2,%3}, {%4,%5,%6,%7}, {%8,%9}, {%0,%1,%2,%3};"
        : "+f"(c[0]), "+f"(c[1]), "+f"(c[2]), "+f"(c[3])
        : "r"(a[0]), "r"(a[1]), "r"(a[2]), "r"(a[3]), "r"(b[0]), "r"(b[1]));
}

// split a float4 into bf16 hi/lo and store to the A buffers
__device__ __forceinline__ void store_a_split(
        __nv_bfloat16* sAhi, __nv_bfloat16* sAlo, int r, int c, float4 a) {
    __nv_bfloat162 h0 = __floats2bfloat162_rn(a.x, a.y);
    __nv_bfloat162 h1 = __floats2bfloat162_rn(a.z, a.w);
    float2 h0f = __bfloat1622float2(h0);
    float2 h1f = __bfloat1622float2(h1);
    __nv_bfloat162 l0 = __floats2bfloat162_rn(a.x - h0f.x, a.y - h0f.y);
    __nv_bfloat162 l1 = __floats2bfloat162_rn(a.z - h1f.x, a.w - h1f.y);
    *(__nv_bfloat162*)&sAhi[r * SASTRIDE + c]     = h0;
    *(__nv_bfloat162*)&sAhi[r * SASTRIDE + c + 2] = h1;
    *(__nv_bfloat162*)&sAlo[r * SASTRIDE + c]     = l0;
    *(__nv_bfloat162*)&sAlo[r * SASTRIDE + c + 2] = l1;
}

// ---------------- single-weight persistent GEMM (3-term split) -------------
// MODE 0: C = A@W + bias
// MODE 1: A' = relu(bn2(relu(bn1(points@W1))@W2)); C = A'@W + bias + extra
template <int MODE>
__global__ void __launch_bounds__(256, 2) gemm_p(
        const float* __restrict__ A, const __nv_bfloat16* __restrict__ Bhi,
        const __nv_bfloat16* __restrict__ Blo, const float* __restrict__ bias,
        float* __restrict__ C, const float* __restrict__ extra,
        const float* __restrict__ gamma, const float* __restrict__ beta,
        const float* __restrict__ points, const float* __restrict__ W1,
        const float* __restrict__ W2, int nrows) {
    extern __shared__ char smraw[];
    __nv_bfloat16* sBhi = (__nv_bfloat16*)smraw;
    __nv_bfloat16* sBlo = sBhi + SB_ELEMS;
    __nv_bfloat16* sA   = sBlo + SB_ELEMS;
    float* s_sc = (float*)(sA + 4 * ABUF_ELEMS);
    float* s_sh = s_sc + CH;

    int tid = threadIdx.x;
#pragma unroll
    for (int i = 0; i < 8; i++) {
        int g = i * 256 + tid;
        int nn = g >> 4;
        int kk = (g & 15) * 8;
        *(uint4*)&sBhi[nn * SASTRIDE + kk] = __ldg((const uint4*)&Bhi[nn * CH + kk]);
        *(uint4*)&sBlo[nn * SASTRIDE + kk] = __ldg((const uint4*)&Blo[nn * CH + kk]);
    }
    if (MODE == 1 && tid < CH) {
        float invn = 1.f / (float)nrows;
        float mu  = g_s2[tid] * invn;
        float var = g_s2[CH + tid] * invn - mu * mu;
        float rs  = rsqrtf(var + BN_EPS);
        float s   = rs * __ldg(&gamma[tid]);
        s_sc[tid] = s; s_sh[tid] = __ldg(&beta[tid]) - mu * s;
    }
    __syncthreads();

    int rbase = tid >> 5;
    int c = (tid & 31) * 4;
    float w1[9], sc1[3], sh1[3];
    float4 w20, w21, w22, sc4, sh4;
    if (MODE == 1) {
#pragma unroll
        for (int i = 0; i < 9; i++) w1[i] = __ldg(&W1[i]);
#pragma unroll
        for (int j = 0; j < 3; j++) { sc1[j] = g_bn1[j]; sh1[j] = g_bn1[3 + j]; }
        w20 = __ldg((const float4*)&W2[0 * CH + c]);
        w21 = __ldg((const float4*)&W2[1 * CH + c]);
        w22 = __ldg((const float4*)&W2[2 * CH + c]);
        sc4 = *(const float4*)&s_sc[c];
        sh4 = *(const float4*)&s_sh[c];
    }

    int wid = tid >> 5, lane = tid & 31;
    int warp_m = (wid & 1) * 16;
    int warp_n = (wid >> 1) * 32;
    int rq = lane >> 2;
    int kq = (lane & 3) * 2;

    unsigned uA   = (unsigned)__cvta_generic_to_shared(sA);
    unsigned uBhi = (unsigned)__cvta_generic_to_shared(sBhi);
    unsigned uBlo = (unsigned)__cvta_generic_to_shared(sBlo);
    int arow = warp_m + (lane & 15);
    int acol = (lane >> 4) * 8;
    unsigned aOff = (unsigned)((arow * SASTRIDE + acol) * 2);
    int brow = warp_n + (lane & 7) + ((lane >> 4) & 1) * 8;
    int bcol = ((lane >> 3) & 1) * 8;
    unsigned bHi = uBhi + (unsigned)((brow * SASTRIDE + bcol) * 2);
    unsigned bLo = uBlo + (unsigned)((brow * SASTRIDE + bcol) * 2);
    const unsigned BROW16 = 16 * SASTRIDE * 2;
    const unsigned ABUF_B = 2 * ABUF_ELEMS * 2;
    const unsigned ALO_B  = ABUF_ELEMS * 2;

    int ntiles = (nrows + BM - 1) / BM;
    int t = blockIdx.x;

    float4 pref[4];
#define LOAD_PREF(TT)                                                         \
    {                                                                         \
        _Pragma("unroll")                                                     \
        for (int i = 0; i < 4; i++) {                                         \
            int row = (TT) * BM + i * 8 + rbase;                              \
            float4 a = make_float4(0.f, 0.f, 0.f, 0.f);                       \
            if (row < nrows) {                                                \
                if (MODE == 1) {                                              \
                    float px = __ldg(&points[row * 3 + 0]);                   \
                    float py = __ldg(&points[row * 3 + 1]);                   \
                    float pz = __ldg(&points[row * 3 + 2]);                   \
                    float t0 = fmaxf(fmaf(px * w1[0] + py * w1[3] + pz * w1[6], sc1[0], sh1[0]), 0.f); \
                    float t1 = fmaxf(fmaf(px * w1[1] + py * w1[4] + pz * w1[7], sc1[1], sh1[1]), 0.f); \
                    float t2 = fmaxf(fmaf(px * w1[2] + py * w1[5] + pz * w1[8], sc1[2], sh1[2]), 0.f); \
                    a.x = fmaxf(fmaf(t0 * w20.x + t1 * w21.x + t2 * w22.x, sc4.x, sh4.x), 0.f); \
                    a.y = fmaxf(fmaf(t0 * w20.y + t1 * w21.y + t2 * w22.y, sc4.y, sh4.y), 0.f); \
                    a.z = fmaxf(fmaf(t0 * w20.z + t1 * w21.z + t2 * w22.z, sc4.z, sh4.z), 0.f); \
                    a.w = fmaxf(fmaf(t0 * w20.w + t1 * w21.w + t2 * w22.w, sc4.w, sh4.w), 0.f); \
                } else {                                                      \
                    a = __ldg((const float4*)&A[(size_t)row * CH + c]);       \
                }                                                             \
            }                                                                 \
            pref[i] = a;                                                      \
        }                                                                     \
    }
    if (t < ntiles) LOAD_PREF(t);

    int it = 0;
    while (t < ntiles) {
        int buf = it & 1;
        __nv_bfloat16* sAhi = sA + buf * 2 * ABUF_ELEMS;
        __nv_bfloat16* sAlo = sAhi + ABUF_ELEMS;
#pragma unroll
        for (int i = 0; i < 4; i++)
            store_a_split(sAhi, sAlo, i * 8 + rbase, c, pref[i]);
        __syncthreads();

        int row_lo = t * BM + warp_m + rq;
        int row_hi = row_lo + 8;
        bool ok_lo = row_lo < nrows, ok_hi = row_hi < nrows;

        float2 ext[8];
        if (MODE == 1) {
#pragma unroll
            for (int nt = 0; nt < 4; nt++) {
                int col = warp_n + nt * 8 + kq;
                ext[nt]     = ok_lo ? __ldg((const float2*)&extra[(size_t)row_lo * CH + col])
                                    : make_float2(0.f, 0.f);
                ext[4 + nt] = ok_hi ? __ldg((const float2*)&extra[(size_t)row_hi * CH + col])
                                    : make_float2(0.f, 0.f);
            }
        }
        int tn = t + GEMM_GRID;
        if (tn < ntiles) LOAD_PREF(tn);

        unsigned aHi = uA + buf * ABUF_B + aOff;
        unsigned aLo = aHi + ALO_B;
        float acc[4][4];
#pragma unroll
        for (int nt = 0; nt < 4; nt++)
#pragma unroll
            for (int j = 0; j < 4; j++) acc[nt][j] = 0.f;
#pragma unroll
        for (int ks = 0; ks < 8; ks++) {
            unsigned ko = ks * 32;
            unsigned ah[4], al[4];
            LDSM4(ah[0], ah[1], ah[2], ah[3], aHi + ko);
            LDSM4(al[0], al[1], al[2], al[3], aLo + ko);
            unsigned bh[8], bl[8];
            LDSM4(bh[0], bh[1], bh[2], bh[3], bHi + ko);
            LDSM4(bh[4], bh[5], bh[6], bh[7], bHi + BROW16 + ko);
            LDSM4(bl[0], bl[1], bl[2], bl[3], bLo + ko);
            LDSM4(bl[4], bl[5], bl[6], bl[7], bLo + BROW16 + ko);
#pragma unroll
            for (int nt = 0; nt < 4; nt++) {
                mma16816(acc[nt], ah, bh + 2 * nt);
                mma16816(acc[nt], ah, bl + 2 * nt);
                mma16816(acc[nt], al, bh + 2 * nt);
            }
        }

#pragma unroll
        for (int nt = 0; nt < 4; nt++) {
            int col = warp_n + nt * 8 + kq;
            float2 bs = *(const float2*)&bias[col];
            acc[nt][0] += bs.x; acc[nt][1] += bs.y;
            acc[nt][2] += bs.x; acc[nt][3] += bs.y;
            if (MODE == 1) {
                acc[nt][0] += ext[nt].x;     acc[nt][1] += ext[nt].y;
                acc[nt][2] += ext[4 + nt].x; acc[nt][3] += ext[4 + nt].y;
            }
            if (ok_lo)
                *(float2*)&C[(size_t)row_lo * CH + col] =
                    make_float2(acc[nt][0], acc[nt][1]);
            if (ok_hi)
                *(float2*)&C[(size_t)row_hi * CH + col] =
                    make_float2(acc[nt][2], acc[nt][3]);
        }
        t = tn; ++it;
    }
#undef LOAD_PREF
}

// ---------------- merged q+v persistent GEMM (3-term split both) -----------
// q = l2norm16(A@Wq + bq) -> fp32; v = A@Wv + bv -> fp16. A staged once.
// 170 KB smem -> 1 CTA/SM; grid = 148 persistent.
__global__ void __launch_bounds__(256, 1) gemm_qv(
        const float* __restrict__ A,
        const __nv_bfloat16* __restrict__ Bqh, const __nv_bfloat16* __restrict__ Bql,
        const __nv_bfloat16* __restrict__ Bvh, const __nv_bfloat16* __restrict__ Bvl,
        const float* __restrict__ bq, const float* __restrict__ bv,
        float* __restrict__ Cq, __half* __restrict__ Cv, int nrows) {
    extern __shared__ char smraw[];
    __nv_bfloat16* sBqh = (__nv_bfloat16*)smraw;
    __nv_bfloat16* sBql = sBqh + SB_ELEMS;
    __nv_bfloat16* sBvh = sBql + SB_ELEMS;
    __nv_bfloat16* sBvl = sBvh + SB_ELEMS;
    __nv_bfloat16* sA   = sBvl + SB_ELEMS;

    int tid = threadIdx.x;
#pragma unroll
    for (int i = 0; i < 8; i++) {
        int g = i * 256 + tid;
        int nn = g >> 4;
        int kk = (g & 15) * 8;
        *(uint4*)&sBqh[nn * SASTRIDE + kk] = __ldg((const uint4*)&Bqh[nn * CH + kk]);
        *(uint4*)&sBql[nn * SASTRIDE + kk] = __ldg((const uint4*)&Bql[nn * CH + kk]);
        *(uint4*)&sBvh[nn * SASTRIDE + kk] = __ldg((const uint4*)&Bvh[nn * CH + kk]);
        *(uint4*)&sBvl[nn * SASTRIDE + kk] = __ldg((const uint4*)&Bvl[nn * CH + kk]);
    }
    __syncthreads();

    int rbase = tid >> 5;
    int c = (tid & 31) * 4;
    int wid = tid >> 5, lane = tid & 31;
    int warp_m = (wid & 1) * 16;
    int warp_n = (wid >> 1) * 32;
    int rq = lane >> 2;
    int kq = (lane & 3) * 2;

    unsigned uA   = (unsigned)__cvta_generic_to_shared(sA);
    unsigned uBqh = (unsigned)__cvta_generic_to_shared(sBqh);
    unsigned uBql = (unsigned)__cvta_generic_to_shared(sBql);
    unsigned uBvh = (unsigned)__cvta_generic_to_shared(sBvh);
    unsigned uBvl = (unsigned)__cvta_generic_to_shared(sBvl);
    int arow = warp_m + (lane & 15);
    int acol = (lane >> 4) * 8;
    unsigned aOff = (unsigned)((arow * SASTRIDE + acol) * 2);
    int brow = warp_n + (lane & 7) + ((lane >> 4) & 1) * 8;
    int bcol = ((lane >> 3) & 1) * 8;
    unsigned bQh = uBqh + (unsigned)((brow * SASTRIDE + bcol) * 2);
    unsigned bQl = uBql + (unsigned)((brow * SASTRIDE + bcol) * 2);
    unsigned bVh = uBvh + (unsigned)((brow * SASTRIDE + bcol) * 2);
    unsigned bVl = uBvl + (unsigned)((brow * SASTRIDE + bcol) * 2);
    const unsigned BROW16 = 16 * SASTRIDE * 2;
    const unsigned ABUF_B = 2 * ABUF_ELEMS * 2;
    const unsigned ALO_B  = ABUF_ELEMS * 2;

    int ntiles = (nrows + BM - 1) / BM;
    int t = blockIdx.x;

    float4 pref[4];
#define LOAD_PREF_QV(TT)                                                      \
    {                                                                         \
        _Pragma("unroll")                                                     \
        for (int i = 0; i < 4; i++) {                                         \
            int row = (TT) * BM + i * 8 + rbase;                              \
            pref[i] = (row < nrows)                                           \
                ? __ldg((const float4*)&A[(size_t)row * CH + c])              \
                : make_float4(0.f, 0.f, 0.f, 0.f);                            \
        }                                                                     \
    }
    if (t < ntiles) LOAD_PREF_QV(t);

    int it = 0;
    while (t < ntiles) {
        int buf = it & 1;
        __nv_bfloat16* sAhi = sA + buf * 2 * ABUF_ELEMS;
        __nv_bfloat16* sAlo = sAhi + ABUF_ELEMS;
#pragma unroll
        for (int i = 0; i < 4; i++)
            store_a_split(sAhi, sAlo, i * 8 + rbase, c, pref[i]);
        __syncthreads();

        int row_lo = t * BM + warp_m + rq;
        int row_hi = row_lo + 8;
        bool ok_lo = row_lo < nrows, ok_hi = row_hi < nrows;

        int tn = t + QV_GRID;
        if (tn < ntiles) LOAD_PREF_QV(tn);

        unsigned aHi = uA + buf * ABUF_B + aOff;
        unsigned aLo = aHi + ALO_B;
        float accq[4][4], accv[4][4];
#pragma unroll
        for (int nt = 0; nt < 4; nt++)
#pragma unroll
            for (int j = 0; j < 4; j++) { accq[nt][j] = 0.f; accv[nt][j] = 0.f; }
#pragma unroll
        for (int ks = 0; ks < 8; ks++) {
            unsigned ko = ks * 32;
            unsigned ah[4], al[4];
            LDSM4(ah[0], ah[1], ah[2], ah[3], aHi + ko);
            LDSM4(al[0], al[1], al[2], al[3], aLo + ko);
            unsigned qh[8], ql[8], vh[8], vl[8];
            LDSM4(qh[0], qh[1], qh[2], qh[3], bQh + ko);
            LDSM4(qh[4], qh[5], qh[6], qh[7], bQh + BROW16 + ko);
            LDSM4(ql[0], ql[1], ql[2], ql[3], bQl + ko);
            LDSM4(ql[4], ql[5], ql[6], ql[7], bQl + BROW16 + ko);
            LDSM4(vh[0], vh[1], vh[2], vh[3], bVh + ko);
            LDSM4(vh[4], vh[5], vh[6], vh[7], bVh + BROW16 + ko);
            LDSM4(vl[0], vl[1], vl[2], vl[3], bVl + ko);
            LDSM4(vl[4], vl[5], vl[6], vl[7], bVl + BROW16 + ko);
#pragma unroll
            for (int nt = 0; nt < 4; nt++) {
                mma16816(accq[nt], ah, qh + 2 * nt);
                mma16816(accq[nt], ah, ql + 2 * nt);
                mma16816(accq[nt], al, qh + 2 * nt);
                mma16816(accv[nt], ah, vh + 2 * nt);
                mma16816(accv[nt], ah, vl + 2 * nt);
                mma16816(accv[nt], al, vh + 2 * nt);
            }
        }

        // ---- q epilogue: bias + l2norm per 16ch head ----
#pragma unroll
        for (int nt = 0; nt < 4; nt++) {
            int col = warp_n + nt * 8 + kq;
            float2 bs = *(const float2*)&bq[col];
            accq[nt][0] += bs.x; accq[nt][1] += bs.y;
            accq[nt][2] += bs.x; accq[nt][3] += bs.y;
        }
#pragma unroll
        for (int hp = 0; hp < 2; hp++) {
            int n0 = hp * 2, n1 = n0 + 1;
            float s0 = accq[n0][0] * accq[n0][0] + accq[n0][1] * accq[n0][1]
                     + accq[n1][0] * accq[n1][0] + accq[n1][1] * accq[n1][1];
            float s1 = accq[n0][2] * accq[n0][2] + accq[n0][3] * accq[n0][3]
                     + accq[n1][2] * accq[n1][2] + accq[n1][3] * accq[n1][3];
            s0 += __shfl_xor_sync(0xFFFFFFFFu, s0, 1);
            s0 += __shfl_xor_sync(0xFFFFFFFFu, s0, 2);
            s1 += __shfl_xor_sync(0xFFFFFFFFu, s1, 1);
            s1 += __shfl_xor_sync(0xFFFFFFFFu, s1, 2);
            float i0 = 1.f / fmaxf(sqrtf(s0), 1e-12f);
            float i1 = 1.f / fmaxf(sqrtf(s1), 1e-12f);
            accq[n0][0] *= i0; accq[n0][1] *= i0;
            accq[n1][0] *= i0; accq[n1][1] *= i0;
            accq[n0][2] *= i1; accq[n0][3] *= i1;
            accq[n1][2] *= i1; accq[n1][3] *= i1;
        }
        // ---- v epilogue: bias + fp16 store ----
#pragma unroll
        for (int nt = 0; nt < 4; nt++) {
            int col = warp_n + nt * 8 + kq;
            float2 bs = *(const float2*)&bv[col];
            accv[nt][0] += bs.x; accv[nt][1] += bs.y;
            accv[nt][2] += bs.x; accv[nt][3] += bs.y;
            if (ok_lo) {
                *(float2*)&Cq[(size_t)row_lo * CH + col] =
                    make_float2(accq[nt][0], accq[nt][1]);
                *(__half2*)&Cv[(size_t)row_lo * CH + col] =
                    __floats2half2_rn(accv[nt][0], accv[nt][1]);
            }
            if (ok_hi) {
                *(float2*)&Cq[(size_t)row_hi * CH + col] =
                    make_float2(accq[nt][2], accq[nt][3]);
                *(__half2*)&Cv[(size_t)row_hi * CH + col] =
                    __floats2half2_rn(accv[nt][2], accv[nt][3]);
            }
        }
        t = tn; ++it;
    }
#undef LOAD_PREF_QV
}

// ---------------- multi-block exclusive scan of g_cnt -----------------------
#define SC_CHUNK 1024
__global__ void __launch_bounds__(SC_CHUNK) scan1_kernel(int n) {
    __shared__ int sm[SC_CHUNK];
    int t = threadIdx.x;
    int i = blockIdx.x * SC_CHUNK + t;
    int v = (i < n) ? g_cnt[i] : 0;
    sm[t] = v;
    __syncthreads();
#pragma unroll
    for (int o = 1; o < SC_CHUNK; o <<= 1) {
        int x = (t >= o) ? sm[t - o] : 0;
        __syncthreads();
        sm[t] += x;
        __syncthreads();
    }
    if (i < n) g_off[i] = sm[t] - v;
    if (t == SC_CHUNK - 1) g_bsum[blockIdx.x] = sm[t];
}

__global__ void __launch_bounds__(128) scan2_kernel(int nb) {
    __shared__ int sm[128];
    int t = threadIdx.x;
    int v = (t < nb) ? g_bsum[t] : 0;
    sm[t] = v;
    __syncthreads();
#pragma unroll
    for (int o = 1; o < 128; o <<= 1) {
        int x = (t >= o) ? sm[t - o] : 0;
        __syncthreads();
        sm[t] += x;
        __syncthreads();
    }
    if (t < nb) g_bbase[t] = sm[t] - v;
}

__global__ void __launch_bounds__(SC_CHUNK) scan3_kernel(int n) {
    int i = blockIdx.x * SC_CHUNK + threadIdx.x;
    if (i < n) {
        int o = g_off[i] + g_bbase[blockIdx.x];
        g_off[i] = o;
        g_cur[i] = o;
    }
}

__global__ void __launch_bounds__(256) place_kernel(const int* __restrict__ kq, int M) {
    int i = blockIdx.x * blockDim.x + threadIdx.x;
    if (i < M) {
        int q = __ldg(&kq[M + i]);
        int pos = atomicAdd(&g_cur[q], 1);
        int kk = __ldg(&kq[i]);
        int key = kk / KVOL;
        int kern = kk - key * KVOL;
        g_sorted[pos] = (key << 5) | kern;   // pre-encoded for gather
    }
}

// ---------------- persistent segment gather: warp per query ----------------
#define GATHER_BLOCKS 592
__global__ void __launch_bounds__(256) gather_kernel(int n) {
    __shared__ float s_npe[KVOL * CH];
    for (int i = threadIdx.x; i < KVOL * CH / 4; i += 256)
        ((float4*)s_npe)[i] = ((const float4*)g_npe)[i];
    __syncthreads();

    int lane = threadIdx.x & 31;
    int c4 = lane * 4;
    int wid0 = (blockIdx.x * 256 + threadIdx.x) >> 5;
    const int nwarps = GATHER_BLOCKS * 8;

    for (int gw = wid0; gw < n; gw += nwarps) {
        int beg = __ldg(&g_off[gw]);
        int cnt = __ldg(&g_cnt[gw]);
        float4 qv = __ldcs((const float4*)&g_q[(size_t)gw * CH + c4]);
        float4 acc = make_float4(0.f, 0.f, 0.f, 0.f);

        int i = 0;
        // ---- 8-wide batches (MLP=8) ----
        for (; i + 8 <= cnt; i += 8) {
            int e[8];
#pragma unroll
            for (int j = 0; j < 8; j++) e[j] = __ldg(&g_sorted[beg + i + j]);
            uint2 vh[8];
#pragma unroll
            for (int j = 0; j < 8; j++)
                vh[j] = __ldg((const uint2*)&g_vh[(size_t)(e[j] >> 5) * CH + c4]);
            float s[8];
#pragma unroll
            for (int j = 0; j < 8; j++) {
                float4 p = *(const float4*)&s_npe[(e[j] & 31) * CH + c4];
                float t = qv.x * p.x + qv.y * p.y + qv.z * p.z + qv.w * p.w;
                t += __shfl_xor_sync(0xFFFFFFFFu, t, 1);
                t += __shfl_xor_sync(0xFFFFFFFFu, t, 2);
                s[j] = t;
            }
#pragma unroll
            for (int j = 0; j < 8; j++) {
                float2 v0 = __half22float2(*(const __half2*)&vh[j].x);
                float2 v1 = __half22float2(*(const __half2*)&vh[j].y);
                acc.x = fmaf(s[j], v0.x, acc.x);
                acc.y = fmaf(s[j], v0.y, acc.y);
                acc.z = fmaf(s[j], v1.x, acc.z);
                acc.w = fmaf(s[j], v1.y, acc.w);
            }
        }
        // ---- 4-wide ----
        if (i + 4 <= cnt) {
            int e[4];
#pragma unroll
            for (int j = 0; j < 4; j++) e[j] = __ldg(&g_sorted[beg + i + j]);
            uint2 vh[4];
#pragma unroll
            for (int j = 0; j < 4; j++)
                vh[j] = __ldg((const uint2*)&g_vh[(size_t)(e[j] >> 5) * CH + c4]);
#pragma unroll
            for (int j = 0; j < 4; j++) {
                float4 p = *(const float4*)&s_npe[(e[j] & 31) * CH + c4];
                float t = qv.x * p.x + qv.y * p.y + qv.z * p.z + qv.w * p.w;
                t += __shfl_xor_sync(0xFFFFFFFFu, t, 1);
                t += __shfl_xor_sync(0xFFFFFFFFu, t, 2);
                float2 v0 = __half22float2(*(const __half2*)&vh[j].x);
                float2 v1 = __half22float2(*(const __half2*)&vh[j].y);
                acc.x = fmaf(t, v0.x, acc.x);
                acc.y = fmaf(t, v0.y, acc.y);
                acc.z = fmaf(t, v1.x, acc.z);
                acc.w = fmaf(t, v1.y, acc.w);
            }
            i += 4;
        }
        // ---- tail ----
        for (; i < cnt; i++) {
            int e = __ldg(&g_sorted[beg + i]);
            uint2 vh = __ldg((const uint2*)&g_vh[(size_t)(e >> 5) * CH + c4]);
            float4 p = *(const float4*)&s_npe[(e & 31) * CH + c4];
            float t = qv.x * p.x + qv.y * p.y + qv.z * p.z + qv.w * p.w;
            t += __shfl_xor_sync(0xFFFFFFFFu, t, 1);
            t += __shfl_xor_sync(0xFFFFFFFFu, t, 2);
            float2 v0 = __half22float2(*(const __half2*)&vh.x);
            float2 v1 = __half22float2(*(const __half2*)&vh.y);
            acc.x = fmaf(t, v0.x, acc.x);
            acc.y = fmaf(t, v0.y, acc.y);
            acc.z = fmaf(t, v1.x, acc.z);
            acc.w = fmaf(t, v1.y, acc.w);
        }
        __stcs((float4*)&g_acc[(size_t)gw * CH + c4], acc);
    }
}

// ---------------- host launch ----------------------------------------------
extern "C" void kernel_launch(void* const* d_in, const int* in_sizes, int n_in,
                              void* d_out, int out_size) {
    const float* feats   = (const float*)d_in[0];
    const float* points  = (const float*)d_in[1];
    const int*   kq      = (const int*)d_in[2];
    const float* W1 = (const float*)d_in[3];
    const float* g1 = (const float*)d_in[4];
    const float* b1 = (const float*)d_in[5];
    const float* W2 = (const float*)d_in[6];
    const float* g2 = (const float*)d_in[7];
    const float* b2 = (const float*)d_in[8];
    const float* W3 = (const float*)d_in[9];
    const float* b3 = (const float*)d_in[10];
    const float* Wq = (const float*)d_in[11];
    const float* bq = (const float*)d_in[12];
    const float* Wv = (const float*)d_in[13];
    const float* bv = (const float*)d_in[14];
    const float* pos_enc = (const float*)d_in[15];
    const float* Wo = (const float*)d_in[16];
    const float* bo = (const float*)d_in[17];

    int N = in_sizes[0] / CH;
    int M = in_sizes[2] / 2;

    cudaFuncSetAttribute((const void*)gemm_p<0>,
                         cudaFuncAttributeMaxDynamicSharedMemorySize, TC_SMEM_1);
    cudaFuncSetAttribute((const void*)gemm_p<1>,
                         cudaFuncAttributeMaxDynamicSharedMemorySize, TC_SMEM_1);
    cudaFuncSetAttribute((const void*)gemm_qv,
                         cudaFuncAttributeMaxDynamicSharedMemorySize, TC_SMEM_QV);

    float* xp; float* qp; float* ap; __half* vhp;
    __nv_bfloat16* whi; __nv_bfloat16* wlo;
    { void* t; cudaGetSymbolAddress(&t, g_x);   xp  = (float*)t; }
    { void* t; cudaGetSymbolAddress(&t, g_q);   qp  = (float*)t; }
    { void* t; cudaGetSymbolAddress(&t, g_vh);  vhp = (__half*)t; }
    { void* t; cudaGetSymbolAddress(&t, g_acc); ap  = (float*)t; }
    { void* t; cudaGetSymbolAddress(&t, g_Whi); whi = (__nv_bfloat16*)t; }
    { void* t; cudaGetSymbolAddress(&t, g_Wlo); wlo = (__nv_bfloat16*)t; }
    void* cntp = nullptr;
    cudaGetSymbolAddress(&cntp, g_cnt);
    cudaMemsetAsync(cntp, 0, (size_t)N * sizeof(int), 0);

    int nsb = (N + SC_CHUNK - 1) / SC_CHUNK;

    init_kernel<<<1, 256>>>(pos_enc);
    stats1_kernel<<<256, 256>>>(points, W1, N, W3, Wq, Wv, Wo, kq, M);
    h2_kernel<<<(N + H2_PB - 1) / H2_PB, 256>>>(points, W1, g1, b1, W2, N);
    scan1_kernel<<<nsb, SC_CHUNK>>>(N);
    scan2_kernel<<<1, 128>>>(nsb);
    scan3_kernel<<<nsb, SC_CHUNK>>>(N);
    place_kernel<<<(M + 255) / 256, 256>>>(kq, M);

    // x = relu(bn2(h2(points))) @ W3 + b3 + feats
    gemm_p<1><<<GEMM_GRID, 256, TC_SMEM_1>>>(nullptr, whi + 0 * CH * CH, wlo + 0 * CH * CH,
                                             b3, xp, feats, g2, b2, points, W1, W2, N);
    // q (l2norm, fp32) and v (fp16) in one pass over x (3-term split both)
    gemm_qv<<<QV_GRID, 256, TC_SMEM_QV>>>(xp,
                                          whi + 1 * CH * CH, wlo + 1 * CH * CH,
                                          whi + 2 * CH * CH, wlo + 2 * CH * CH,
                                          bq, bv, qp, vhp, N);

    // attention: persistent segment gather
    gather_kernel<<<GATHER_BLOCKS, 256>>>(N);

    // out = acc @ Wo + bo
    gemm_p<0><<<GEMM_GRID, 256, TC_SMEM_1>>>(ap, whi + 3 * CH * CH, wlo + 3 * CH * CH,
                                             bo, (float*)d_out, nullptr, nullptr, nullptr,
                                             nullptr, nullptr, nullptr, N);
}